// round 6
// baseline (speedup 1.0000x reference)
#include <cuda_runtime.h>

#define Bsz 16
#define Lsz 512
#define Dsz 512
#define Hsz 8
#define DKsz 64
#define BHsz (Bsz*Hsz)

// Scratch (allocation-free contract: __device__ globals)
__device__ float g_q[Bsz*Hsz*Lsz*DKsz];
__device__ float g_k[Bsz*Hsz*Lsz*DKsz];
__device__ float g_v[Bsz*Hsz*Lsz*DKsz];
__device__ float g_x[Bsz*Lsz*Dsz];

// ---------------------------------------------------------------------------
// Projection / fc GEMM: C[8192,512] = X[8192,512] @ W[512,512]
// MODE 0/1/2: X=input, write split-heads into g_q/g_k/g_v ([B,H,L,DK])
// MODE 3:     X=g_x,  write plain [M,N] into outp (the fc output)
// Tiles: BM=BN=64, BK=16, 256 threads, 4x4 micro-tile, float4 smem reads.
// ---------------------------------------------------------------------------
template<int MODE>
__global__ __launch_bounds__(256) void proj_kernel(const float* __restrict__ Xin,
                                                   const float* __restrict__ W,
                                                   float* __restrict__ outp)
{
    __shared__ float As[16][68];   // As[k][m]  (transposed A tile)
    __shared__ float Bs[16][68];   // Bs[k][n]
    const float* X = (MODE == 3) ? g_x : Xin;

    const int tid = threadIdx.x;
    const int tx = tid & 15, ty = tid >> 4;
    const int mBase = blockIdx.y * 64;
    const int nBase = blockIdx.x * 64;

    const int la_m  = tid >> 2;          // 0..63
    const int la_k4 = (tid & 3) * 4;     // 0,4,8,12
    const int lb_k  = tid >> 4;          // 0..15
    const int lb_n4 = (tid & 15) * 4;    // 0..60

    float acc[4][4] = {};

    for (int k0 = 0; k0 < 512; k0 += 16) {
        float4 a4 = *(const float4*)&X[(mBase + la_m) * 512 + k0 + la_k4];
        As[la_k4 + 0][la_m] = a4.x;
        As[la_k4 + 1][la_m] = a4.y;
        As[la_k4 + 2][la_m] = a4.z;
        As[la_k4 + 3][la_m] = a4.w;
        *(float4*)&Bs[lb_k][lb_n4] =
            *(const float4*)&W[(k0 + lb_k) * 512 + nBase + lb_n4];
        __syncthreads();

        #pragma unroll
        for (int kk = 0; kk < 16; kk++) {
            float4 a = *(const float4*)&As[kk][ty * 4];
            float4 b = *(const float4*)&Bs[kk][tx * 4];
            float av[4] = {a.x, a.y, a.z, a.w};
            float bv[4] = {b.x, b.y, b.z, b.w};
            #pragma unroll
            for (int i = 0; i < 4; i++)
                #pragma unroll
                for (int j = 0; j < 4; j++)
                    acc[i][j] = fmaf(av[i], bv[j], acc[i][j]);
        }
        __syncthreads();
    }

    if (MODE == 3) {
        #pragma unroll
        for (int i = 0; i < 4; i++) {
            float4 o = {acc[i][0], acc[i][1], acc[i][2], acc[i][3]};
            *(float4*)&outp[(mBase + ty * 4 + i) * 512 + nBase + tx * 4] = o;
        }
    } else {
        float* dst = (MODE == 0) ? g_q : (MODE == 1) ? g_k : g_v;
        const int h = nBase >> 6;  // BN=64 == DK -> one head per n-tile
        #pragma unroll
        for (int i = 0; i < 4; i++) {
            int m  = mBase + ty * 4 + i;
            int bb = m >> 9;
            int ll = m & 511;
            float4 o = {acc[i][0], acc[i][1], acc[i][2], acc[i][3]};
            *(float4*)&dst[(((bb * Hsz + h) * Lsz) + ll) * DKsz + tx * 4] = o;
        }
    }
}

// ---------------------------------------------------------------------------
// Fused attention: per (bh, 64-row q tile):
//   S = (Q Kt)/8  -> mask -> softmax -> *aiw -> p_attn (global) -> X = P V
// Dynamic smem: s[64][513] + qs[64][68](d-major) + kv[64][68]  = 166,144 B
// MASK is int32 0/1 (bool upcast by the harness). Reading as int with a
// nonzero test is also correct if it were float32 0.0/1.0.
// ---------------------------------------------------------------------------
__global__ __launch_bounds__(256) void attn_kernel(const int* __restrict__ mask,
                                                   const float* __restrict__ aiw,
                                                   float* __restrict__ p_out)
{
    extern __shared__ float sm[];
    float* s  = sm;                // [64][513]
    float* qs = sm + 64 * 513;     // [64][68]  qs[d][m]
    float* kv = qs + 64 * 68;      // [64][68]

    const int tid = threadIdx.x;
    const int tx = tid & 15, ty = tid >> 4;
    const int bh = blockIdx.y;
    const int b  = bh >> 3;
    const int h  = bh & 7;
    const int qBase = blockIdx.x * 64;

    const int lr  = tid >> 2;        // 0..63 row
    const int lc4 = (tid & 3) * 4;   // 0,4,8,12

    // ---- load Q tile transposed: qs[d][m]
    {
        const float* qg = g_q + (bh * Lsz + qBase) * DKsz;
        #pragma unroll
        for (int c0 = 0; c0 < 64; c0 += 16) {
            float4 v = *(const float4*)&qg[lr * 64 + c0 + lc4];
            qs[(c0 + lc4 + 0) * 68 + lr] = v.x;
            qs[(c0 + lc4 + 1) * 68 + lr] = v.y;
            qs[(c0 + lc4 + 2) * 68 + lr] = v.z;
            qs[(c0 + lc4 + 3) * 68 + lr] = v.w;
        }
    }

    // ---- S = Q K^T / 8
    for (int nt = 0; nt < 8; nt++) {
        const float* kg = g_k + (bh * Lsz + nt * 64) * DKsz;
        #pragma unroll
        for (int c0 = 0; c0 < 64; c0 += 16) {
            float4 v = *(const float4*)&kg[lr * 64 + c0 + lc4];
            kv[(c0 + lc4 + 0) * 68 + lr] = v.x;
            kv[(c0 + lc4 + 1) * 68 + lr] = v.y;
            kv[(c0 + lc4 + 2) * 68 + lr] = v.z;
            kv[(c0 + lc4 + 3) * 68 + lr] = v.w;
        }
        __syncthreads();

        float acc[4][4] = {};
        #pragma unroll 16
        for (int d = 0; d < 64; d++) {
            float4 a  = *(const float4*)&qs[d * 68 + ty * 4];
            float4 b4 = *(const float4*)&kv[d * 68 + tx * 4];
            float av[4] = {a.x, a.y, a.z, a.w};
            float bv[4] = {b4.x, b4.y, b4.z, b4.w};
            #pragma unroll
            for (int i = 0; i < 4; i++)
                #pragma unroll
                for (int j = 0; j < 4; j++)
                    acc[i][j] = fmaf(av[i], bv[j], acc[i][j]);
        }
        #pragma unroll
        for (int i = 0; i < 4; i++)
            #pragma unroll
            for (int j = 0; j < 4; j++)
                s[(ty * 4 + i) * 513 + nt * 64 + tx * 4 + j] = acc[i][j] * 0.125f;
        __syncthreads();
    }

    // ---- mask + softmax + *aiw + write p_attn (8 warps x 8 rows each)
    {
        const int warp = tid >> 5, lane = tid & 31;
        for (int r = 0; r < 8; r++) {
            const int m = warp * 8 + r;
            const int qRow = qBase + m;
            const int*   mrow = mask + ((size_t)b * Lsz + qRow) * Lsz;   // int32 mask
            const float* arow = aiw  + ((size_t)b * Lsz + qRow) * Lsz;
            float* srow = s + m * 513;

            float mx = -1e30f;
            for (int k = lane; k < 512; k += 32) {
                float v = (mrow[k] != 0) ? -1e30f : srow[k];
                srow[k] = v;
                mx = fmaxf(mx, v);
            }
            #pragma unroll
            for (int o = 16; o; o >>= 1) mx = fmaxf(mx, __shfl_xor_sync(0xffffffffu, mx, o));

            float sum = 0.f;
            for (int k = lane; k < 512; k += 32) {
                float e = __expf(srow[k] - mx);   // masked: exp(-1e30-mx) -> 0
                srow[k] = e;
                sum += e;
            }
            #pragma unroll
            for (int o = 16; o; o >>= 1) sum += __shfl_xor_sync(0xffffffffu, sum, o);
            const float inv = 1.f / sum;

            float* prow = p_out + ((size_t)bh * Lsz + qRow) * Lsz;
            for (int k = lane; k < 512; k += 32) {
                float p = srow[k] * inv * arow[k];
                srow[k] = p;
                prow[k] = p;
            }
        }
    }
    __syncthreads();

    // ---- X = P V
    float acc[4][4] = {};
    for (int kt = 0; kt < 8; kt++) {
        const float* vg = g_v + (bh * Lsz + kt * 64) * DKsz;
        #pragma unroll
        for (int c0 = 0; c0 < 64; c0 += 16)
            *(float4*)&kv[lr * 68 + c0 + lc4] = *(const float4*)&vg[lr * 64 + c0 + lc4];
        __syncthreads();

        #pragma unroll 16
        for (int kk = 0; kk < 64; kk++) {
            float4 b4 = *(const float4*)&kv[kk * 68 + tx * 4];
            float a0 = s[(ty * 4 + 0) * 513 + kt * 64 + kk];
            float a1 = s[(ty * 4 + 1) * 513 + kt * 64 + kk];
            float a2 = s[(ty * 4 + 2) * 513 + kt * 64 + kk];
            float a3 = s[(ty * 4 + 3) * 513 + kt * 64 + kk];
            float av[4] = {a0, a1, a2, a3};
            float bv[4] = {b4.x, b4.y, b4.z, b4.w};
            #pragma unroll
            for (int i = 0; i < 4; i++)
                #pragma unroll
                for (int j = 0; j < 4; j++)
                    acc[i][j] = fmaf(av[i], bv[j], acc[i][j]);
        }
        __syncthreads();
    }

    #pragma unroll
    for (int i = 0; i < 4; i++) {
        const int qRow = qBase + ty * 4 + i;
        float4 o = {acc[i][0], acc[i][1], acc[i][2], acc[i][3]};
        *(float4*)&g_x[((size_t)b * Lsz + qRow) * Dsz + h * 64 + tx * 4] = o;
    }
}

// ---------------------------------------------------------------------------
extern "C" void kernel_launch(void* const* d_in, const int* in_sizes, int n_in,
                              void* d_out, int out_size)
{
    (void)in_sizes; (void)n_in; (void)out_size;
    const float* query = (const float*)d_in[0];
    const float* keyt  = (const float*)d_in[1];
    const float* value = (const float*)d_in[2];
    const int*   mask  = (const int*)d_in[3];     // bool upcast to int32 by harness
    const float* aiw   = (const float*)d_in[4];
    const float* wQ    = (const float*)d_in[5];
    const float* wK    = (const float*)d_in[6];
    const float* wV    = (const float*)d_in[7];
    const float* wfc   = (const float*)d_in[8];

    float* outx = (float*)d_out;                       // x: [B,L,D]
    float* outp = outx + (size_t)Bsz * Lsz * Dsz;      // p_attn: [B,H,L,L]

    dim3 gp(8, 128), tp(256);
    proj_kernel<0><<<gp, tp>>>(query, wQ, nullptr);
    proj_kernel<1><<<gp, tp>>>(keyt,  wK, nullptr);
    proj_kernel<2><<<gp, tp>>>(value, wV, nullptr);

    const int smem = (64 * 513 + 2 * 64 * 68) * (int)sizeof(float);  // 166,144 B
    cudaFuncSetAttribute((const void*)attn_kernel,
                         cudaFuncAttributeMaxDynamicSharedMemorySize, smem);
    attn_kernel<<<dim3(8, 128), 256, smem>>>(mask, aiw, outp);

    proj_kernel<3><<<gp, tp>>>(nullptr, wfc, outx);
}

// round 7
// speedup vs baseline: 1.1267x; 1.1267x over previous
#include <cuda_runtime.h>
#include <cuda_bf16.h>
#include <cstdint>

#define Bsz 16
#define Lsz 512
#define Dsz 512
#define Hsz 8
#define DKsz 64
#define BHsz (Bsz*Hsz)

// Scratch (allocation-free contract: __device__ globals)
__device__ float g_q[Bsz*Hsz*Lsz*DKsz];
__device__ float g_k[Bsz*Hsz*Lsz*DKsz];
__device__ float g_v[Bsz*Hsz*Lsz*DKsz];
__device__ float g_x[Bsz*Lsz*Dsz];

// ---------------------------------------------------------------------------
// bf16x2-split tensor-core GEMM: C[8192,512] = X[8192,512] @ W[512,512]
// Each fp32 a is split a = hi + lo (bf16 each); product uses 3 MMAs
// (hi*hi + hi*lo + lo*hi), keeping ~16 mantissa bits -> rel err ~1e-5.
// Tile: BM=128, BN=64, BK=32. 256 threads = 8 warps (4 m x 2 n), warp 32x32.
// MODE 0/1/2: write split-heads into g_q/g_k/g_v; MODE 3: g_x @ wfc -> outp.
// ---------------------------------------------------------------------------
__device__ __forceinline__ void mma_bf16(float* c, const uint32_t* a, const uint32_t* b)
{
    asm volatile(
        "mma.sync.aligned.m16n8k16.row.col.f32.bf16.bf16.f32 "
        "{%0,%1,%2,%3}, {%4,%5,%6,%7}, {%8,%9}, {%0,%1,%2,%3};\n"
        : "+f"(c[0]), "+f"(c[1]), "+f"(c[2]), "+f"(c[3])
        : "r"(a[0]), "r"(a[1]), "r"(a[2]), "r"(a[3]), "r"(b[0]), "r"(b[1]));
}

template<int MODE>
__global__ __launch_bounds__(256) void proj_mma(const float* __restrict__ Xin,
                                                const float* __restrict__ W,
                                                float* __restrict__ outp)
{
    const float* X = (MODE == 3) ? g_x : Xin;

    __shared__ __nv_bfloat16 Ah[128][40];   // [m][k], stride 40 -> conflict-free b32 frag loads
    __shared__ __nv_bfloat16 Al[128][40];
    __shared__ __nv_bfloat16 Bh[64][40];    // [n][k] (transposed W tile)
    __shared__ __nv_bfloat16 Bl[64][40];

    const int tid  = threadIdx.x;
    const int wid  = tid >> 5;
    const int lane = tid & 31;
    const int wm = (wid >> 1) * 32;     // warp m offset within 128
    const int wn = (wid & 1) * 32;      // warp n offset within 64
    const int g  = lane >> 2;           // 0..7
    const int t4 = lane & 3;            // 0..3

    const int mBase = blockIdx.x * 128;
    const int nBase = blockIdx.y * 64;

    // loader indices
    const int ar = tid >> 1;            // 0..127  A row
    const int ac = (tid & 1) * 16;      // A col base (floats)
    const int bn = tid & 63;            // 0..63   B n
    const int bk = (tid >> 6) * 8;      // 0,8,16,24  B k base

    float acc[2][4][4] = {};            // [mfrag][nfrag][c0..c3]

    for (int k0 = 0; k0 < 512; k0 += 32) {
        // ---- A tile 128x32: load fp32, split to bf16 hi/lo
        #pragma unroll
        for (int j = 0; j < 4; j++) {
            const int cc = ac + j * 4;
            float4 v = *(const float4*)&X[(size_t)(mBase + ar) * 512 + k0 + cc];
            float vv[4] = {v.x, v.y, v.z, v.w};
            #pragma unroll
            for (int e = 0; e < 4; e++) {
                __nv_bfloat16 h = __float2bfloat16(vv[e]);
                __nv_bfloat16 l = __float2bfloat16(vv[e] - __bfloat162float(h));
                Ah[ar][cc + e] = h;
                Al[ar][cc + e] = l;
            }
        }
        // ---- B tile 32x64 -> Bs[n][k] (transpose + split); coalesced per-k LDG
        {
            __align__(16) __nv_bfloat16 bh8[8];
            __align__(16) __nv_bfloat16 bl8[8];
            #pragma unroll
            for (int i = 0; i < 8; i++) {
                float w = W[(size_t)(k0 + bk + i) * 512 + nBase + bn];
                __nv_bfloat16 h = __float2bfloat16(w);
                bh8[i] = h;
                bl8[i] = __float2bfloat16(w - __bfloat162float(h));
            }
            *(uint4*)&Bh[bn][bk] = *(const uint4*)bh8;
            *(uint4*)&Bl[bn][bk] = *(const uint4*)bl8;
        }
        __syncthreads();

        #pragma unroll
        for (int ks = 0; ks < 32; ks += 16) {
            uint32_t a_h[2][4], a_l[2][4];
            #pragma unroll
            for (int mf = 0; mf < 2; mf++) {
                const int r0 = wm + mf * 16 + g;
                a_h[mf][0] = *(const uint32_t*)&Ah[r0    ][ks + 2 * t4];
                a_h[mf][1] = *(const uint32_t*)&Ah[r0 + 8][ks + 2 * t4];
                a_h[mf][2] = *(const uint32_t*)&Ah[r0    ][ks + 2 * t4 + 8];
                a_h[mf][3] = *(const uint32_t*)&Ah[r0 + 8][ks + 2 * t4 + 8];
                a_l[mf][0] = *(const uint32_t*)&Al[r0    ][ks + 2 * t4];
                a_l[mf][1] = *(const uint32_t*)&Al[r0 + 8][ks + 2 * t4];
                a_l[mf][2] = *(const uint32_t*)&Al[r0    ][ks + 2 * t4 + 8];
                a_l[mf][3] = *(const uint32_t*)&Al[r0 + 8][ks + 2 * t4 + 8];
            }
            #pragma unroll
            for (int nf = 0; nf < 4; nf++) {
                const int nc = wn + nf * 8 + g;
                uint32_t b_h[2], b_l[2];
                b_h[0] = *(const uint32_t*)&Bh[nc][ks + 2 * t4];
                b_h[1] = *(const uint32_t*)&Bh[nc][ks + 2 * t4 + 8];
                b_l[0] = *(const uint32_t*)&Bl[nc][ks + 2 * t4];
                b_l[1] = *(const uint32_t*)&Bl[nc][ks + 2 * t4 + 8];
                #pragma unroll
                for (int mf = 0; mf < 2; mf++) {
                    mma_bf16(acc[mf][nf], a_h[mf], b_h);
                    mma_bf16(acc[mf][nf], a_h[mf], b_l);
                    mma_bf16(acc[mf][nf], a_l[mf], b_h);
                }
            }
        }
        __syncthreads();
    }

    // ---- epilogue: c0:(g,2t4) c1:(g,2t4+1) c2:(g+8,2t4) c3:(g+8,2t4+1)
    #pragma unroll
    for (int mf = 0; mf < 2; mf++) {
        #pragma unroll
        for (int nf = 0; nf < 4; nf++) {
            const int col = wn + nf * 8 + 2 * t4;           // 0..63 within block
            const int r0  = mBase + wm + mf * 16 + g;
            const int r1  = r0 + 8;
            float2 lo2 = {acc[mf][nf][0], acc[mf][nf][1]};
            float2 hi2 = {acc[mf][nf][2], acc[mf][nf][3]};
            if (MODE == 3) {
                *(float2*)&outp[(size_t)r0 * 512 + nBase + col] = lo2;
                *(float2*)&outp[(size_t)r1 * 512 + nBase + col] = hi2;
            } else {
                float* dst = (MODE == 0) ? g_q : (MODE == 1) ? g_k : g_v;
                const int h = blockIdx.y;                    // BN=64 == DK
                const int b0 = r0 >> 9, l0 = r0 & 511;
                const int b1 = r1 >> 9, l1 = r1 & 511;
                *(float2*)&dst[(((size_t)b0 * Hsz + h) * Lsz + l0) * DKsz + col] = lo2;
                *(float2*)&dst[(((size_t)b1 * Hsz + h) * Lsz + l1) * DKsz + col] = hi2;
            }
        }
    }
}

// ---------------------------------------------------------------------------
// Fused attention (512 threads, 16 warps): per (bh, 64-row q tile):
//   S = (Q Kt)/8 -> mask -> softmax -> *aiw -> p_attn -> X = P V
// Dynamic smem: s[64][513] + qs[64][68](d-major) + kv[64][68] = 166,144 B
// ---------------------------------------------------------------------------
__global__ __launch_bounds__(512) void attn_kernel(const int* __restrict__ mask,
                                                   const float* __restrict__ aiw,
                                                   float* __restrict__ p_out)
{
    extern __shared__ float sm[];
    float* s  = sm;                // [64][513]
    float* qs = sm + 64 * 513;     // [64][68]  qs[d][m]
    float* kv = qs + 64 * 68;      // [64][68]

    const int tid = threadIdx.x;
    const int tx = tid & 15;           // n/4
    const int ty = tid >> 4;           // 0..31 (2-row microtile)
    const int bh = blockIdx.y;
    const int b  = bh >> 3;
    const int h  = bh & 7;
    const int qBase = blockIdx.x * 64;

    const int lr  = tid >> 3;          // 0..63 row
    const int lc4 = (tid & 7) * 4;     // 0..28

    // ---- load Q tile transposed: qs[d][m]
    {
        const float* qg = g_q + ((size_t)bh * Lsz + qBase) * DKsz;
        #pragma unroll
        for (int c0 = 0; c0 < 64; c0 += 32) {
            float4 v = *(const float4*)&qg[lr * 64 + c0 + lc4];
            qs[(c0 + lc4 + 0) * 68 + lr] = v.x;
            qs[(c0 + lc4 + 1) * 68 + lr] = v.y;
            qs[(c0 + lc4 + 2) * 68 + lr] = v.z;
            qs[(c0 + lc4 + 3) * 68 + lr] = v.w;
        }
    }

    // ---- S = Q K^T / 8
    for (int nt = 0; nt < 8; nt++) {
        const float* kg = g_k + ((size_t)bh * Lsz + nt * 64) * DKsz;
        #pragma unroll
        for (int c0 = 0; c0 < 64; c0 += 32) {
            float4 v = *(const float4*)&kg[lr * 64 + c0 + lc4];
            kv[(c0 + lc4 + 0) * 68 + lr] = v.x;
            kv[(c0 + lc4 + 1) * 68 + lr] = v.y;
            kv[(c0 + lc4 + 2) * 68 + lr] = v.z;
            kv[(c0 + lc4 + 3) * 68 + lr] = v.w;
        }
        __syncthreads();

        float acc[2][4] = {};
        #pragma unroll 16
        for (int d = 0; d < 64; d++) {
            float2 a  = *(const float2*)&qs[d * 68 + ty * 2];
            float4 b4 = *(const float4*)&kv[d * 68 + tx * 4];
            float av[2] = {a.x, a.y};
            float bv[4] = {b4.x, b4.y, b4.z, b4.w};
            #pragma unroll
            for (int i = 0; i < 2; i++)
                #pragma unroll
                for (int j = 0; j < 4; j++)
                    acc[i][j] = fmaf(av[i], bv[j], acc[i][j]);
        }
        #pragma unroll
        for (int i = 0; i < 2; i++)
            #pragma unroll
            for (int j = 0; j < 4; j++)
                s[(ty * 2 + i) * 513 + nt * 64 + tx * 4 + j] = acc[i][j] * 0.125f;
        __syncthreads();
    }

    // ---- mask + softmax + *aiw + write p_attn (16 warps x 4 rows each)
    {
        const int warp = tid >> 5, lane = tid & 31;
        #pragma unroll
        for (int r = 0; r < 4; r++) {
            const int m = warp * 4 + r;
            const int qRow = qBase + m;
            const int*   mrow = mask + ((size_t)b * Lsz + qRow) * Lsz;
            const float* arow = aiw  + ((size_t)b * Lsz + qRow) * Lsz;
            float* srow = s + m * 513;

            float mx = -1e30f;
            for (int k = lane; k < 512; k += 32) {
                float v = (mrow[k] != 0) ? -1e30f : srow[k];
                srow[k] = v;
                mx = fmaxf(mx, v);
            }
            #pragma unroll
            for (int o = 16; o; o >>= 1) mx = fmaxf(mx, __shfl_xor_sync(0xffffffffu, mx, o));

            float sum = 0.f;
            for (int k = lane; k < 512; k += 32) {
                float e = __expf(srow[k] - mx);
                srow[k] = e;
                sum += e;
            }
            #pragma unroll
            for (int o = 16; o; o >>= 1) sum += __shfl_xor_sync(0xffffffffu, sum, o);
            const float inv = 1.f / sum;

            float* prow = p_out + ((size_t)bh * Lsz + qRow) * Lsz;
            for (int k = lane; k < 512; k += 32) {
                float p = srow[k] * inv * arow[k];
                srow[k] = p;
                prow[k] = p;
            }
        }
    }
    __syncthreads();

    // ---- X = P V
    float acc[2][4] = {};
    for (int kt = 0; kt < 8; kt++) {
        const float* vg = g_v + ((size_t)bh * Lsz + kt * 64) * DKsz;
        #pragma unroll
        for (int c0 = 0; c0 < 64; c0 += 32)
            *(float4*)&kv[lr * 68 + c0 + lc4] = *(const float4*)&vg[lr * 64 + c0 + lc4];
        __syncthreads();

        #pragma unroll 16
        for (int kk = 0; kk < 64; kk++) {
            float4 b4 = *(const float4*)&kv[kk * 68 + tx * 4];
            float a0 = s[(ty * 2 + 0) * 513 + kt * 64 + kk];
            float a1 = s[(ty * 2 + 1) * 513 + kt * 64 + kk];
            float av[2] = {a0, a1};
            float bv[4] = {b4.x, b4.y, b4.z, b4.w};
            #pragma unroll
            for (int i = 0; i < 2; i++)
                #pragma unroll
                for (int j = 0; j < 4; j++)
                    acc[i][j] = fmaf(av[i], bv[j], acc[i][j]);
        }
        __syncthreads();
    }

    #pragma unroll
    for (int i = 0; i < 2; i++) {
        const int qRow = qBase + ty * 2 + i;
        float4 o = {acc[i][0], acc[i][1], acc[i][2], acc[i][3]};
        *(float4*)&g_x[((size_t)b * Lsz + qRow) * Dsz + h * 64 + tx * 4] = o;
    }
}

// ---------------------------------------------------------------------------
extern "C" void kernel_launch(void* const* d_in, const int* in_sizes, int n_in,
                              void* d_out, int out_size)
{
    (void)in_sizes; (void)n_in; (void)out_size;
    const float* query = (const float*)d_in[0];
    const float* keyt  = (const float*)d_in[1];
    const float* value = (const float*)d_in[2];
    const int*   mask  = (const int*)d_in[3];     // bool upcast to int32 by harness
    const float* aiw   = (const float*)d_in[4];
    const float* wQ    = (const float*)d_in[5];
    const float* wK    = (const float*)d_in[6];
    const float* wV    = (const float*)d_in[7];
    const float* wfc   = (const float*)d_in[8];

    float* outx = (float*)d_out;                       // x: [B,L,D]
    float* outp = outx + (size_t)Bsz * Lsz * Dsz;      // p_attn: [B,H,L,L]

    dim3 gp(64, 8), tp(256);                           // 128x64 tiles
    proj_mma<0><<<gp, tp>>>(query, wQ, nullptr);
    proj_mma<1><<<gp, tp>>>(keyt,  wK, nullptr);
    proj_mma<2><<<gp, tp>>>(value, wV, nullptr);

    const int smem = (64 * 513 + 2 * 64 * 68) * (int)sizeof(float);  // 166,144 B
    cudaFuncSetAttribute((const void*)attn_kernel,
                         cudaFuncAttributeMaxDynamicSharedMemorySize, smem);
    attn_kernel<<<dim3(8, 128), 512, smem>>>(mask, aiw, outp);

    proj_mma<3><<<gp, tp>>>(nullptr, wfc, outx);
}

// round 8
// speedup vs baseline: 1.3796x; 1.2244x over previous
#include <cuda_runtime.h>
#include <cuda_bf16.h>
#include <cstdint>

#define Bsz 16
#define Lsz 512
#define Dsz 512
#define Hsz 8
#define DKsz 64
#define BHsz (Bsz*Hsz)

#define SD 516   // score row stride (floats), 16B-aligned rows
#define BS 72    // bf16 buffer row stride (halves)

// Scratch (allocation-free contract: __device__ globals)
__device__ float g_q[Bsz*Hsz*Lsz*DKsz];
__device__ float g_k[Bsz*Hsz*Lsz*DKsz];
__device__ float g_v[Bsz*Hsz*Lsz*DKsz];
__device__ float g_x[Bsz*Lsz*Dsz];

// ---------------------------------------------------------------------------
__device__ __forceinline__ void mma_bf16(float* c, const uint32_t* a, const uint32_t* b)
{
    asm volatile(
        "mma.sync.aligned.m16n8k16.row.col.f32.bf16.bf16.f32 "
        "{%0,%1,%2,%3}, {%4,%5,%6,%7}, {%8,%9}, {%0,%1,%2,%3};\n"
        : "+f"(c[0]), "+f"(c[1]), "+f"(c[2]), "+f"(c[3])
        : "r"(a[0]), "r"(a[1]), "r"(a[2]), "r"(a[3]), "r"(b[0]), "r"(b[1]));
}

// split 8 consecutive fp32 into bf16 hi/lo, vector-stored
__device__ __forceinline__ void split8(float4 v0, float4 v1,
                                       __nv_bfloat16* dh, __nv_bfloat16* dl)
{
    __align__(16) __nv_bfloat16 hh[8], ll[8];
    float vv[8] = {v0.x, v0.y, v0.z, v0.w, v1.x, v1.y, v1.z, v1.w};
    #pragma unroll
    for (int e = 0; e < 8; e++) {
        __nv_bfloat16 h = __float2bfloat16(vv[e]);
        hh[e] = h;
        ll[e] = __float2bfloat16(vv[e] - __bfloat162float(h));
    }
    *(uint4*)dh = *(const uint4*)hh;
    *(uint4*)dl = *(const uint4*)ll;
}

// ---------------------------------------------------------------------------
// bf16x2-split tensor-core GEMM: C[8192,512] = X[8192,512] @ W[512,512]
// (validated in R6: rel_err ~1.1e-5)
// ---------------------------------------------------------------------------
template<int MODE>
__global__ __launch_bounds__(256) void proj_mma(const float* __restrict__ Xin,
                                                const float* __restrict__ W,
                                                float* __restrict__ outp)
{
    const float* X = (MODE == 3) ? g_x : Xin;

    __shared__ __nv_bfloat16 Ah[128][40];
    __shared__ __nv_bfloat16 Al[128][40];
    __shared__ __nv_bfloat16 Bh[64][40];
    __shared__ __nv_bfloat16 Bl[64][40];

    const int tid  = threadIdx.x;
    const int wid  = tid >> 5;
    const int lane = tid & 31;
    const int wm = (wid >> 1) * 32;
    const int wn = (wid & 1) * 32;
    const int g  = lane >> 2;
    const int t4 = lane & 3;

    const int mBase = blockIdx.x * 128;
    const int nBase = blockIdx.y * 64;

    const int ar = tid >> 1;
    const int ac = (tid & 1) * 16;
    const int bn = tid & 63;
    const int bk = (tid >> 6) * 8;

    float acc[2][4][4] = {};

    for (int k0 = 0; k0 < 512; k0 += 32) {
        #pragma unroll
        for (int j = 0; j < 4; j++) {
            const int cc = ac + j * 4;
            float4 v = *(const float4*)&X[(size_t)(mBase + ar) * 512 + k0 + cc];
            float vv[4] = {v.x, v.y, v.z, v.w};
            #pragma unroll
            for (int e = 0; e < 4; e++) {
                __nv_bfloat16 h = __float2bfloat16(vv[e]);
                __nv_bfloat16 l = __float2bfloat16(vv[e] - __bfloat162float(h));
                Ah[ar][cc + e] = h;
                Al[ar][cc + e] = l;
            }
        }
        {
            __align__(16) __nv_bfloat16 bh8[8];
            __align__(16) __nv_bfloat16 bl8[8];
            #pragma unroll
            for (int i = 0; i < 8; i++) {
                float w = W[(size_t)(k0 + bk + i) * 512 + nBase + bn];
                __nv_bfloat16 h = __float2bfloat16(w);
                bh8[i] = h;
                bl8[i] = __float2bfloat16(w - __bfloat162float(h));
            }
            *(uint4*)&Bh[bn][bk] = *(const uint4*)bh8;
            *(uint4*)&Bl[bn][bk] = *(const uint4*)bl8;
        }
        __syncthreads();

        #pragma unroll
        for (int ks = 0; ks < 32; ks += 16) {
            uint32_t a_h[2][4], a_l[2][4];
            #pragma unroll
            for (int mf = 0; mf < 2; mf++) {
                const int r0 = wm + mf * 16 + g;
                a_h[mf][0] = *(const uint32_t*)&Ah[r0    ][ks + 2 * t4];
                a_h[mf][1] = *(const uint32_t*)&Ah[r0 + 8][ks + 2 * t4];
                a_h[mf][2] = *(const uint32_t*)&Ah[r0    ][ks + 2 * t4 + 8];
                a_h[mf][3] = *(const uint32_t*)&Ah[r0 + 8][ks + 2 * t4 + 8];
                a_l[mf][0] = *(const uint32_t*)&Al[r0    ][ks + 2 * t4];
                a_l[mf][1] = *(const uint32_t*)&Al[r0 + 8][ks + 2 * t4];
                a_l[mf][2] = *(const uint32_t*)&Al[r0    ][ks + 2 * t4 + 8];
                a_l[mf][3] = *(const uint32_t*)&Al[r0 + 8][ks + 2 * t4 + 8];
            }
            #pragma unroll
            for (int nf = 0; nf < 4; nf++) {
                const int nc = wn + nf * 8 + g;
                uint32_t b_h[2], b_l[2];
                b_h[0] = *(const uint32_t*)&Bh[nc][ks + 2 * t4];
                b_h[1] = *(const uint32_t*)&Bh[nc][ks + 2 * t4 + 8];
                b_l[0] = *(const uint32_t*)&Bl[nc][ks + 2 * t4];
                b_l[1] = *(const uint32_t*)&Bl[nc][ks + 2 * t4 + 8];
                #pragma unroll
                for (int mf = 0; mf < 2; mf++) {
                    mma_bf16(acc[mf][nf], a_h[mf], b_h);
                    mma_bf16(acc[mf][nf], a_h[mf], b_l);
                    mma_bf16(acc[mf][nf], a_l[mf], b_h);
                }
            }
        }
        __syncthreads();
    }

    #pragma unroll
    for (int mf = 0; mf < 2; mf++) {
        #pragma unroll
        for (int nf = 0; nf < 4; nf++) {
            const int col = wn + nf * 8 + 2 * t4;
            const int r0  = mBase + wm + mf * 16 + g;
            const int r1  = r0 + 8;
            float2 lo2 = {acc[mf][nf][0], acc[mf][nf][1]};
            float2 hi2 = {acc[mf][nf][2], acc[mf][nf][3]};
            if (MODE == 3) {
                *(float2*)&outp[(size_t)r0 * 512 + nBase + col] = lo2;
                *(float2*)&outp[(size_t)r1 * 512 + nBase + col] = hi2;
            } else {
                float* dst = (MODE == 0) ? g_q : (MODE == 1) ? g_k : g_v;
                const int h = blockIdx.y;
                const int b0 = r0 >> 9, l0 = r0 & 511;
                const int b1 = r1 >> 9, l1 = r1 & 511;
                *(float2*)&dst[(((size_t)b0 * Hsz + h) * Lsz + l0) * DKsz + col] = lo2;
                *(float2*)&dst[(((size_t)b1 * Hsz + h) * Lsz + l1) * DKsz + col] = hi2;
            }
        }
    }
}

// ---------------------------------------------------------------------------
// Tensor-core fused attention. 512 threads = 16 warps (4m x 4n).
// smem: s[64][516] fp32 (132,096B) + 4 bf16 bufs [64][72] (36,864B) = 168,960B
// Phase1: S = QK^T/8 (bf16-split mma, 8 n-chunks). Phase2: softmax etc.
// Phase3: X = P V (bf16-split mma, 8 k-chunks, bufs reused for P/V).
// ---------------------------------------------------------------------------
__global__ __launch_bounds__(512) void attn_mma(const int* __restrict__ mask,
                                                const float* __restrict__ aiw,
                                                float* __restrict__ p_out)
{
    extern __shared__ float sm[];
    float* s = sm;                                        // [64][516]
    __nv_bfloat16* bufs = (__nv_bfloat16*)(sm + 64 * SD);
    __nv_bfloat16* B0 = bufs;              // Qh / Ph
    __nv_bfloat16* B1 = bufs + 64 * BS;    // Ql / Pl
    __nv_bfloat16* B2 = bufs + 2 * 64 * BS; // Kh / Vh
    __nv_bfloat16* B3 = bufs + 3 * 64 * BS; // Kl / Vl

    const int tid  = threadIdx.x;
    const int wid  = tid >> 5;
    const int lane = tid & 31;
    const int g  = lane >> 2;
    const int t4 = lane & 3;
    const int wm = (wid & 3) * 16;     // warp m offset
    const int wc = wid >> 2;           // warp n group (0..3), 16 cols each

    const int bh = blockIdx.y;
    const int b  = bh >> 3;
    const int h  = bh & 7;
    const int qBase = blockIdx.x * 64;

    const int cr = tid >> 3;           // conversion row 0..63
    const int cc = (tid & 7) * 8;      // conversion col base 0..56

    // ---- convert Q tile once: [m][dk] hi/lo
    {
        const float* qg = g_q + ((size_t)bh * Lsz + qBase) * DKsz;
        float4 v0 = *(const float4*)&qg[cr * 64 + cc];
        float4 v1 = *(const float4*)&qg[cr * 64 + cc + 4];
        split8(v0, v1, &B0[cr * BS + cc], &B1[cr * BS + cc]);
    }

    // ---- Phase 1: S = Q K^T / 8
    for (int nt = 0; nt < 8; nt++) {
        const float* kg = g_k + ((size_t)bh * Lsz + nt * 64) * DKsz;
        float4 v0 = *(const float4*)&kg[cr * 64 + cc];
        float4 v1 = *(const float4*)&kg[cr * 64 + cc + 4];
        split8(v0, v1, &B2[cr * BS + cc], &B3[cr * BS + cc]);
        __syncthreads();

        float acc[2][4] = {};
        #pragma unroll
        for (int ks = 0; ks < 64; ks += 16) {
            uint32_t ah[4], al[4];
            const int r0 = wm + g;
            ah[0] = *(const uint32_t*)&B0[ r0      * BS + ks + 2 * t4];
            ah[1] = *(const uint32_t*)&B0[(r0 + 8) * BS + ks + 2 * t4];
            ah[2] = *(const uint32_t*)&B0[ r0      * BS + ks + 2 * t4 + 8];
            ah[3] = *(const uint32_t*)&B0[(r0 + 8) * BS + ks + 2 * t4 + 8];
            al[0] = *(const uint32_t*)&B1[ r0      * BS + ks + 2 * t4];
            al[1] = *(const uint32_t*)&B1[(r0 + 8) * BS + ks + 2 * t4];
            al[2] = *(const uint32_t*)&B1[ r0      * BS + ks + 2 * t4 + 8];
            al[3] = *(const uint32_t*)&B1[(r0 + 8) * BS + ks + 2 * t4 + 8];
            #pragma unroll
            for (int nf = 0; nf < 2; nf++) {
                const int nc = wc * 16 + nf * 8 + g;
                uint32_t bhv[2], blv[2];
                bhv[0] = *(const uint32_t*)&B2[nc * BS + ks + 2 * t4];
                bhv[1] = *(const uint32_t*)&B2[nc * BS + ks + 2 * t4 + 8];
                blv[0] = *(const uint32_t*)&B3[nc * BS + ks + 2 * t4];
                blv[1] = *(const uint32_t*)&B3[nc * BS + ks + 2 * t4 + 8];
                mma_bf16(acc[nf], ah, bhv);
                mma_bf16(acc[nf], ah, blv);
                mma_bf16(acc[nf], al, bhv);
            }
        }
        #pragma unroll
        for (int nf = 0; nf < 2; nf++) {
            const int col = nt * 64 + wc * 16 + nf * 8 + 2 * t4;
            const int row = wm + g;
            s[ row      * SD + col    ] = acc[nf][0] * 0.125f;
            s[ row      * SD + col + 1] = acc[nf][1] * 0.125f;
            s[(row + 8) * SD + col    ] = acc[nf][2] * 0.125f;
            s[(row + 8) * SD + col + 1] = acc[nf][3] * 0.125f;
        }
        __syncthreads();
    }

    // ---- Phase 2: mask + softmax + *aiw + p_attn write (16 warps x 4 rows)
    {
        #pragma unroll
        for (int r = 0; r < 4; r++) {
            const int m = wid * 4 + r;
            const int qRow = qBase + m;
            const int*   mrow = mask + ((size_t)b * Lsz + qRow) * Lsz;
            const float* arow = aiw  + ((size_t)b * Lsz + qRow) * Lsz;
            float* srow = s + m * SD;

            float mx = -1e30f;
            for (int k = lane; k < 512; k += 32) {
                float v = (mrow[k] != 0) ? -1e30f : srow[k];
                srow[k] = v;
                mx = fmaxf(mx, v);
            }
            #pragma unroll
            for (int o = 16; o; o >>= 1) mx = fmaxf(mx, __shfl_xor_sync(0xffffffffu, mx, o));

            float sum = 0.f;
            for (int k = lane; k < 512; k += 32) {
                float e = __expf(srow[k] - mx);
                srow[k] = e;
                sum += e;
            }
            #pragma unroll
            for (int o = 16; o; o >>= 1) sum += __shfl_xor_sync(0xffffffffu, sum, o);
            const float inv = 1.f / sum;

            float* prow = p_out + ((size_t)bh * Lsz + qRow) * Lsz;
            for (int k = lane; k < 512; k += 32) {
                float p = srow[k] * inv * arow[k];
                srow[k] = p;
                prow[k] = p;
            }
        }
    }
    __syncthreads();

    // ---- Phase 3: X = P V  (accumulate across 8 k-chunks)
    float acc[2][4] = {};
    for (int kt = 0; kt < 8; kt++) {
        // P chunk -> B0/B1 ([m][kpos])
        {
            const float* ps = &s[cr * SD + kt * 64 + cc];
            split8(*(const float4*)ps, *(const float4*)(ps + 4),
                   &B0[cr * BS + cc], &B1[cr * BS + cc]);
        }
        // V chunk transposed -> B2/B3 ([dk][kpos])
        {
            const float* vg = g_v + ((size_t)bh * Lsz + kt * 64) * DKsz;
            float4 v0 = *(const float4*)&vg[cr * 64 + cc];
            float4 v1 = *(const float4*)&vg[cr * 64 + cc + 4];
            float vv[8] = {v0.x, v0.y, v0.z, v0.w, v1.x, v1.y, v1.z, v1.w};
            #pragma unroll
            for (int e = 0; e < 8; e++) {
                __nv_bfloat16 hh = __float2bfloat16(vv[e]);
                B2[(cc + e) * BS + cr] = hh;
                B3[(cc + e) * BS + cr] = __float2bfloat16(vv[e] - __bfloat162float(hh));
            }
        }
        __syncthreads();

        #pragma unroll
        for (int ks = 0; ks < 64; ks += 16) {
            uint32_t ah[4], al[4];
            const int r0 = wm + g;
            ah[0] = *(const uint32_t*)&B0[ r0      * BS + ks + 2 * t4];
            ah[1] = *(const uint32_t*)&B0[(r0 + 8) * BS + ks + 2 * t4];
            ah[2] = *(const uint32_t*)&B0[ r0      * BS + ks + 2 * t4 + 8];
            ah[3] = *(const uint32_t*)&B0[(r0 + 8) * BS + ks + 2 * t4 + 8];
            al[0] = *(const uint32_t*)&B1[ r0      * BS + ks + 2 * t4];
            al[1] = *(const uint32_t*)&B1[(r0 + 8) * BS + ks + 2 * t4];
            al[2] = *(const uint32_t*)&B1[ r0      * BS + ks + 2 * t4 + 8];
            al[3] = *(const uint32_t*)&B1[(r0 + 8) * BS + ks + 2 * t4 + 8];
            #pragma unroll
            for (int nf = 0; nf < 2; nf++) {
                const int nc = wc * 16 + nf * 8 + g;
                uint32_t bhv[2], blv[2];
                bhv[0] = *(const uint32_t*)&B2[nc * BS + ks + 2 * t4];
                bhv[1] = *(const uint32_t*)&B2[nc * BS + ks + 2 * t4 + 8];
                blv[0] = *(const uint32_t*)&B3[nc * BS + ks + 2 * t4];
                blv[1] = *(const uint32_t*)&B3[nc * BS + ks + 2 * t4 + 8];
                mma_bf16(acc[nf], ah, bhv);
                mma_bf16(acc[nf], ah, blv);
                mma_bf16(acc[nf], al, bhv);
            }
        }
        __syncthreads();
    }

    // ---- X epilogue
    #pragma unroll
    for (int nf = 0; nf < 2; nf++) {
        const int col = wc * 16 + nf * 8 + 2 * t4;   // dk within head
        const int row = qBase + wm + g;
        float2 lo2 = {acc[nf][0], acc[nf][1]};
        float2 hi2 = {acc[nf][2], acc[nf][3]};
        *(float2*)&g_x[((size_t)b * Lsz + row    ) * Dsz + h * 64 + col] = lo2;
        *(float2*)&g_x[((size_t)b * Lsz + row + 8) * Dsz + h * 64 + col] = hi2;
    }
}

// ---------------------------------------------------------------------------
extern "C" void kernel_launch(void* const* d_in, const int* in_sizes, int n_in,
                              void* d_out, int out_size)
{
    (void)in_sizes; (void)n_in; (void)out_size;
    const float* query = (const float*)d_in[0];
    const float* keyt  = (const float*)d_in[1];
    const float* value = (const float*)d_in[2];
    const int*   mask  = (const int*)d_in[3];     // bool upcast to int32
    const float* aiw   = (const float*)d_in[4];
    const float* wQ    = (const float*)d_in[5];
    const float* wK    = (const float*)d_in[6];
    const float* wV    = (const float*)d_in[7];
    const float* wfc   = (const float*)d_in[8];

    float* outx = (float*)d_out;                       // x: [B,L,D]
    float* outp = outx + (size_t)Bsz * Lsz * Dsz;      // p_attn: [B,H,L,L]

    dim3 gp(64, 8), tp(256);
    proj_mma<0><<<gp, tp>>>(query, wQ, nullptr);
    proj_mma<1><<<gp, tp>>>(keyt,  wK, nullptr);
    proj_mma<2><<<gp, tp>>>(value, wV, nullptr);

    const int smem = 64 * SD * (int)sizeof(float)
                   + 4 * 64 * BS * (int)sizeof(__nv_bfloat16);   // 168,960 B
    cudaFuncSetAttribute((const void*)attn_mma,
                         cudaFuncAttributeMaxDynamicSharedMemorySize, smem);
    attn_mma<<<dim3(8, 128), 512, smem>>>(mask, aiw, outp);

    proj_mma<3><<<gp, tp>>>(nullptr, wfc, outx);
}

// round 9
// speedup vs baseline: 1.6097x; 1.1668x over previous
#include <cuda_runtime.h>
#include <cuda_bf16.h>
#include <cstdint>

#define Bsz 16
#define Lsz 512
#define Dsz 512
#define Hsz 8
#define DKsz 64
#define BHsz (Bsz*Hsz)

#define SD 516   // score row stride (floats)
#define BS 72    // bf16 buffer row stride (halves)

// Scratch (allocation-free contract: __device__ globals)
// Q,K: [BH][L][DK] bf16 hi/lo.  V: transposed [BH][DK][L] bf16 hi/lo.
__device__ __nv_bfloat16 g_qh[BHsz*Lsz*DKsz], g_ql[BHsz*Lsz*DKsz];
__device__ __nv_bfloat16 g_kh[BHsz*Lsz*DKsz], g_kl[BHsz*Lsz*DKsz];
__device__ __nv_bfloat16 g_vth[BHsz*DKsz*Lsz], g_vtl[BHsz*DKsz*Lsz];
__device__ float g_x[Bsz*Lsz*Dsz];

// ---------------------------------------------------------------------------
__device__ __forceinline__ void mma_bf16(float* c, const uint32_t* a, const uint32_t* b)
{
    asm volatile(
        "mma.sync.aligned.m16n8k16.row.col.f32.bf16.bf16.f32 "
        "{%0,%1,%2,%3}, {%4,%5,%6,%7}, {%8,%9}, {%0,%1,%2,%3};\n"
        : "+f"(c[0]), "+f"(c[1]), "+f"(c[2]), "+f"(c[3])
        : "r"(a[0]), "r"(a[1]), "r"(a[2]), "r"(a[3]), "r"(b[0]), "r"(b[1]));
}

__device__ __forceinline__ void ldsm_x4(uint32_t* r, const void* p)
{
    uint32_t a = (uint32_t)__cvta_generic_to_shared(p);
    asm volatile("ldmatrix.sync.aligned.m8n8.x4.shared.b16 {%0,%1,%2,%3}, [%4];"
                 : "=r"(r[0]), "=r"(r[1]), "=r"(r[2]), "=r"(r[3]) : "r"(a));
}

// split 8 consecutive fp32 into bf16 hi/lo, vector-stored to smem
__device__ __forceinline__ void split8(float4 v0, float4 v1,
                                       __nv_bfloat16* dh, __nv_bfloat16* dl)
{
    __align__(16) __nv_bfloat16 hh[8], ll[8];
    float vv[8] = {v0.x, v0.y, v0.z, v0.w, v1.x, v1.y, v1.z, v1.w};
    #pragma unroll
    for (int e = 0; e < 8; e++) {
        __nv_bfloat16 h = __float2bfloat16(vv[e]);
        hh[e] = h;
        ll[e] = __float2bfloat16(vv[e] - __bfloat162float(h));
    }
    *(uint4*)dh = *(const uint4*)hh;
    *(uint4*)dl = *(const uint4*)ll;
}

__device__ __forceinline__ void split2(float x, float y, uint32_t& hp, uint32_t& lp)
{
    __nv_bfloat16 hx = __float2bfloat16(x), hy = __float2bfloat16(y);
    __nv_bfloat16 lx = __float2bfloat16(x - __bfloat162float(hx));
    __nv_bfloat16 ly = __float2bfloat16(y - __bfloat162float(hy));
    __nv_bfloat162 hh = {hx, hy}, ll = {lx, ly};
    hp = *(uint32_t*)&hh;
    lp = *(uint32_t*)&ll;
}

// ---------------------------------------------------------------------------
// bf16x2-split tensor-core GEMM: C[8192,512] = X[8192,512] @ W[512,512]
// BM=128,BN=64,BK=32, 8 warps (4m x 2n), warp 32x32. Register double-buffered
// global loads + ldmatrix fragment loads.
// MODE 0: ->g_qh/g_ql   MODE 1: ->g_kh/g_kl   MODE 2: ->g_vth/g_vtl (transposed)
// MODE 3: g_x @ wfc -> outp (fp32)
// ---------------------------------------------------------------------------
template<int MODE>
__global__ __launch_bounds__(256) void proj_mma(const float* __restrict__ Xin,
                                                const float* __restrict__ W,
                                                float* __restrict__ outp)
{
    const float* X = (MODE == 3) ? g_x : Xin;

    __shared__ __nv_bfloat16 Ah[128][40];
    __shared__ __nv_bfloat16 Al[128][40];
    __shared__ __nv_bfloat16 Bh[64][40];
    __shared__ __nv_bfloat16 Bl[64][40];

    const int tid  = threadIdx.x;
    const int wid  = tid >> 5;
    const int lane = tid & 31;
    const int wm = (wid >> 1) * 32;
    const int wn = (wid & 1) * 32;
    const int g  = lane >> 2;
    const int t4 = lane & 3;

    const int mBase = blockIdx.x * 128;
    const int nBase = blockIdx.y * 64;

    const int ar = tid >> 1;
    const int ac = (tid & 1) * 16;
    const int bn = tid & 63;
    const int bk = (tid >> 6) * 8;

    // ldmatrix source offsets (per-lane constant parts)
    const int a_r0 = wm + (lane & 15);
    const int a_c  = (lane >> 4) << 3;
    const int b_r0 = wn + (lane & 7) + ((lane >> 4) << 3);
    const int b_c  = ((lane >> 3) & 1) * 8;

    float acc[2][4][4] = {};

    float4 a_stage[4];
    float  b_stage[8];

    // prologue: stage tile 0
    #pragma unroll
    for (int j = 0; j < 4; j++)
        a_stage[j] = *(const float4*)&X[(size_t)(mBase + ar) * 512 + ac + j * 4];
    #pragma unroll
    for (int i = 0; i < 8; i++)
        b_stage[i] = W[(size_t)(bk + i) * 512 + nBase + bn];

    for (int k0 = 0; k0 < 512; k0 += 32) {
        // ---- convert staged regs -> smem
        #pragma unroll
        for (int j = 0; j < 4; j++) {
            const int cc = ac + j * 4;
            float vv[4] = {a_stage[j].x, a_stage[j].y, a_stage[j].z, a_stage[j].w};
            #pragma unroll
            for (int e = 0; e < 4; e++) {
                __nv_bfloat16 h = __float2bfloat16(vv[e]);
                Ah[ar][cc + e] = h;
                Al[ar][cc + e] = __float2bfloat16(vv[e] - __bfloat162float(h));
            }
        }
        {
            __align__(16) __nv_bfloat16 bh8[8], bl8[8];
            #pragma unroll
            for (int i = 0; i < 8; i++) {
                __nv_bfloat16 h = __float2bfloat16(b_stage[i]);
                bh8[i] = h;
                bl8[i] = __float2bfloat16(b_stage[i] - __bfloat162float(h));
            }
            *(uint4*)&Bh[bn][bk] = *(const uint4*)bh8;
            *(uint4*)&Bl[bn][bk] = *(const uint4*)bl8;
        }
        __syncthreads();

        // ---- prefetch next tile into regs (overlaps with compute below)
        if (k0 + 32 < 512) {
            #pragma unroll
            for (int j = 0; j < 4; j++)
                a_stage[j] = *(const float4*)&X[(size_t)(mBase + ar) * 512 + k0 + 32 + ac + j * 4];
            #pragma unroll
            for (int i = 0; i < 8; i++)
                b_stage[i] = W[(size_t)(k0 + 32 + bk + i) * 512 + nBase + bn];
        }

        // ---- compute 2 ks steps
        #pragma unroll
        for (int ks = 0; ks < 32; ks += 16) {
            uint32_t ah0[4], ah1[4], al0[4], al1[4];
            ldsm_x4(ah0, &Ah[a_r0     ][ks + a_c]);
            ldsm_x4(ah1, &Ah[a_r0 + 16][ks + a_c]);
            ldsm_x4(al0, &Al[a_r0     ][ks + a_c]);
            ldsm_x4(al1, &Al[a_r0 + 16][ks + a_c]);
            uint32_t bh01[4], bh23[4], bl01[4], bl23[4];
            ldsm_x4(bh01, &Bh[b_r0     ][ks + b_c]);
            ldsm_x4(bh23, &Bh[b_r0 + 16][ks + b_c]);
            ldsm_x4(bl01, &Bl[b_r0     ][ks + b_c]);
            ldsm_x4(bl23, &Bl[b_r0 + 16][ks + b_c]);

            const uint32_t* AH[2] = {ah0, ah1};
            const uint32_t* AL[2] = {al0, al1};
            const uint32_t* BH[4] = {&bh01[0], &bh01[2], &bh23[0], &bh23[2]};
            const uint32_t* BL[4] = {&bl01[0], &bl01[2], &bl23[0], &bl23[2]};
            #pragma unroll
            for (int mf = 0; mf < 2; mf++)
                #pragma unroll
                for (int nf = 0; nf < 4; nf++) {
                    mma_bf16(acc[mf][nf], AH[mf], BH[nf]);
                    mma_bf16(acc[mf][nf], AH[mf], BL[nf]);
                    mma_bf16(acc[mf][nf], AL[mf], BH[nf]);
                }
        }
        __syncthreads();
    }

    // ---- epilogue
    #pragma unroll
    for (int mf = 0; mf < 2; mf++) {
        #pragma unroll
        for (int nf = 0; nf < 4; nf++) {
            const int col = wn + nf * 8 + 2 * t4;
            const int r0  = mBase + wm + mf * 16 + g;
            const int r1  = r0 + 8;
            float v0 = acc[mf][nf][0], v1 = acc[mf][nf][1];
            float v2 = acc[mf][nf][2], v3 = acc[mf][nf][3];
            if (MODE == 3) {
                float2 lo2 = {v0, v1}, hi2 = {v2, v3};
                *(float2*)&outp[(size_t)r0 * 512 + nBase + col] = lo2;
                *(float2*)&outp[(size_t)r1 * 512 + nBase + col] = hi2;
            } else {
                const int hh = blockIdx.y;               // BN=64 == DK
                const int b0 = r0 >> 9, l0 = r0 & 511;
                const int b1 = r1 >> 9, l1 = r1 & 511;
                if (MODE == 2) {
                    // transposed V: [bh][dk][L]
                    __nv_bfloat16 h0 = __float2bfloat16(v0);
                    __nv_bfloat16 h1 = __float2bfloat16(v1);
                    __nv_bfloat16 h2 = __float2bfloat16(v2);
                    __nv_bfloat16 h3 = __float2bfloat16(v3);
                    size_t c0 = ((size_t)(b0 * Hsz + hh) * DKsz + col) * Lsz;
                    size_t c1 = ((size_t)(b0 * Hsz + hh) * DKsz + col + 1) * Lsz;
                    g_vth[c0 + l0] = h0;
                    g_vtl[c0 + l0] = __float2bfloat16(v0 - __bfloat162float(h0));
                    g_vth[c1 + l0] = h1;
                    g_vtl[c1 + l0] = __float2bfloat16(v1 - __bfloat162float(h1));
                    g_vth[c0 + l1] = h2;
                    g_vtl[c0 + l1] = __float2bfloat16(v2 - __bfloat162float(h2));
                    g_vth[c1 + l1] = h3;
                    g_vtl[c1 + l1] = __float2bfloat16(v3 - __bfloat162float(h3));
                } else {
                    __nv_bfloat16* dh = (MODE == 0) ? g_qh : g_kh;
                    __nv_bfloat16* dl = (MODE == 0) ? g_ql : g_kl;
                    uint32_t hp, lp;
                    split2(v0, v1, hp, lp);
                    size_t i0 = (((size_t)b0 * Hsz + hh) * Lsz + l0) * DKsz + col;
                    *(uint32_t*)&dh[i0] = hp;
                    *(uint32_t*)&dl[i0] = lp;
                    split2(v2, v3, hp, lp);
                    size_t i1 = (((size_t)b1 * Hsz + hh) * Lsz + l1) * DKsz + col;
                    *(uint32_t*)&dh[i1] = hp;
                    *(uint32_t*)&dl[i1] = lp;
                }
            }
        }
    }
}

// ---------------------------------------------------------------------------
// Tensor-core fused attention. 512 threads = 16 warps (4m x 4n).
// smem: s[64][516] fp32 + 4 bf16 bufs [64][72] = 168,960 B.
// Q/K/V arrive pre-split bf16 (hi/lo); V pre-transposed. Register
// double-buffered chunk loads; ldmatrix fragment loads.
// ---------------------------------------------------------------------------
__global__ __launch_bounds__(512) void attn_mma(const int* __restrict__ mask,
                                                const float* __restrict__ aiw,
                                                float* __restrict__ p_out)
{
    extern __shared__ float sm[];
    float* s = sm;                                        // [64][516]
    __nv_bfloat16* bufs = (__nv_bfloat16*)(sm + 64 * SD);
    __nv_bfloat16* B0 = bufs;               // Qh / Ph
    __nv_bfloat16* B1 = bufs + 64 * BS;     // Ql / Pl
    __nv_bfloat16* B2 = bufs + 2 * 64 * BS; // Kh / Vh
    __nv_bfloat16* B3 = bufs + 3 * 64 * BS; // Kl / Vl

    const int tid  = threadIdx.x;
    const int wid  = tid >> 5;
    const int lane = tid & 31;
    const int g  = lane >> 2;
    const int t4 = lane & 3;
    const int wm = (wid & 3) * 16;
    const int wc = wid >> 2;

    const int bh = blockIdx.y;
    const int b  = bh >> 3;
    const int h  = bh & 7;
    const int qBase = blockIdx.x * 64;

    const int cr = tid >> 3;           // copy row 0..63
    const int cc = (tid & 7) * 8;      // copy col base (halves)

    // ldmatrix per-lane address parts
    const int a_r = wm + (lane & 15);
    const int a_c = (lane >> 4) << 3;
    const int b_r = wc * 16 + (lane & 7) + ((lane >> 4) << 3);
    const int b_c = ((lane >> 3) & 1) * 8;

    // ---- Q tile copy (pre-split)
    {
        const size_t qo = ((size_t)bh * Lsz + qBase + cr) * DKsz + cc;
        *(uint4*)&B0[cr * BS + cc] = *(const uint4*)&g_qh[qo];
        *(uint4*)&B1[cr * BS + cc] = *(const uint4*)&g_ql[qo];
    }

    // ---- Phase 1: S = Q K^T / 8 (register double-buffered K chunks)
    uint4 kh = *(const uint4*)&g_kh[((size_t)bh * Lsz + cr) * DKsz + cc];
    uint4 kl = *(const uint4*)&g_kl[((size_t)bh * Lsz + cr) * DKsz + cc];

    for (int nt = 0; nt < 8; nt++) {
        __syncthreads();                       // prev compute done (and Q stored, nt=0)
        *(uint4*)&B2[cr * BS + cc] = kh;
        *(uint4*)&B3[cr * BS + cc] = kl;
        __syncthreads();
        if (nt < 7) {
            const size_t ko = ((size_t)bh * Lsz + (nt + 1) * 64 + cr) * DKsz + cc;
            kh = *(const uint4*)&g_kh[ko];
            kl = *(const uint4*)&g_kl[ko];
        }

        float acc[2][4] = {};
        #pragma unroll
        for (int ks = 0; ks < 64; ks += 16) {
            uint32_t ah[4], al[4], bhv[4], blv[4];
            ldsm_x4(ah,  &B0[a_r * BS + ks + a_c]);
            ldsm_x4(al,  &B1[a_r * BS + ks + a_c]);
            ldsm_x4(bhv, &B2[b_r * BS + ks + b_c]);
            ldsm_x4(blv, &B3[b_r * BS + ks + b_c]);
            mma_bf16(acc[0], ah, &bhv[0]);
            mma_bf16(acc[0], ah, &blv[0]);
            mma_bf16(acc[0], al, &bhv[0]);
            mma_bf16(acc[1], ah, &bhv[2]);
            mma_bf16(acc[1], ah, &blv[2]);
            mma_bf16(acc[1], al, &bhv[2]);
        }
        #pragma unroll
        for (int nf = 0; nf < 2; nf++) {
            const int col = nt * 64 + wc * 16 + nf * 8 + 2 * t4;
            const int row = wm + g;
            s[ row      * SD + col    ] = acc[nf][0] * 0.125f;
            s[ row      * SD + col + 1] = acc[nf][1] * 0.125f;
            s[(row + 8) * SD + col    ] = acc[nf][2] * 0.125f;
            s[(row + 8) * SD + col + 1] = acc[nf][3] * 0.125f;
        }
    }
    __syncthreads();

    // ---- Phase 2: mask + softmax + *aiw + p_attn write (16 warps x 4 rows)
    {
        #pragma unroll
        for (int r = 0; r < 4; r++) {
            const int m = wid * 4 + r;
            const int qRow = qBase + m;
            const int*   mrow = mask + ((size_t)b * Lsz + qRow) * Lsz;
            const float* arow = aiw  + ((size_t)b * Lsz + qRow) * Lsz;
            float* srow = s + m * SD;

            float mx = -1e30f;
            for (int k = lane; k < 512; k += 32) {
                float v = (mrow[k] != 0) ? -1e30f : srow[k];
                srow[k] = v;
                mx = fmaxf(mx, v);
            }
            #pragma unroll
            for (int o = 16; o; o >>= 1) mx = fmaxf(mx, __shfl_xor_sync(0xffffffffu, mx, o));

            float sum = 0.f;
            for (int k = lane; k < 512; k += 32) {
                float e = __expf(srow[k] - mx);
                srow[k] = e;
                sum += e;
            }
            #pragma unroll
            for (int o = 16; o; o >>= 1) sum += __shfl_xor_sync(0xffffffffu, sum, o);
            const float inv = 1.f / sum;

            float* prow = p_out + ((size_t)bh * Lsz + qRow) * Lsz;
            for (int k = lane; k < 512; k += 32) {
                float p = srow[k] * inv * arow[k];
                srow[k] = p;
                prow[k] = p;
            }
        }
    }
    __syncthreads();

    // ---- Phase 3: X = P V (V pre-transposed [dk][L]; double-buffered)
    uint4 vh = *(const uint4*)&g_vth[((size_t)bh * DKsz + cr) * Lsz + cc];
    uint4 vl = *(const uint4*)&g_vtl[((size_t)bh * DKsz + cr) * Lsz + cc];

    float acc[2][4] = {};
    for (int kt = 0; kt < 8; kt++) {
        __syncthreads();
        *(uint4*)&B2[cr * BS + cc] = vh;       // row cr = dk, cols = kpos
        *(uint4*)&B3[cr * BS + cc] = vl;
        {
            const float* ps = &s[cr * SD + kt * 64 + cc];
            split8(*(const float4*)ps, *(const float4*)(ps + 4),
                   &B0[cr * BS + cc], &B1[cr * BS + cc]);
        }
        __syncthreads();
        if (kt < 7) {
            const size_t vo = ((size_t)bh * DKsz + cr) * Lsz + (kt + 1) * 64 + cc;
            vh = *(const uint4*)&g_vth[vo];
            vl = *(const uint4*)&g_vtl[vo];
        }

        #pragma unroll
        for (int ks = 0; ks < 64; ks += 16) {
            uint32_t ah[4], al[4], bhv[4], blv[4];
            ldsm_x4(ah,  &B0[a_r * BS + ks + a_c]);
            ldsm_x4(al,  &B1[a_r * BS + ks + a_c]);
            ldsm_x4(bhv, &B2[b_r * BS + ks + b_c]);
            ldsm_x4(blv, &B3[b_r * BS + ks + b_c]);
            mma_bf16(acc[0], ah, &bhv[0]);
            mma_bf16(acc[0], ah, &blv[0]);
            mma_bf16(acc[0], al, &bhv[0]);
            mma_bf16(acc[1], ah, &bhv[2]);
            mma_bf16(acc[1], ah, &blv[2]);
            mma_bf16(acc[1], al, &bhv[2]);
        }
    }

    // ---- X epilogue
    #pragma unroll
    for (int nf = 0; nf < 2; nf++) {
        const int col = wc * 16 + nf * 8 + 2 * t4;   // dk within head
        const int row = qBase + wm + g;
        float2 lo2 = {acc[nf][0], acc[nf][1]};
        float2 hi2 = {acc[nf][2], acc[nf][3]};
        *(float2*)&g_x[((size_t)b * Lsz + row    ) * Dsz + h * 64 + col] = lo2;
        *(float2*)&g_x[((size_t)b * Lsz + row + 8) * Dsz + h * 64 + col] = hi2;
    }
}

// ---------------------------------------------------------------------------
extern "C" void kernel_launch(void* const* d_in, const int* in_sizes, int n_in,
                              void* d_out, int out_size)
{
    (void)in_sizes; (void)n_in; (void)out_size;
    const float* query = (const float*)d_in[0];
    const float* keyt  = (const float*)d_in[1];
    const float* value = (const float*)d_in[2];
    const int*   mask  = (const int*)d_in[3];     // bool upcast to int32
    const float* aiw   = (const float*)d_in[4];
    const float* wQ    = (const float*)d_in[5];
    const float* wK    = (const float*)d_in[6];
    const float* wV    = (const float*)d_in[7];
    const float* wfc   = (const float*)d_in[8];

    float* outx = (float*)d_out;                       // x: [B,L,D]
    float* outp = outx + (size_t)Bsz * Lsz * Dsz;      // p_attn: [B,H,L,L]

    dim3 gp(64, 8), tp(256);
    proj_mma<0><<<gp, tp>>>(query, wQ, nullptr);
    proj_mma<1><<<gp, tp>>>(keyt,  wK, nullptr);
    proj_mma<2><<<gp, tp>>>(value, wV, nullptr);

    const int smem = 64 * SD * (int)sizeof(float)
                   + 4 * 64 * BS * (int)sizeof(__nv_bfloat16);   // 168,960 B
    cudaFuncSetAttribute((const void*)attn_mma,
                         cudaFuncAttributeMaxDynamicSharedMemorySize, smem);
    attn_mma<<<dim3(8, 128), 512, smem>>>(mask, aiw, outp);

    proj_mma<3><<<gp, tp>>>(nullptr, wfc, outx);
}

// round 10
// speedup vs baseline: 1.8535x; 1.1514x over previous
#include <cuda_runtime.h>
#include <cuda_bf16.h>
#include <cstdint>

#define Bsz 16
#define Lsz 512
#define Dsz 512
#define Hsz 8
#define DKsz 64
#define BHsz (Bsz*Hsz)

#define SD 516   // score row stride (floats)
#define BS 72    // bf16 buffer row stride (halves)

// Scratch (allocation-free contract: __device__ globals)
__device__ __nv_bfloat16 g_qh[BHsz*Lsz*DKsz], g_ql[BHsz*Lsz*DKsz];
__device__ __nv_bfloat16 g_kh[BHsz*Lsz*DKsz], g_kl[BHsz*Lsz*DKsz];
__device__ __nv_bfloat16 g_vth[BHsz*DKsz*Lsz], g_vtl[BHsz*DKsz*Lsz];
__device__ __nv_bfloat16 g_inh[Bsz*Lsz*Dsz], g_inl[Bsz*Lsz*Dsz];   // staged GEMM input (x for fc)
__device__ __nv_bfloat16 g_wh[4*Dsz*Dsz],  g_wl[4*Dsz*Dsz];        // weights, transposed [n][k]

// ---------------------------------------------------------------------------
__device__ __forceinline__ void mma_bf16(float* c, const uint32_t* a, const uint32_t* b)
{
    asm volatile(
        "mma.sync.aligned.m16n8k16.row.col.f32.bf16.bf16.f32 "
        "{%0,%1,%2,%3}, {%4,%5,%6,%7}, {%8,%9}, {%0,%1,%2,%3};\n"
        : "+f"(c[0]), "+f"(c[1]), "+f"(c[2]), "+f"(c[3])
        : "r"(a[0]), "r"(a[1]), "r"(a[2]), "r"(a[3]), "r"(b[0]), "r"(b[1]));
}

__device__ __forceinline__ void ldsm_x4(uint32_t* r, const void* p)
{
    uint32_t a = (uint32_t)__cvta_generic_to_shared(p);
    asm volatile("ldmatrix.sync.aligned.m8n8.x4.shared.b16 {%0,%1,%2,%3}, [%4];"
                 : "=r"(r[0]), "=r"(r[1]), "=r"(r[2]), "=r"(r[3]) : "r"(a));
}

__device__ __forceinline__ void split8(float4 v0, float4 v1,
                                       __nv_bfloat16* dh, __nv_bfloat16* dl)
{
    __align__(16) __nv_bfloat16 hh[8], ll[8];
    float vv[8] = {v0.x, v0.y, v0.z, v0.w, v1.x, v1.y, v1.z, v1.w};
    #pragma unroll
    for (int e = 0; e < 8; e++) {
        __nv_bfloat16 h = __float2bfloat16(vv[e]);
        hh[e] = h;
        ll[e] = __float2bfloat16(vv[e] - __bfloat162float(h));
    }
    *(uint4*)dh = *(const uint4*)hh;
    *(uint4*)dl = *(const uint4*)ll;
}

__device__ __forceinline__ void split2(float x, float y, uint32_t& hp, uint32_t& lp)
{
    __nv_bfloat16 hx = __float2bfloat16(x), hy = __float2bfloat16(y);
    __nv_bfloat16 lx = __float2bfloat16(x - __bfloat162float(hx));
    __nv_bfloat16 ly = __float2bfloat16(y - __bfloat162float(hy));
    __nv_bfloat162 hh = {hx, hy}, ll = {lx, ly};
    hp = *(uint32_t*)&hh;
    lp = *(uint32_t*)&ll;
}

// ---------------------------------------------------------------------------
// Conversion kernels (memory-bound, run once per tensor)
// ---------------------------------------------------------------------------
__global__ __launch_bounds__(256) void cvt_split(const float* __restrict__ src)
{
    const size_t i = ((size_t)blockIdx.x * 256 + threadIdx.x) * 8;
    float4 v0 = *(const float4*)&src[i];
    float4 v1 = *(const float4*)&src[i + 4];
    split8(v0, v1, &g_inh[i], &g_inl[i]);
}

// W [k][n] fp32 -> g_wh/g_wl [widx][n][k] bf16 hi/lo
__global__ __launch_bounds__(1024) void cvt_wt(const float* __restrict__ w, int widx)
{
    __shared__ float t[32][33];
    const int k0 = blockIdx.x * 32, n0 = blockIdx.y * 32;
    const int tx = threadIdx.x, ty = threadIdx.y;
    t[ty][tx] = w[(size_t)(k0 + ty) * 512 + n0 + tx];
    __syncthreads();
    float v = t[tx][ty];                       // element (k0+tx, n0+ty)
    __nv_bfloat16 h = __float2bfloat16(v);
    size_t o = (size_t)widx * 512 * 512 + (size_t)(n0 + ty) * 512 + (k0 + tx);
    g_wh[o] = h;
    g_wl[o] = __float2bfloat16(v - __bfloat162float(h));
}

// ---------------------------------------------------------------------------
// Pure-bf16 tensor-core GEMM: C[8192,512] = Xsplit @ Wsplit(MODE)
// BM=128,BN=64,BK=32, 8 warps (4m x 2n). No conversions in the loop:
// uint4 copies + ldmatrix + 3 split MMAs. Register double-buffered.
// MODE 0: ->g_qh/g_ql  1: ->g_kh/g_kl  2: ->g_vth/g_vtl (transposed)  3: ->outp fp32
// ---------------------------------------------------------------------------
template<int MODE>
__global__ __launch_bounds__(256) void proj_mma(float* __restrict__ outp)
{
    __shared__ __nv_bfloat16 Ah[128][40];
    __shared__ __nv_bfloat16 Al[128][40];
    __shared__ __nv_bfloat16 Bh[64][40];
    __shared__ __nv_bfloat16 Bl[64][40];

    const __nv_bfloat16* Wh = g_wh + (size_t)MODE * 512 * 512;
    const __nv_bfloat16* Wl = g_wl + (size_t)MODE * 512 * 512;

    const int tid  = threadIdx.x;
    const int wid  = tid >> 5;
    const int lane = tid & 31;
    const int wm = (wid >> 1) * 32;
    const int wn = (wid & 1) * 32;
    const int g  = lane >> 2;
    const int t4 = lane & 3;

    const int mBase = blockIdx.x * 128;
    const int nBase = blockIdx.y * 64;

    // loader indices: A two 8-half chunks/thread/buf, B one chunk/thread/buf
    const int ar0 = tid >> 1;
    const int ac0 = (tid & 1) * 16;            // chunks at ac0 and ac0+8
    const int br  = tid >> 2;
    const int bc  = (tid & 3) * 8;

    // ldmatrix per-lane offsets
    const int a_r0 = wm + (lane & 15);
    const int a_c  = (lane >> 4) << 3;
    const int b_r0 = wn + (lane & 7) + ((lane >> 4) << 3);
    const int b_c  = ((lane >> 3) & 1) * 8;

    float acc[2][4][4] = {};

    uint4 sAh[2], sAl[2], sBh, sBl;
    // prologue: stage tile 0
    {
        const size_t a0 = (size_t)(mBase + ar0) * 512 + ac0;
        sAh[0] = *(const uint4*)&g_inh[a0];
        sAh[1] = *(const uint4*)&g_inh[a0 + 8];
        sAl[0] = *(const uint4*)&g_inl[a0];
        sAl[1] = *(const uint4*)&g_inl[a0 + 8];
        const size_t b0 = (size_t)(nBase + br) * 512 + bc;
        sBh = *(const uint4*)&Wh[b0];
        sBl = *(const uint4*)&Wl[b0];
    }

    for (int k0 = 0; k0 < 512; k0 += 32) {
        *(uint4*)&Ah[ar0][ac0]     = sAh[0];
        *(uint4*)&Ah[ar0][ac0 + 8] = sAh[1];
        *(uint4*)&Al[ar0][ac0]     = sAl[0];
        *(uint4*)&Al[ar0][ac0 + 8] = sAl[1];
        *(uint4*)&Bh[br][bc] = sBh;
        *(uint4*)&Bl[br][bc] = sBl;
        __syncthreads();

        if (k0 + 32 < 512) {
            const size_t a0 = (size_t)(mBase + ar0) * 512 + k0 + 32 + ac0;
            sAh[0] = *(const uint4*)&g_inh[a0];
            sAh[1] = *(const uint4*)&g_inh[a0 + 8];
            sAl[0] = *(const uint4*)&g_inl[a0];
            sAl[1] = *(const uint4*)&g_inl[a0 + 8];
            const size_t b0 = (size_t)(nBase + br) * 512 + k0 + 32 + bc;
            sBh = *(const uint4*)&Wh[b0];
            sBl = *(const uint4*)&Wl[b0];
        }

        #pragma unroll
        for (int ks = 0; ks < 32; ks += 16) {
            uint32_t ah0[4], ah1[4], al0[4], al1[4];
            ldsm_x4(ah0, &Ah[a_r0     ][ks + a_c]);
            ldsm_x4(ah1, &Ah[a_r0 + 16][ks + a_c]);
            ldsm_x4(al0, &Al[a_r0     ][ks + a_c]);
            ldsm_x4(al1, &Al[a_r0 + 16][ks + a_c]);
            uint32_t bh01[4], bh23[4], bl01[4], bl23[4];
            ldsm_x4(bh01, &Bh[b_r0     ][ks + b_c]);
            ldsm_x4(bh23, &Bh[b_r0 + 16][ks + b_c]);
            ldsm_x4(bl01, &Bl[b_r0     ][ks + b_c]);
            ldsm_x4(bl23, &Bl[b_r0 + 16][ks + b_c]);

            const uint32_t* AH[2] = {ah0, ah1};
            const uint32_t* AL[2] = {al0, al1};
            const uint32_t* BH[4] = {&bh01[0], &bh01[2], &bh23[0], &bh23[2]};
            const uint32_t* BL[4] = {&bl01[0], &bl01[2], &bl23[0], &bl23[2]};
            #pragma unroll
            for (int mf = 0; mf < 2; mf++)
                #pragma unroll
                for (int nf = 0; nf < 4; nf++) {
                    mma_bf16(acc[mf][nf], AH[mf], BH[nf]);
                    mma_bf16(acc[mf][nf], AH[mf], BL[nf]);
                    mma_bf16(acc[mf][nf], AL[mf], BH[nf]);
                }
        }
        __syncthreads();
    }

    // ---- epilogue
    #pragma unroll
    for (int mf = 0; mf < 2; mf++) {
        #pragma unroll
        for (int nf = 0; nf < 4; nf++) {
            const int col = wn + nf * 8 + 2 * t4;
            const int r0  = mBase + wm + mf * 16 + g;
            const int r1  = r0 + 8;
            float v0 = acc[mf][nf][0], v1 = acc[mf][nf][1];
            float v2 = acc[mf][nf][2], v3 = acc[mf][nf][3];
            if (MODE == 3) {
                float2 lo2 = {v0, v1}, hi2 = {v2, v3};
                *(float2*)&outp[(size_t)r0 * 512 + nBase + col] = lo2;
                *(float2*)&outp[(size_t)r1 * 512 + nBase + col] = hi2;
            } else {
                const int hh = blockIdx.y;               // BN=64 == DK
                const int b0 = r0 >> 9, l0 = r0 & 511;
                const int b1 = r1 >> 9, l1 = r1 & 511;
                if (MODE == 2) {
                    __nv_bfloat16 h0 = __float2bfloat16(v0);
                    __nv_bfloat16 h1 = __float2bfloat16(v1);
                    __nv_bfloat16 h2 = __float2bfloat16(v2);
                    __nv_bfloat16 h3 = __float2bfloat16(v3);
                    size_t c0 = ((size_t)(b0 * Hsz + hh) * DKsz + col) * Lsz;
                    size_t c1 = ((size_t)(b0 * Hsz + hh) * DKsz + col + 1) * Lsz;
                    g_vth[c0 + l0] = h0;
                    g_vtl[c0 + l0] = __float2bfloat16(v0 - __bfloat162float(h0));
                    g_vth[c1 + l0] = h1;
                    g_vtl[c1 + l0] = __float2bfloat16(v1 - __bfloat162float(h1));
                    g_vth[c0 + l1] = h2;
                    g_vtl[c0 + l1] = __float2bfloat16(v2 - __bfloat162float(h2));
                    g_vth[c1 + l1] = h3;
                    g_vtl[c1 + l1] = __float2bfloat16(v3 - __bfloat162float(h3));
                } else {
                    __nv_bfloat16* dh = (MODE == 0) ? g_qh : g_kh;
                    __nv_bfloat16* dl = (MODE == 0) ? g_ql : g_kl;
                    uint32_t hp, lp;
                    split2(v0, v1, hp, lp);
                    size_t i0 = (((size_t)b0 * Hsz + hh) * Lsz + l0) * DKsz + col;
                    *(uint32_t*)&dh[i0] = hp;
                    *(uint32_t*)&dl[i0] = lp;
                    split2(v2, v3, hp, lp);
                    size_t i1 = (((size_t)b1 * Hsz + hh) * Lsz + l1) * DKsz + col;
                    *(uint32_t*)&dh[i1] = hp;
                    *(uint32_t*)&dl[i1] = lp;
                }
            }
        }
    }
}

// ---------------------------------------------------------------------------
// Tensor-core fused attention (unchanged from R8 except x epilogue now
// writes bf16 hi/lo into g_inh/g_inl for the fc GEMM).
// ---------------------------------------------------------------------------
__global__ __launch_bounds__(512) void attn_mma(const int* __restrict__ mask,
                                                const float* __restrict__ aiw,
                                                float* __restrict__ p_out)
{
    extern __shared__ float sm[];
    float* s = sm;                                        // [64][516]
    __nv_bfloat16* bufs = (__nv_bfloat16*)(sm + 64 * SD);
    __nv_bfloat16* B0 = bufs;               // Qh / Ph
    __nv_bfloat16* B1 = bufs + 64 * BS;     // Ql / Pl
    __nv_bfloat16* B2 = bufs + 2 * 64 * BS; // Kh / Vh
    __nv_bfloat16* B3 = bufs + 3 * 64 * BS; // Kl / Vl

    const int tid  = threadIdx.x;
    const int wid  = tid >> 5;
    const int lane = tid & 31;
    const int g  = lane >> 2;
    const int t4 = lane & 3;
    const int wm = (wid & 3) * 16;
    const int wc = wid >> 2;

    const int bh = blockIdx.y;
    const int b  = bh >> 3;
    const int h  = bh & 7;
    const int qBase = blockIdx.x * 64;

    const int cr = tid >> 3;
    const int cc = (tid & 7) * 8;

    const int a_r = wm + (lane & 15);
    const int a_c = (lane >> 4) << 3;
    const int b_r = wc * 16 + (lane & 7) + ((lane >> 4) << 3);
    const int b_c = ((lane >> 3) & 1) * 8;

    // ---- Q tile copy (pre-split)
    {
        const size_t qo = ((size_t)bh * Lsz + qBase + cr) * DKsz + cc;
        *(uint4*)&B0[cr * BS + cc] = *(const uint4*)&g_qh[qo];
        *(uint4*)&B1[cr * BS + cc] = *(const uint4*)&g_ql[qo];
    }

    // ---- Phase 1: S = Q K^T / 8
    uint4 kh = *(const uint4*)&g_kh[((size_t)bh * Lsz + cr) * DKsz + cc];
    uint4 kl = *(const uint4*)&g_kl[((size_t)bh * Lsz + cr) * DKsz + cc];

    for (int nt = 0; nt < 8; nt++) {
        __syncthreads();
        *(uint4*)&B2[cr * BS + cc] = kh;
        *(uint4*)&B3[cr * BS + cc] = kl;
        __syncthreads();
        if (nt < 7) {
            const size_t ko = ((size_t)bh * Lsz + (nt + 1) * 64 + cr) * DKsz + cc;
            kh = *(const uint4*)&g_kh[ko];
            kl = *(const uint4*)&g_kl[ko];
        }

        float acc[2][4] = {};
        #pragma unroll
        for (int ks = 0; ks < 64; ks += 16) {
            uint32_t ah[4], al[4], bhv[4], blv[4];
            ldsm_x4(ah,  &B0[a_r * BS + ks + a_c]);
            ldsm_x4(al,  &B1[a_r * BS + ks + a_c]);
            ldsm_x4(bhv, &B2[b_r * BS + ks + b_c]);
            ldsm_x4(blv, &B3[b_r * BS + ks + b_c]);
            mma_bf16(acc[0], ah, &bhv[0]);
            mma_bf16(acc[0], ah, &blv[0]);
            mma_bf16(acc[0], al, &bhv[0]);
            mma_bf16(acc[1], ah, &bhv[2]);
            mma_bf16(acc[1], ah, &blv[2]);
            mma_bf16(acc[1], al, &bhv[2]);
        }
        #pragma unroll
        for (int nf = 0; nf < 2; nf++) {
            const int col = nt * 64 + wc * 16 + nf * 8 + 2 * t4;
            const int row = wm + g;
            s[ row      * SD + col    ] = acc[nf][0] * 0.125f;
            s[ row      * SD + col + 1] = acc[nf][1] * 0.125f;
            s[(row + 8) * SD + col    ] = acc[nf][2] * 0.125f;
            s[(row + 8) * SD + col + 1] = acc[nf][3] * 0.125f;
        }
    }
    __syncthreads();

    // ---- Phase 2: mask + softmax + *aiw + p_attn write
    {
        #pragma unroll
        for (int r = 0; r < 4; r++) {
            const int m = wid * 4 + r;
            const int qRow = qBase + m;
            const int*   mrow = mask + ((size_t)b * Lsz + qRow) * Lsz;
            const float* arow = aiw  + ((size_t)b * Lsz + qRow) * Lsz;
            float* srow = s + m * SD;

            float mx = -1e30f;
            for (int k = lane; k < 512; k += 32) {
                float v = (mrow[k] != 0) ? -1e30f : srow[k];
                srow[k] = v;
                mx = fmaxf(mx, v);
            }
            #pragma unroll
            for (int o = 16; o; o >>= 1) mx = fmaxf(mx, __shfl_xor_sync(0xffffffffu, mx, o));

            float sum = 0.f;
            for (int k = lane; k < 512; k += 32) {
                float e = __expf(srow[k] - mx);
                srow[k] = e;
                sum += e;
            }
            #pragma unroll
            for (int o = 16; o; o >>= 1) sum += __shfl_xor_sync(0xffffffffu, sum, o);
            const float inv = 1.f / sum;

            float* prow = p_out + ((size_t)bh * Lsz + qRow) * Lsz;
            for (int k = lane; k < 512; k += 32) {
                float p = srow[k] * inv * arow[k];
                srow[k] = p;
                prow[k] = p;
            }
        }
    }
    __syncthreads();

    // ---- Phase 3: X = P V
    uint4 vh = *(const uint4*)&g_vth[((size_t)bh * DKsz + cr) * Lsz + cc];
    uint4 vl = *(const uint4*)&g_vtl[((size_t)bh * DKsz + cr) * Lsz + cc];

    float acc[2][4] = {};
    for (int kt = 0; kt < 8; kt++) {
        __syncthreads();
        *(uint4*)&B2[cr * BS + cc] = vh;
        *(uint4*)&B3[cr * BS + cc] = vl;
        {
            const float* ps = &s[cr * SD + kt * 64 + cc];
            split8(*(const float4*)ps, *(const float4*)(ps + 4),
                   &B0[cr * BS + cc], &B1[cr * BS + cc]);
        }
        __syncthreads();
        if (kt < 7) {
            const size_t vo = ((size_t)bh * DKsz + cr) * Lsz + (kt + 1) * 64 + cc;
            vh = *(const uint4*)&g_vth[vo];
            vl = *(const uint4*)&g_vtl[vo];
        }

        #pragma unroll
        for (int ks = 0; ks < 64; ks += 16) {
            uint32_t ah[4], al[4], bhv[4], blv[4];
            ldsm_x4(ah,  &B0[a_r * BS + ks + a_c]);
            ldsm_x4(al,  &B1[a_r * BS + ks + a_c]);
            ldsm_x4(bhv, &B2[b_r * BS + ks + b_c]);
            ldsm_x4(blv, &B3[b_r * BS + ks + b_c]);
            mma_bf16(acc[0], ah, &bhv[0]);
            mma_bf16(acc[0], ah, &blv[0]);
            mma_bf16(acc[0], al, &bhv[0]);
            mma_bf16(acc[1], ah, &bhv[2]);
            mma_bf16(acc[1], ah, &blv[2]);
            mma_bf16(acc[1], al, &bhv[2]);
        }
    }

    // ---- X epilogue: write bf16 hi/lo straight into the fc staging buffers
    #pragma unroll
    for (int nf = 0; nf < 2; nf++) {
        const int col = wc * 16 + nf * 8 + 2 * t4;
        const int row = qBase + wm + g;
        uint32_t hp, lp;
        split2(acc[nf][0], acc[nf][1], hp, lp);
        size_t i0 = ((size_t)b * Lsz + row) * Dsz + h * 64 + col;
        *(uint32_t*)&g_inh[i0] = hp;
        *(uint32_t*)&g_inl[i0] = lp;
        split2(acc[nf][2], acc[nf][3], hp, lp);
        size_t i1 = ((size_t)b * Lsz + row + 8) * Dsz + h * 64 + col;
        *(uint32_t*)&g_inh[i1] = hp;
        *(uint32_t*)&g_inl[i1] = lp;
    }
}

// ---------------------------------------------------------------------------
extern "C" void kernel_launch(void* const* d_in, const int* in_sizes, int n_in,
                              void* d_out, int out_size)
{
    (void)in_sizes; (void)n_in; (void)out_size;
    const float* query = (const float*)d_in[0];
    const float* keyt  = (const float*)d_in[1];
    const float* value = (const float*)d_in[2];
    const int*   mask  = (const int*)d_in[3];     // bool upcast to int32
    const float* aiw   = (const float*)d_in[4];
    const float* wQ    = (const float*)d_in[5];
    const float* wK    = (const float*)d_in[6];
    const float* wV    = (const float*)d_in[7];
    const float* wfc   = (const float*)d_in[8];

    float* outx = (float*)d_out;                       // x: [B,L,D]
    float* outp = outx + (size_t)Bsz * Lsz * Dsz;      // p_attn: [B,H,L,L]

    // weights: convert + transpose once
    dim3 wg(16, 16), wt(32, 32);
    cvt_wt<<<wg, wt>>>(wQ, 0);
    cvt_wt<<<wg, wt>>>(wK, 1);
    cvt_wt<<<wg, wt>>>(wV, 2);
    cvt_wt<<<wg, wt>>>(wfc, 3);

    dim3 gp(64, 8), tp(256);
    cvt_split<<<2048, 256>>>(query);
    proj_mma<0><<<gp, tp>>>(nullptr);
    cvt_split<<<2048, 256>>>(keyt);
    proj_mma<1><<<gp, tp>>>(nullptr);
    cvt_split<<<2048, 256>>>(value);
    proj_mma<2><<<gp, tp>>>(nullptr);

    const int smem = 64 * SD * (int)sizeof(float)
                   + 4 * 64 * BS * (int)sizeof(__nv_bfloat16);   // 168,960 B
    cudaFuncSetAttribute((const void*)attn_mma,
                         cudaFuncAttributeMaxDynamicSharedMemorySize, smem);
    attn_mma<<<dim3(8, 128), 512, smem>>>(mask, aiw, outp);

    proj_mma<3><<<gp, tp>>>(outx);
}

// round 11
// speedup vs baseline: 2.0794x; 1.1219x over previous
#include <cuda_runtime.h>
#include <cuda_bf16.h>
#include <cstdint>

#define Bsz 16
#define Lsz 512
#define Dsz 512
#define Hsz 8
#define DKsz 64
#define BHsz (Bsz*Hsz)

#define SD 516   // score row stride (floats)
#define BS 72    // bf16 buffer row stride (halves)

// Scratch (allocation-free contract: __device__ globals)
__device__ __nv_bfloat16 g_qh[BHsz*Lsz*DKsz], g_ql[BHsz*Lsz*DKsz];
__device__ __nv_bfloat16 g_kh[BHsz*Lsz*DKsz], g_kl[BHsz*Lsz*DKsz];
__device__ __nv_bfloat16 g_vth[BHsz*DKsz*Lsz], g_vtl[BHsz*DKsz*Lsz];
__device__ __nv_bfloat16 g_inh[Bsz*Lsz*Dsz], g_inl[Bsz*Lsz*Dsz];   // staged GEMM input (x for fc)
__device__ __nv_bfloat16 g_wh[4*Dsz*Dsz],  g_wl[4*Dsz*Dsz];        // weights, transposed [n][k]

// ---------------------------------------------------------------------------
__device__ __forceinline__ void mma_bf16(float* c, const uint32_t* a, const uint32_t* b)
{
    asm volatile(
        "mma.sync.aligned.m16n8k16.row.col.f32.bf16.bf16.f32 "
        "{%0,%1,%2,%3}, {%4,%5,%6,%7}, {%8,%9}, {%0,%1,%2,%3};\n"
        : "+f"(c[0]), "+f"(c[1]), "+f"(c[2]), "+f"(c[3])
        : "r"(a[0]), "r"(a[1]), "r"(a[2]), "r"(a[3]), "r"(b[0]), "r"(b[1]));
}

__device__ __forceinline__ void ldsm_x4(uint32_t* r, const void* p)
{
    uint32_t a = (uint32_t)__cvta_generic_to_shared(p);
    asm volatile("ldmatrix.sync.aligned.m8n8.x4.shared.b16 {%0,%1,%2,%3}, [%4];"
                 : "=r"(r[0]), "=r"(r[1]), "=r"(r[2]), "=r"(r[3]) : "r"(a));
}

__device__ __forceinline__ void split8(float4 v0, float4 v1,
                                       __nv_bfloat16* dh, __nv_bfloat16* dl)
{
    __align__(16) __nv_bfloat16 hh[8], ll[8];
    float vv[8] = {v0.x, v0.y, v0.z, v0.w, v1.x, v1.y, v1.z, v1.w};
    #pragma unroll
    for (int e = 0; e < 8; e++) {
        __nv_bfloat16 h = __float2bfloat16(vv[e]);
        hh[e] = h;
        ll[e] = __float2bfloat16(vv[e] - __bfloat162float(h));
    }
    *(uint4*)dh = *(const uint4*)hh;
    *(uint4*)dl = *(const uint4*)ll;
}

__device__ __forceinline__ void split2(float x, float y, uint32_t& hp, uint32_t& lp)
{
    __nv_bfloat16 hx = __float2bfloat16(x), hy = __float2bfloat16(y);
    __nv_bfloat16 lx = __float2bfloat16(x - __bfloat162float(hx));
    __nv_bfloat16 ly = __float2bfloat16(y - __bfloat162float(hy));
    __nv_bfloat162 hh = {hx, hy}, ll = {lx, ly};
    hp = *(uint32_t*)&hh;
    lp = *(uint32_t*)&ll;
}

// ---------------------------------------------------------------------------
// Conversion kernels (memory-bound, run once per tensor)
// ---------------------------------------------------------------------------
__global__ __launch_bounds__(256) void cvt_split(const float* __restrict__ src)
{
    const size_t i = ((size_t)blockIdx.x * 256 + threadIdx.x) * 8;
    float4 v0 = *(const float4*)&src[i];
    float4 v1 = *(const float4*)&src[i + 4];
    split8(v0, v1, &g_inh[i], &g_inl[i]);
}

// W [k][n] fp32 -> g_wh/g_wl [widx][n][k] bf16 hi/lo
__global__ __launch_bounds__(1024) void cvt_wt(const float* __restrict__ w, int widx)
{
    __shared__ float t[32][33];
    const int k0 = blockIdx.x * 32, n0 = blockIdx.y * 32;
    const int tx = threadIdx.x, ty = threadIdx.y;
    t[ty][tx] = w[(size_t)(k0 + ty) * 512 + n0 + tx];
    __syncthreads();
    float v = t[tx][ty];                       // element (k0+tx, n0+ty)
    __nv_bfloat16 h = __float2bfloat16(v);
    size_t o = (size_t)widx * 512 * 512 + (size_t)(n0 + ty) * 512 + (k0 + tx);
    g_wh[o] = h;
    g_wl[o] = __float2bfloat16(v - __bfloat162float(h));
}

// ---------------------------------------------------------------------------
// Pure-bf16 tensor-core GEMM: C[8192,512] = Xsplit @ Wsplit(MODE)
// BM=128,BN=64,BK=32, 8 warps (4m x 2n). Smem DOUBLE-BUFFERED: one sync
// per k0 iteration; staged-register stores overlap MMA compute.
// MODE 0: ->g_qh/g_ql  1: ->g_kh/g_kl  2: ->g_vth/g_vtl (transposed)  3: ->outp fp32
// ---------------------------------------------------------------------------
template<int MODE>
__global__ __launch_bounds__(256) void proj_mma(float* __restrict__ outp)
{
    __shared__ __nv_bfloat16 Ah[2][128][40];
    __shared__ __nv_bfloat16 Al[2][128][40];
    __shared__ __nv_bfloat16 Bh[2][64][40];
    __shared__ __nv_bfloat16 Bl[2][64][40];

    const __nv_bfloat16* Wh = g_wh + (size_t)MODE * 512 * 512;
    const __nv_bfloat16* Wl = g_wl + (size_t)MODE * 512 * 512;

    const int tid  = threadIdx.x;
    const int wid  = tid >> 5;
    const int lane = tid & 31;
    const int wm = (wid >> 1) * 32;
    const int wn = (wid & 1) * 32;
    const int g  = lane >> 2;
    const int t4 = lane & 3;

    const int mBase = blockIdx.x * 128;
    const int nBase = blockIdx.y * 64;

    const int ar0 = tid >> 1;
    const int ac0 = (tid & 1) * 16;
    const int br  = tid >> 2;
    const int bc  = (tid & 3) * 8;

    const int a_r0 = wm + (lane & 15);
    const int a_c  = (lane >> 4) << 3;
    const int b_r0 = wn + (lane & 7) + ((lane >> 4) << 3);
    const int b_c  = ((lane >> 3) & 1) * 8;

    float acc[2][4][4] = {};

    uint4 sAh[2], sAl[2], sBh, sBl;
    auto stage = [&](int k0) {
        const size_t a0 = (size_t)(mBase + ar0) * 512 + k0 + ac0;
        sAh[0] = *(const uint4*)&g_inh[a0];
        sAh[1] = *(const uint4*)&g_inh[a0 + 8];
        sAl[0] = *(const uint4*)&g_inl[a0];
        sAl[1] = *(const uint4*)&g_inl[a0 + 8];
        const size_t b0 = (size_t)(nBase + br) * 512 + k0 + bc;
        sBh = *(const uint4*)&Wh[b0];
        sBl = *(const uint4*)&Wl[b0];
    };
    auto commit = [&](int buf) {
        *(uint4*)&Ah[buf][ar0][ac0]     = sAh[0];
        *(uint4*)&Ah[buf][ar0][ac0 + 8] = sAh[1];
        *(uint4*)&Al[buf][ar0][ac0]     = sAl[0];
        *(uint4*)&Al[buf][ar0][ac0 + 8] = sAl[1];
        *(uint4*)&Bh[buf][br][bc] = sBh;
        *(uint4*)&Bl[buf][br][bc] = sBl;
    };

    // prologue: tile0 -> buf0; stage tile1
    stage(0);
    commit(0);
    stage(32);
    __syncthreads();

    int buf = 0;
    for (int k0 = 0; k0 < 512; k0 += 32, buf ^= 1) {
        // store staged tile (k0+32) into the other buffer, prefetch k0+64
        if (k0 + 32 < 512) {
            commit(buf ^ 1);
            if (k0 + 64 < 512) stage(k0 + 64);
        }

        #pragma unroll
        for (int ks = 0; ks < 32; ks += 16) {
            uint32_t ah0[4], ah1[4], al0[4], al1[4];
            ldsm_x4(ah0, &Ah[buf][a_r0     ][ks + a_c]);
            ldsm_x4(ah1, &Ah[buf][a_r0 + 16][ks + a_c]);
            ldsm_x4(al0, &Al[buf][a_r0     ][ks + a_c]);
            ldsm_x4(al1, &Al[buf][a_r0 + 16][ks + a_c]);
            uint32_t bh01[4], bh23[4], bl01[4], bl23[4];
            ldsm_x4(bh01, &Bh[buf][b_r0     ][ks + b_c]);
            ldsm_x4(bh23, &Bh[buf][b_r0 + 16][ks + b_c]);
            ldsm_x4(bl01, &Bl[buf][b_r0     ][ks + b_c]);
            ldsm_x4(bl23, &Bl[buf][b_r0 + 16][ks + b_c]);

            const uint32_t* AH[2] = {ah0, ah1};
            const uint32_t* AL[2] = {al0, al1};
            const uint32_t* BH[4] = {&bh01[0], &bh01[2], &bh23[0], &bh23[2]};
            const uint32_t* BL[4] = {&bl01[0], &bl01[2], &bl23[0], &bl23[2]};
            #pragma unroll
            for (int mf = 0; mf < 2; mf++)
                #pragma unroll
                for (int nf = 0; nf < 4; nf++) {
                    mma_bf16(acc[mf][nf], AH[mf], BH[nf]);
                    mma_bf16(acc[mf][nf], AH[mf], BL[nf]);
                    mma_bf16(acc[mf][nf], AL[mf], BH[nf]);
                }
        }
        __syncthreads();
    }

    // ---- epilogue
    #pragma unroll
    for (int mf = 0; mf < 2; mf++) {
        #pragma unroll
        for (int nf = 0; nf < 4; nf++) {
            const int col = wn + nf * 8 + 2 * t4;
            const int r0  = mBase + wm + mf * 16 + g;
            const int r1  = r0 + 8;
            float v0 = acc[mf][nf][0], v1 = acc[mf][nf][1];
            float v2 = acc[mf][nf][2], v3 = acc[mf][nf][3];
            if (MODE == 3) {
                float2 lo2 = {v0, v1}, hi2 = {v2, v3};
                *(float2*)&outp[(size_t)r0 * 512 + nBase + col] = lo2;
                *(float2*)&outp[(size_t)r1 * 512 + nBase + col] = hi2;
            } else {
                const int hh = blockIdx.y;               // BN=64 == DK
                const int b0 = r0 >> 9, l0 = r0 & 511;
                const int b1 = r1 >> 9, l1 = r1 & 511;
                if (MODE == 2) {
                    __nv_bfloat16 h0 = __float2bfloat16(v0);
                    __nv_bfloat16 h1 = __float2bfloat16(v1);
                    __nv_bfloat16 h2 = __float2bfloat16(v2);
                    __nv_bfloat16 h3 = __float2bfloat16(v3);
                    size_t c0 = ((size_t)(b0 * Hsz + hh) * DKsz + col) * Lsz;
                    size_t c1 = ((size_t)(b0 * Hsz + hh) * DKsz + col + 1) * Lsz;
                    g_vth[c0 + l0] = h0;
                    g_vtl[c0 + l0] = __float2bfloat16(v0 - __bfloat162float(h0));
                    g_vth[c1 + l0] = h1;
                    g_vtl[c1 + l0] = __float2bfloat16(v1 - __bfloat162float(h1));
                    g_vth[c0 + l1] = h2;
                    g_vtl[c0 + l1] = __float2bfloat16(v2 - __bfloat162float(h2));
                    g_vth[c1 + l1] = h3;
                    g_vtl[c1 + l1] = __float2bfloat16(v3 - __bfloat162float(h3));
                } else {
                    __nv_bfloat16* dh = (MODE == 0) ? g_qh : g_kh;
                    __nv_bfloat16* dl = (MODE == 0) ? g_ql : g_kl;
                    uint32_t hp, lp;
                    split2(v0, v1, hp, lp);
                    size_t i0 = (((size_t)b0 * Hsz + hh) * Lsz + l0) * DKsz + col;
                    *(uint32_t*)&dh[i0] = hp;
                    *(uint32_t*)&dl[i0] = lp;
                    split2(v2, v3, hp, lp);
                    size_t i1 = (((size_t)b1 * Hsz + hh) * Lsz + l1) * DKsz + col;
                    *(uint32_t*)&dh[i1] = hp;
                    *(uint32_t*)&dl[i1] = lp;
                }
            }
        }
    }
}

// ---------------------------------------------------------------------------
// Tensor-core fused attention. 512 threads = 16 warps (4m x 4n).
// smem: s[64][516] fp32 + 8 bf16 bufs [64][72] = 205,824 B.
// K (phase 1) and P/V (phase 3) smem ping-pong -> one sync per chunk.
// Softmax fully vectorized (float4/int4), scores register-resident.
// ---------------------------------------------------------------------------
__global__ __launch_bounds__(512) void attn_mma(const int* __restrict__ mask,
                                                const float* __restrict__ aiw,
                                                float* __restrict__ p_out)
{
    extern __shared__ float sm[];
    float* s = sm;                                        // [64][516]
    __nv_bfloat16* base = (__nv_bfloat16*)(sm + 64 * SD);
    // 8 buffers of [64][BS]:
    // 0/1: Qh/Ql (phase1), Ph/Pl ping0 (phase3)
    // 2/3: Kh/Kl ping0, Vh/Vl ping0
    // 4/5: Ph/Pl ping1
    // 6/7: Kh/Kl ping1, Vh/Vl ping1
    __nv_bfloat16* Bf[8];
    #pragma unroll
    for (int i = 0; i < 8; i++) Bf[i] = base + (size_t)i * 64 * BS;

    const int tid  = threadIdx.x;
    const int wid  = tid >> 5;
    const int lane = tid & 31;
    const int g  = lane >> 2;
    const int t4 = lane & 3;
    const int wm = (wid & 3) * 16;
    const int wc = wid >> 2;

    const int bh = blockIdx.y;
    const int b  = bh >> 3;
    const int h  = bh & 7;
    const int qBase = blockIdx.x * 64;

    const int cr = tid >> 3;
    const int cc = (tid & 7) * 8;

    const int a_r = wm + (lane & 15);
    const int a_c = (lane >> 4) << 3;
    const int b_r = wc * 16 + (lane & 7) + ((lane >> 4) << 3);
    const int b_c = ((lane >> 3) & 1) * 8;

    // ---- Phase 1: S = Q K^T / 8  (K ping-pong, one sync per chunk)
    {
        const size_t qo = ((size_t)bh * Lsz + qBase + cr) * DKsz + cc;
        *(uint4*)&Bf[0][cr * BS + cc] = *(const uint4*)&g_qh[qo];
        *(uint4*)&Bf[1][cr * BS + cc] = *(const uint4*)&g_ql[qo];
    }
    uint4 kh = *(const uint4*)&g_kh[((size_t)bh * Lsz + cr) * DKsz + cc];
    uint4 kl = *(const uint4*)&g_kl[((size_t)bh * Lsz + cr) * DKsz + cc];
    *(uint4*)&Bf[2][cr * BS + cc] = kh;
    *(uint4*)&Bf[3][cr * BS + cc] = kl;
    if (1 < 8) {
        const size_t ko = ((size_t)bh * Lsz + 64 + cr) * DKsz + cc;
        kh = *(const uint4*)&g_kh[ko];
        kl = *(const uint4*)&g_kl[ko];
    }
    __syncthreads();

    for (int nt = 0; nt < 8; nt++) {
        const int cb = (nt & 1) ? 6 : 2;          // current K buf pair
        if (nt < 7) {
            const int nb = (nt & 1) ? 2 : 6;      // next K buf pair
            *(uint4*)&Bf[nb    ][cr * BS + cc] = kh;
            *(uint4*)&Bf[nb + 1][cr * BS + cc] = kl;
            if (nt < 6) {
                const size_t ko = ((size_t)bh * Lsz + (nt + 2) * 64 + cr) * DKsz + cc;
                kh = *(const uint4*)&g_kh[ko];
                kl = *(const uint4*)&g_kl[ko];
            }
        }

        float acc[2][4] = {};
        #pragma unroll
        for (int ks = 0; ks < 64; ks += 16) {
            uint32_t ah[4], al[4], bhv[4], blv[4];
            ldsm_x4(ah,  &Bf[0][a_r * BS + ks + a_c]);
            ldsm_x4(al,  &Bf[1][a_r * BS + ks + a_c]);
            ldsm_x4(bhv, &Bf[cb    ][b_r * BS + ks + b_c]);
            ldsm_x4(blv, &Bf[cb + 1][b_r * BS + ks + b_c]);
            mma_bf16(acc[0], ah, &bhv[0]);
            mma_bf16(acc[0], ah, &blv[0]);
            mma_bf16(acc[0], al, &bhv[0]);
            mma_bf16(acc[1], ah, &bhv[2]);
            mma_bf16(acc[1], ah, &blv[2]);
            mma_bf16(acc[1], al, &bhv[2]);
        }
        #pragma unroll
        for (int nf = 0; nf < 2; nf++) {
            const int col = nt * 64 + wc * 16 + nf * 8 + 2 * t4;
            const int row = wm + g;
            s[ row      * SD + col    ] = acc[nf][0] * 0.125f;
            s[ row      * SD + col + 1] = acc[nf][1] * 0.125f;
            s[(row + 8) * SD + col    ] = acc[nf][2] * 0.125f;
            s[(row + 8) * SD + col + 1] = acc[nf][3] * 0.125f;
        }
        __syncthreads();
    }

    // ---- Phase 2: vectorized mask + softmax + *aiw + p_attn (regs-resident)
    {
        #pragma unroll
        for (int r = 0; r < 4; r++) {
            const int m = wid * 4 + r;
            const int qRow = qBase + m;
            const int4*   m4 = (const int4*)  (mask + ((size_t)b * Lsz + qRow) * Lsz);
            const float4* a4 = (const float4*)(aiw  + ((size_t)b * Lsz + qRow) * Lsz);
            float4* s4 = (float4*)(s + m * SD);
            float4* p4 = (float4*)(p_out + ((size_t)bh * Lsz + qRow) * Lsz);

            float4 sv[4];
            float mx = -1e30f;
            #pragma unroll
            for (int j = 0; j < 4; j++) {
                const int gidx = j * 32 + lane;
                float4 v = s4[gidx];
                int4  mm = m4[gidx];
                v.x = mm.x ? -1e30f : v.x;
                v.y = mm.y ? -1e30f : v.y;
                v.z = mm.z ? -1e30f : v.z;
                v.w = mm.w ? -1e30f : v.w;
                sv[j] = v;
                mx = fmaxf(mx, fmaxf(fmaxf(v.x, v.y), fmaxf(v.z, v.w)));
            }
            #pragma unroll
            for (int o = 16; o; o >>= 1) mx = fmaxf(mx, __shfl_xor_sync(0xffffffffu, mx, o));

            float sum = 0.f;
            #pragma unroll
            for (int j = 0; j < 4; j++) {
                sv[j].x = __expf(sv[j].x - mx);
                sv[j].y = __expf(sv[j].y - mx);
                sv[j].z = __expf(sv[j].z - mx);
                sv[j].w = __expf(sv[j].w - mx);
                sum += (sv[j].x + sv[j].y) + (sv[j].z + sv[j].w);
            }
            #pragma unroll
            for (int o = 16; o; o >>= 1) sum += __shfl_xor_sync(0xffffffffu, sum, o);
            const float inv = 1.f / sum;

            #pragma unroll
            for (int j = 0; j < 4; j++) {
                const int gidx = j * 32 + lane;
                float4 a = a4[gidx];
                float4 p;
                p.x = sv[j].x * inv * a.x;
                p.y = sv[j].y * inv * a.y;
                p.z = sv[j].z * inv * a.z;
                p.w = sv[j].w * inv * a.w;
                p4[gidx] = p;
                s4[gidx] = p;
            }
        }
    }
    __syncthreads();

    // ---- Phase 3: X = P V  (P and V ping-pong, one sync per chunk)
    uint4 vh = *(const uint4*)&g_vth[((size_t)bh * DKsz + cr) * Lsz + cc];
    uint4 vl = *(const uint4*)&g_vtl[((size_t)bh * DKsz + cr) * Lsz + cc];
    *(uint4*)&Bf[2][cr * BS + cc] = vh;
    *(uint4*)&Bf[3][cr * BS + cc] = vl;
    {
        const float* ps = &s[cr * SD + cc];
        split8(*(const float4*)ps, *(const float4*)(ps + 4),
               &Bf[0][cr * BS + cc], &Bf[1][cr * BS + cc]);
    }
    {
        const size_t vo = ((size_t)bh * DKsz + cr) * Lsz + 64 + cc;
        vh = *(const uint4*)&g_vth[vo];
        vl = *(const uint4*)&g_vtl[vo];
    }
    __syncthreads();

    float acc[2][4] = {};
    for (int kt = 0; kt < 8; kt++) {
        const int pb = (kt & 1) ? 4 : 0;          // current P buf pair
        const int vb = (kt & 1) ? 6 : 2;          // current V buf pair
        if (kt < 7) {
            const int npb = (kt & 1) ? 0 : 4;
            const int nvb = (kt & 1) ? 2 : 6;
            *(uint4*)&Bf[nvb    ][cr * BS + cc] = vh;
            *(uint4*)&Bf[nvb + 1][cr * BS + cc] = vl;
            const float* ps = &s[cr * SD + (kt + 1) * 64 + cc];
            split8(*(const float4*)ps, *(const float4*)(ps + 4),
                   &Bf[npb][cr * BS + cc], &Bf[npb + 1][cr * BS + cc]);
            if (kt < 6) {
                const size_t vo = ((size_t)bh * DKsz + cr) * Lsz + (kt + 2) * 64 + cc;
                vh = *(const uint4*)&g_vth[vo];
                vl = *(const uint4*)&g_vtl[vo];
            }
        }

        #pragma unroll
        for (int ks = 0; ks < 64; ks += 16) {
            uint32_t ah[4], al[4], bhv[4], blv[4];
            ldsm_x4(ah,  &Bf[pb    ][a_r * BS + ks + a_c]);
            ldsm_x4(al,  &Bf[pb + 1][a_r * BS + ks + a_c]);
            ldsm_x4(bhv, &Bf[vb    ][b_r * BS + ks + b_c]);
            ldsm_x4(blv, &Bf[vb + 1][b_r * BS + ks + b_c]);
            mma_bf16(acc[0], ah, &bhv[0]);
            mma_bf16(acc[0], ah, &blv[0]);
            mma_bf16(acc[0], al, &bhv[0]);
            mma_bf16(acc[1], ah, &bhv[2]);
            mma_bf16(acc[1], ah, &blv[2]);
            mma_bf16(acc[1], al, &bhv[2]);
        }
        __syncthreads();
    }

    // ---- X epilogue: write bf16 hi/lo straight into the fc staging buffers
    #pragma unroll
    for (int nf = 0; nf < 2; nf++) {
        const int col = wc * 16 + nf * 8 + 2 * t4;
        const int row = qBase + wm + g;
        uint32_t hp, lp;
        split2(acc[nf][0], acc[nf][1], hp, lp);
        size_t i0 = ((size_t)b * Lsz + row) * Dsz + h * 64 + col;
        *(uint32_t*)&g_inh[i0] = hp;
        *(uint32_t*)&g_inl[i0] = lp;
        split2(acc[nf][2], acc[nf][3], hp, lp);
        size_t i1 = ((size_t)b * Lsz + row + 8) * Dsz + h * 64 + col;
        *(uint32_t*)&g_inh[i1] = hp;
        *(uint32_t*)&g_inl[i1] = lp;
    }
}

// ---------------------------------------------------------------------------
extern "C" void kernel_launch(void* const* d_in, const int* in_sizes, int n_in,
                              void* d_out, int out_size)
{
    (void)in_sizes; (void)n_in; (void)out_size;
    const float* query = (const float*)d_in[0];
    const float* keyt  = (const float*)d_in[1];
    const float* value = (const float*)d_in[2];
    const int*   mask  = (const int*)d_in[3];     // bool upcast to int32
    const float* aiw   = (const float*)d_in[4];
    const float* wQ    = (const float*)d_in[5];
    const float* wK    = (const float*)d_in[6];
    const float* wV    = (const float*)d_in[7];
    const float* wfc   = (const float*)d_in[8];

    float* outx = (float*)d_out;                       // x: [B,L,D]
    float* outp = outx + (size_t)Bsz * Lsz * Dsz;      // p_attn: [B,H,L,L]

    // weights: convert + transpose once
    dim3 wg(16, 16), wt(32, 32);
    cvt_wt<<<wg, wt>>>(wQ, 0);
    cvt_wt<<<wg, wt>>>(wK, 1);
    cvt_wt<<<wg, wt>>>(wV, 2);
    cvt_wt<<<wg, wt>>>(wfc, 3);

    dim3 gp(64, 8), tp(256);
    cvt_split<<<2048, 256>>>(query);
    proj_mma<0><<<gp, tp>>>(nullptr);
    cvt_split<<<2048, 256>>>(keyt);
    proj_mma<1><<<gp, tp>>>(nullptr);
    cvt_split<<<2048, 256>>>(value);
    proj_mma<2><<<gp, tp>>>(nullptr);

    const int smem = 64 * SD * (int)sizeof(float)
                   + 8 * 64 * BS * (int)sizeof(__nv_bfloat16);   // 205,824 B
    cudaFuncSetAttribute((const void*)attn_mma,
                         cudaFuncAttributeMaxDynamicSharedMemorySize, smem);
    attn_mma<<<dim3(8, 128), 512, smem>>>(mask, aiw, outp);

    proj_mma<3><<<gp, tp>>>(outx);
}

// round 13
// speedup vs baseline: 2.5035x; 1.2040x over previous
#include <cuda_runtime.h>
#include <cuda_fp16.h>
#include <cstdint>

#define Bsz 16
#define Lsz 512
#define Dsz 512
#define Hsz 8
#define DKsz 64
#define BHsz (Bsz*Hsz)

#define SD 516   // score row stride (floats)
#define BS 72    // fp16 buffer row stride (halves)

// Scratch (allocation-free contract: __device__ globals)
// A-side operands keep hi/lo fp16 (full precision); B-side operands are
// plain fp16 (K, V, W) -> C = (ah+al)*bh, 2 MMAs per product.
__device__ __half g_qh[BHsz*Lsz*DKsz], g_ql[BHsz*Lsz*DKsz];
__device__ __half g_kh[BHsz*Lsz*DKsz];
__device__ __half g_vth[BHsz*DKsz*Lsz];
__device__ __half g_inh[Bsz*Lsz*Dsz], g_inl[Bsz*Lsz*Dsz];   // staged GEMM input (x for fc)
__device__ __half g_wh[4*Dsz*Dsz];                          // weights, transposed [n][k]

// ---------------------------------------------------------------------------
__device__ __forceinline__ void mma_f16(float* c, const uint32_t* a, const uint32_t* b)
{
    asm volatile(
        "mma.sync.aligned.m16n8k16.row.col.f32.f16.f16.f32 "
        "{%0,%1,%2,%3}, {%4,%5,%6,%7}, {%8,%9}, {%0,%1,%2,%3};\n"
        : "+f"(c[0]), "+f"(c[1]), "+f"(c[2]), "+f"(c[3])
        : "r"(a[0]), "r"(a[1]), "r"(a[2]), "r"(a[3]), "r"(b[0]), "r"(b[1]));
}

__device__ __forceinline__ void ldsm_x4(uint32_t* r, const void* p)
{
    uint32_t a = (uint32_t)__cvta_generic_to_shared(p);
    asm volatile("ldmatrix.sync.aligned.m8n8.x4.shared.b16 {%0,%1,%2,%3}, [%4];"
                 : "=r"(r[0]), "=r"(r[1]), "=r"(r[2]), "=r"(r[3]) : "r"(a));
}

// split 8 consecutive fp32 into fp16 hi/lo, vector-stored
__device__ __forceinline__ void split8h(float4 v0, float4 v1,
                                        __half* dh, __half* dl)
{
    __align__(16) __half hh[8], ll[8];
    float vv[8] = {v0.x, v0.y, v0.z, v0.w, v1.x, v1.y, v1.z, v1.w};
    #pragma unroll
    for (int e = 0; e < 8; e++) {
        __half h = __float2half_rn(vv[e]);
        hh[e] = h;
        ll[e] = __float2half_rn(vv[e] - __half2float(h));
    }
    *(uint4*)dh = *(const uint4*)hh;
    *(uint4*)dl = *(const uint4*)ll;
}

__device__ __forceinline__ void split2h(float x, float y, uint32_t& hp, uint32_t& lp)
{
    __half hx = __float2half_rn(x), hy = __float2half_rn(y);
    __half lx = __float2half_rn(x - __half2float(hx));
    __half ly = __float2half_rn(y - __half2float(hy));
    __half2 hh = {hx, hy}, ll = {lx, ly};
    hp = *(uint32_t*)&hh;
    lp = *(uint32_t*)&ll;
}

__device__ __forceinline__ uint32_t pack2h(float x, float y)
{
    __half2 h = __floats2half2_rn(x, y);
    return *(uint32_t*)&h;
}

// ---------------------------------------------------------------------------
// Conversion kernels (memory-bound, run once per tensor)
// ---------------------------------------------------------------------------
__global__ __launch_bounds__(256) void cvt_split(const float* __restrict__ src)
{
    const size_t i = ((size_t)blockIdx.x * 256 + threadIdx.x) * 8;
    float4 v0 = *(const float4*)&src[i];
    float4 v1 = *(const float4*)&src[i + 4];
    split8h(v0, v1, &g_inh[i], &g_inl[i]);
}

// W [k][n] fp32 -> g_wh [widx][n][k] fp16 (transposed)
__global__ __launch_bounds__(1024) void cvt_wt(const float* __restrict__ w, int widx)
{
    __shared__ float t[32][33];
    const int k0 = blockIdx.x * 32, n0 = blockIdx.y * 32;
    const int tx = threadIdx.x, ty = threadIdx.y;
    t[ty][tx] = w[(size_t)(k0 + ty) * 512 + n0 + tx];
    __syncthreads();
    float v = t[tx][ty];                       // element (k0+tx, n0+ty)
    g_wh[(size_t)widx * 512 * 512 + (size_t)(n0 + ty) * 512 + (k0 + tx)] = __float2half_rn(v);
}

// ---------------------------------------------------------------------------
// fp16 2-MMA-split tensor-core GEMM: C[8192,512] = (Ahi+Alo) @ Whi(MODE)
// BM=128,BN=64,BK=32, 8 warps (4m x 2n). Smem double-buffered, one sync
// per k0 iteration. B-side is plain fp16 (no lo).
// MODE 0: ->g_qh/g_ql  1: ->g_kh  2: ->g_vth (transposed)  3: ->outp fp32
// ---------------------------------------------------------------------------
template<int MODE>
__global__ __launch_bounds__(256) void proj_mma(float* __restrict__ outp)
{
    __shared__ __half Ah[2][128][40];
    __shared__ __half Al[2][128][40];
    __shared__ __half Bh[2][64][40];

    const __half* Wh = g_wh + (size_t)MODE * 512 * 512;

    const int tid  = threadIdx.x;
    const int wid  = tid >> 5;
    const int lane = tid & 31;
    const int wm = (wid >> 1) * 32;
    const int wn = (wid & 1) * 32;
    const int g  = lane >> 2;
    const int t4 = lane & 3;

    const int mBase = blockIdx.x * 128;
    const int nBase = blockIdx.y * 64;

    const int ar0 = tid >> 1;
    const int ac0 = (tid & 1) * 16;
    const int br  = tid >> 2;
    const int bc  = (tid & 3) * 8;

    const int a_r0 = wm + (lane & 15);
    const int a_c  = (lane >> 4) << 3;
    const int b_r0 = wn + (lane & 7) + ((lane >> 4) << 3);
    const int b_c  = ((lane >> 3) & 1) * 8;

    float acc[2][4][4] = {};

    uint4 sAh[2], sAl[2], sBh;
    auto stage = [&](int k0) {
        const size_t a0 = (size_t)(mBase + ar0) * 512 + k0 + ac0;
        sAh[0] = *(const uint4*)&g_inh[a0];
        sAh[1] = *(const uint4*)&g_inh[a0 + 8];
        sAl[0] = *(const uint4*)&g_inl[a0];
        sAl[1] = *(const uint4*)&g_inl[a0 + 8];
        sBh = *(const uint4*)&Wh[(size_t)(nBase + br) * 512 + k0 + bc];
    };
    auto commit = [&](int buf) {
        *(uint4*)&Ah[buf][ar0][ac0]     = sAh[0];
        *(uint4*)&Ah[buf][ar0][ac0 + 8] = sAh[1];
        *(uint4*)&Al[buf][ar0][ac0]     = sAl[0];
        *(uint4*)&Al[buf][ar0][ac0 + 8] = sAl[1];
        *(uint4*)&Bh[buf][br][bc] = sBh;
    };

    stage(0);
    commit(0);
    stage(32);
    __syncthreads();

    int buf = 0;
    for (int k0 = 0; k0 < 512; k0 += 32, buf ^= 1) {
        if (k0 + 32 < 512) {
            commit(buf ^ 1);
            if (k0 + 64 < 512) stage(k0 + 64);
        }

        #pragma unroll
        for (int ks = 0; ks < 32; ks += 16) {
            uint32_t ah0[4], ah1[4], al0[4], al1[4];
            ldsm_x4(ah0, &Ah[buf][a_r0     ][ks + a_c]);
            ldsm_x4(ah1, &Ah[buf][a_r0 + 16][ks + a_c]);
            ldsm_x4(al0, &Al[buf][a_r0     ][ks + a_c]);
            ldsm_x4(al1, &Al[buf][a_r0 + 16][ks + a_c]);
            uint32_t bh01[4], bh23[4];
            ldsm_x4(bh01, &Bh[buf][b_r0     ][ks + b_c]);
            ldsm_x4(bh23, &Bh[buf][b_r0 + 16][ks + b_c]);

            const uint32_t* AH[2] = {ah0, ah1};
            const uint32_t* AL[2] = {al0, al1};
            const uint32_t* BH[4] = {&bh01[0], &bh01[2], &bh23[0], &bh23[2]};
            #pragma unroll
            for (int mf = 0; mf < 2; mf++)
                #pragma unroll
                for (int nf = 0; nf < 4; nf++) {
                    mma_f16(acc[mf][nf], AH[mf], BH[nf]);
                    mma_f16(acc[mf][nf], AL[mf], BH[nf]);
                }
        }
        __syncthreads();
    }

    // ---- epilogue
    #pragma unroll
    for (int mf = 0; mf < 2; mf++) {
        #pragma unroll
        for (int nf = 0; nf < 4; nf++) {
            const int col = wn + nf * 8 + 2 * t4;
            const int r0  = mBase + wm + mf * 16 + g;
            const int r1  = r0 + 8;
            float v0 = acc[mf][nf][0], v1 = acc[mf][nf][1];
            float v2 = acc[mf][nf][2], v3 = acc[mf][nf][3];
            if (MODE == 3) {
                float2 lo2 = {v0, v1}, hi2 = {v2, v3};
                *(float2*)&outp[(size_t)r0 * 512 + nBase + col] = lo2;
                *(float2*)&outp[(size_t)r1 * 512 + nBase + col] = hi2;
            } else {
                const int hh = blockIdx.y;               // BN=64 == DK
                const int b0 = r0 >> 9, l0 = r0 & 511;
                const int b1 = r1 >> 9, l1 = r1 & 511;
                if (MODE == 2) {
                    // transposed V: [bh][dk][L], fp16 only
                    size_t c0 = ((size_t)(b0 * Hsz + hh) * DKsz + col) * Lsz;
                    size_t c1 = ((size_t)(b0 * Hsz + hh) * DKsz + col + 1) * Lsz;
                    g_vth[c0 + l0] = __float2half_rn(v0);
                    g_vth[c1 + l0] = __float2half_rn(v1);
                    g_vth[c0 + l1] = __float2half_rn(v2);
                    g_vth[c1 + l1] = __float2half_rn(v3);
                } else if (MODE == 1) {
                    // K: fp16 only
                    size_t i0 = (((size_t)b0 * Hsz + hh) * Lsz + l0) * DKsz + col;
                    size_t i1 = (((size_t)b1 * Hsz + hh) * Lsz + l1) * DKsz + col;
                    *(uint32_t*)&g_kh[i0] = pack2h(v0, v1);
                    *(uint32_t*)&g_kh[i1] = pack2h(v2, v3);
                } else {
                    // Q: hi/lo fp16
                    uint32_t hp, lp;
                    split2h(v0, v1, hp, lp);
                    size_t i0 = (((size_t)b0 * Hsz + hh) * Lsz + l0) * DKsz + col;
                    *(uint32_t*)&g_qh[i0] = hp;
                    *(uint32_t*)&g_ql[i0] = lp;
                    split2h(v2, v3, hp, lp);
                    size_t i1 = (((size_t)b1 * Hsz + hh) * Lsz + l1) * DKsz + col;
                    *(uint32_t*)&g_qh[i1] = hp;
                    *(uint32_t*)&g_ql[i1] = lp;
                }
            }
        }
    }
}

// ---------------------------------------------------------------------------
// Tensor-core fused attention. 512 threads = 16 warps (4m x 4n).
// smem: s[64][516] fp32 + 6 fp16 bufs [64][72] = 187,392 B.
// Buffers: 0/1 = Qh/Ql (ph1) & Ph/Pl ping0 (ph3); 2/3 = Ph/Pl ping1;
//          4/5 = K/V hi ping-pong. One sync per chunk; vectorized softmax.
// ---------------------------------------------------------------------------
__global__ __launch_bounds__(512) void attn_mma(const int* __restrict__ mask,
                                                const float* __restrict__ aiw,
                                                float* __restrict__ p_out)
{
    extern __shared__ float sm[];
    float* s = sm;                                        // [64][516]
    __half* base = (__half*)(sm + 64 * SD);
    __half* Bf[6];
    #pragma unroll
    for (int i = 0; i < 6; i++) Bf[i] = base + (size_t)i * 64 * BS;

    const int tid  = threadIdx.x;
    const int wid  = tid >> 5;
    const int lane = tid & 31;
    const int g  = lane >> 2;
    const int t4 = lane & 3;
    const int wm = (wid & 3) * 16;
    const int wc = wid >> 2;

    const int bh = blockIdx.y;
    const int b  = bh >> 3;
    const int h  = bh & 7;
    const int qBase = blockIdx.x * 64;

    const int cr = tid >> 3;
    const int cc = (tid & 7) * 8;

    const int a_r = wm + (lane & 15);
    const int a_c = (lane >> 4) << 3;
    const int b_r = wc * 16 + (lane & 7) + ((lane >> 4) << 3);
    const int b_c = ((lane >> 3) & 1) * 8;

    // ---- Phase 1: S = Q K^T / 8  (K hi-only ping-pong)
    {
        const size_t qo = ((size_t)bh * Lsz + qBase + cr) * DKsz + cc;
        *(uint4*)&Bf[0][cr * BS + cc] = *(const uint4*)&g_qh[qo];
        *(uint4*)&Bf[1][cr * BS + cc] = *(const uint4*)&g_ql[qo];
    }
    uint4 kh = *(const uint4*)&g_kh[((size_t)bh * Lsz + cr) * DKsz + cc];
    *(uint4*)&Bf[4][cr * BS + cc] = kh;
    kh = *(const uint4*)&g_kh[((size_t)bh * Lsz + 64 + cr) * DKsz + cc];
    __syncthreads();

    for (int nt = 0; nt < 8; nt++) {
        const int cb = 4 + (nt & 1);
        if (nt < 7) {
            const int nb = 4 + ((nt + 1) & 1);
            *(uint4*)&Bf[nb][cr * BS + cc] = kh;
            if (nt < 6)
                kh = *(const uint4*)&g_kh[((size_t)bh * Lsz + (nt + 2) * 64 + cr) * DKsz + cc];
        }

        float acc[2][4] = {};
        #pragma unroll
        for (int ks = 0; ks < 64; ks += 16) {
            uint32_t ah[4], al[4], bhv[4];
            ldsm_x4(ah,  &Bf[0][a_r * BS + ks + a_c]);
            ldsm_x4(al,  &Bf[1][a_r * BS + ks + a_c]);
            ldsm_x4(bhv, &Bf[cb][b_r * BS + ks + b_c]);
            mma_f16(acc[0], ah, &bhv[0]);
            mma_f16(acc[0], al, &bhv[0]);
            mma_f16(acc[1], ah, &bhv[2]);
            mma_f16(acc[1], al, &bhv[2]);
        }
        #pragma unroll
        for (int nf = 0; nf < 2; nf++) {
            const int col = nt * 64 + wc * 16 + nf * 8 + 2 * t4;
            const int row = wm + g;
            s[ row      * SD + col    ] = acc[nf][0] * 0.125f;
            s[ row      * SD + col + 1] = acc[nf][1] * 0.125f;
            s[(row + 8) * SD + col    ] = acc[nf][2] * 0.125f;
            s[(row + 8) * SD + col + 1] = acc[nf][3] * 0.125f;
        }
        __syncthreads();
    }

    // ---- Phase 2: vectorized mask + softmax + *aiw + p_attn (regs-resident)
    {
        #pragma unroll
        for (int r = 0; r < 4; r++) {
            const int m = wid * 4 + r;
            const int qRow = qBase + m;
            const int4*   m4 = (const int4*)  (mask + ((size_t)b * Lsz + qRow) * Lsz);
            const float4* a4 = (const float4*)(aiw  + ((size_t)b * Lsz + qRow) * Lsz);
            float4* s4 = (float4*)(s + m * SD);
            float4* p4 = (float4*)(p_out + ((size_t)bh * Lsz + qRow) * Lsz);

            float4 sv[4];
            float mx = -1e30f;
            #pragma unroll
            for (int j = 0; j < 4; j++) {
                const int gidx = j * 32 + lane;
                float4 v = s4[gidx];
                int4  mm = m4[gidx];
                v.x = mm.x ? -1e30f : v.x;
                v.y = mm.y ? -1e30f : v.y;
                v.z = mm.z ? -1e30f : v.z;
                v.w = mm.w ? -1e30f : v.w;
                sv[j] = v;
                mx = fmaxf(mx, fmaxf(fmaxf(v.x, v.y), fmaxf(v.z, v.w)));
            }
            #pragma unroll
            for (int o = 16; o; o >>= 1) mx = fmaxf(mx, __shfl_xor_sync(0xffffffffu, mx, o));

            float sum = 0.f;
            #pragma unroll
            for (int j = 0; j < 4; j++) {
                sv[j].x = __expf(sv[j].x - mx);
                sv[j].y = __expf(sv[j].y - mx);
                sv[j].z = __expf(sv[j].z - mx);
                sv[j].w = __expf(sv[j].w - mx);
                sum += (sv[j].x + sv[j].y) + (sv[j].z + sv[j].w);
            }
            #pragma unroll
            for (int o = 16; o; o >>= 1) sum += __shfl_xor_sync(0xffffffffu, sum, o);
            const float inv = 1.f / sum;

            #pragma unroll
            for (int j = 0; j < 4; j++) {
                const int gidx = j * 32 + lane;
                float4 a = a4[gidx];
                float4 p;
                p.x = sv[j].x * inv * a.x;
                p.y = sv[j].y * inv * a.y;
                p.z = sv[j].z * inv * a.z;
                p.w = sv[j].w * inv * a.w;
                p4[gidx] = p;
                s4[gidx] = p;
            }
        }
    }
    __syncthreads();

    // ---- Phase 3: X = P V  (P hi/lo ping-pong, V hi-only ping-pong)
    uint4 vh = *(const uint4*)&g_vth[((size_t)bh * DKsz + cr) * Lsz + cc];
    *(uint4*)&Bf[4][cr * BS + cc] = vh;
    {
        const float* ps = &s[cr * SD + cc];
        split8h(*(const float4*)ps, *(const float4*)(ps + 4),
                &Bf[0][cr * BS + cc], &Bf[1][cr * BS + cc]);
    }
    vh = *(const uint4*)&g_vth[((size_t)bh * DKsz + cr) * Lsz + 64 + cc];
    __syncthreads();

    float acc[2][4] = {};
    for (int kt = 0; kt < 8; kt++) {
        const int pb = (kt & 1) ? 2 : 0;
        const int vb = 4 + (kt & 1);
        if (kt < 7) {
            const int npb = (kt & 1) ? 0 : 2;
            const int nvb = 4 + ((kt + 1) & 1);
            *(uint4*)&Bf[nvb][cr * BS + cc] = vh;
            const float* ps = &s[cr * SD + (kt + 1) * 64 + cc];
            split8h(*(const float4*)ps, *(const float4*)(ps + 4),
                    &Bf[npb][cr * BS + cc], &Bf[npb + 1][cr * BS + cc]);
            if (kt < 6)
                vh = *(const uint4*)&g_vth[((size_t)bh * DKsz + cr) * Lsz + (kt + 2) * 64 + cc];
        }

        #pragma unroll
        for (int ks = 0; ks < 64; ks += 16) {
            uint32_t ah[4], al[4], bhv[4];
            ldsm_x4(ah,  &Bf[pb    ][a_r * BS + ks + a_c]);
            ldsm_x4(al,  &Bf[pb + 1][a_r * BS + ks + a_c]);
            ldsm_x4(bhv, &Bf[vb][b_r * BS + ks + b_c]);
            mma_f16(acc[0], ah, &bhv[0]);
            mma_f16(acc[0], al, &bhv[0]);
            mma_f16(acc[1], ah, &bhv[2]);
            mma_f16(acc[1], al, &bhv[2]);
        }
        __syncthreads();
    }

    // ---- X epilogue: write fp16 hi/lo straight into the fc staging buffers
    #pragma unroll
    for (int nf = 0; nf < 2; nf++) {
        const int col = wc * 16 + nf * 8 + 2 * t4;
        const int row = qBase + wm + g;
        uint32_t hp, lp;
        split2h(acc[nf][0], acc[nf][1], hp, lp);
        size_t i0 = ((size_t)b * Lsz + row) * Dsz + h * 64 + col;
        *(uint32_t*)&g_inh[i0] = hp;
        *(uint32_t*)&g_inl[i0] = lp;
        split2h(acc[nf][2], acc[nf][3], hp, lp);
        size_t i1 = ((size_t)b * Lsz + row + 8) * Dsz + h * 64 + col;
        *(uint32_t*)&g_inh[i1] = hp;
        *(uint32_t*)&g_inl[i1] = lp;
    }
}

// ---------------------------------------------------------------------------
extern "C" void kernel_launch(void* const* d_in, const int* in_sizes, int n_in,
                              void* d_out, int out_size)
{
    (void)in_sizes; (void)n_in; (void)out_size;
    const float* query = (const float*)d_in[0];
    const float* keyt  = (const float*)d_in[1];
    const float* value = (const float*)d_in[2];
    const int*   mask  = (const int*)d_in[3];     // bool upcast to int32
    const float* aiw   = (const float*)d_in[4];
    const float* wQ    = (const float*)d_in[5];
    const float* wK    = (const float*)d_in[6];
    const float* wV    = (const float*)d_in[7];
    const float* wfc   = (const float*)d_in[8];

    float* outx = (float*)d_out;                       // x: [B,L,D]
    float* outp = outx + (size_t)Bsz * Lsz * Dsz;      // p_attn: [B,H,L,L]

    dim3 wg(16, 16), wt(32, 32);
    cvt_wt<<<wg, wt>>>(wQ, 0);
    cvt_wt<<<wg, wt>>>(wK, 1);
    cvt_wt<<<wg, wt>>>(wV, 2);
    cvt_wt<<<wg, wt>>>(wfc, 3);

    dim3 gp(64, 8), tp(256);
    cvt_split<<<2048, 256>>>(query);
    proj_mma<0><<<gp, tp>>>(nullptr);
    cvt_split<<<2048, 256>>>(keyt);
    proj_mma<1><<<gp, tp>>>(nullptr);
    cvt_split<<<2048, 256>>>(value);
    proj_mma<2><<<gp, tp>>>(nullptr);

    const int smem = 64 * SD * (int)sizeof(float)
                   + 6 * 64 * BS * (int)sizeof(__half);   // 187,392 B
    cudaFuncSetAttribute((const void*)attn_mma,
                         cudaFuncAttributeMaxDynamicSharedMemorySize, smem);
    attn_mma<<<dim3(8, 128), 512, smem>>>(mask, aiw, outp);

    proj_mma<3><<<gp, tp>>>(outx);
}

// round 14
// speedup vs baseline: 2.7800x; 1.1104x over previous
#include <cuda_runtime.h>
#include <cuda_fp16.h>
#include <cstdint>

#define Bsz 16
#define Lsz 512
#define Dsz 512
#define Hsz 8
#define DKsz 64
#define BHsz (Bsz*Hsz)

#define SD 516   // score row stride (floats)
#define BS 72    // fp16 buffer row stride (halves)

// Scratch (allocation-free contract: __device__ globals)
// A-side operands keep hi/lo fp16; B-side (K, V, W) plain fp16.
__device__ __half g_qh[BHsz*Lsz*DKsz], g_ql[BHsz*Lsz*DKsz];   // Q pre-scaled by 1/8
__device__ __half g_kh[BHsz*Lsz*DKsz];
__device__ __half g_vth[BHsz*DKsz*Lsz];
__device__ __half g_sh[3][Bsz*Lsz*Dsz], g_sl[3][Bsz*Lsz*Dsz]; // staged inputs (0 reused for x)
__device__ __half g_wh[4*Dsz*Dsz];                            // weights, transposed [n][k]

// ---------------------------------------------------------------------------
__device__ __forceinline__ void mma_f16(float* c, const uint32_t* a, const uint32_t* b)
{
    asm volatile(
        "mma.sync.aligned.m16n8k16.row.col.f32.f16.f16.f32 "
        "{%0,%1,%2,%3}, {%4,%5,%6,%7}, {%8,%9}, {%0,%1,%2,%3};\n"
        : "+f"(c[0]), "+f"(c[1]), "+f"(c[2]), "+f"(c[3])
        : "r"(a[0]), "r"(a[1]), "r"(a[2]), "r"(a[3]), "r"(b[0]), "r"(b[1]));
}

__device__ __forceinline__ void ldsm_x4(uint32_t* r, const void* p)
{
    uint32_t a = (uint32_t)__cvta_generic_to_shared(p);
    asm volatile("ldmatrix.sync.aligned.m8n8.x4.shared.b16 {%0,%1,%2,%3}, [%4];"
                 : "=r"(r[0]), "=r"(r[1]), "=r"(r[2]), "=r"(r[3]) : "r"(a));
}

__device__ __forceinline__ void split8h(float4 v0, float4 v1,
                                        __half* dh, __half* dl)
{
    __align__(16) __half hh[8], ll[8];
    float vv[8] = {v0.x, v0.y, v0.z, v0.w, v1.x, v1.y, v1.z, v1.w};
    #pragma unroll
    for (int e = 0; e < 8; e++) {
        __half h = __float2half_rn(vv[e]);
        hh[e] = h;
        ll[e] = __float2half_rn(vv[e] - __half2float(h));
    }
    *(uint4*)dh = *(const uint4*)hh;
    *(uint4*)dl = *(const uint4*)ll;
}

__device__ __forceinline__ void split2h(float x, float y, uint32_t& hp, uint32_t& lp)
{
    __half hx = __float2half_rn(x), hy = __float2half_rn(y);
    __half lx = __float2half_rn(x - __half2float(hx));
    __half ly = __float2half_rn(y - __half2float(hy));
    __half2 hh = {hx, hy}, ll = {lx, ly};
    hp = *(uint32_t*)&hh;
    lp = *(uint32_t*)&ll;
}

__device__ __forceinline__ uint32_t pack2h(float x, float y)
{
    __half2 h = __floats2half2_rn(x, y);
    return *(uint32_t*)&h;
}

// ---------------------------------------------------------------------------
// Merged conversion kernels
// ---------------------------------------------------------------------------
// All 4 weights: [k][n] fp32 -> g_wh [widx][n][k] fp16 (transposed)
__global__ __launch_bounds__(1024) void cvt_wt_all(const float* __restrict__ wQ,
                                                   const float* __restrict__ wK,
                                                   const float* __restrict__ wV,
                                                   const float* __restrict__ wfc)
{
    __shared__ float t[32][33];
    const int widx = blockIdx.z;
    const float* w = (widx == 0) ? wQ : (widx == 1) ? wK : (widx == 2) ? wV : wfc;
    const int k0 = blockIdx.x * 32, n0 = blockIdx.y * 32;
    const int tx = threadIdx.x, ty = threadIdx.y;
    t[ty][tx] = w[(size_t)(k0 + ty) * 512 + n0 + tx];
    __syncthreads();
    float v = t[tx][ty];
    g_wh[(size_t)widx * 512 * 512 + (size_t)(n0 + ty) * 512 + (k0 + tx)] = __float2half_rn(v);
}

// All 3 inputs -> hi/lo fp16 staging buffers
__global__ __launch_bounds__(256) void cvt_split3(const float* __restrict__ q,
                                                  const float* __restrict__ k,
                                                  const float* __restrict__ v)
{
    const int src = blockIdx.y;
    const float* s = (src == 0) ? q : (src == 1) ? k : v;
    const size_t i = ((size_t)blockIdx.x * 256 + threadIdx.x) * 8;
    float4 v0 = *(const float4*)&s[i];
    float4 v1 = *(const float4*)&s[i + 4];
    split8h(v0, v1, &g_sh[src][i], &g_sl[src][i]);
}

// ---------------------------------------------------------------------------
// fp16 2-MMA-split tensor-core GEMM: C[8192,512] = (Ahi+Alo) @ Whi(mode)
// BM=128,BN=64,BK=64, 256 thr (8 warps 4m x 2n). Dynamic smem double-buffer
// (92,160 B, 2 CTAs/SM), one sync per BK=64 iteration.
// mode = mode_base + blockIdx.z:
//   0: ->g_qh/g_ql (x0.125)  1: ->g_kh  2: ->g_vth (transposed)  3: ->outp fp32
// ---------------------------------------------------------------------------
#define PROJ_SMEM_BYTES 92160

__global__ __launch_bounds__(256, 2) void proj_all(int mode_base, float* __restrict__ outp)
{
    extern __shared__ __align__(16) char smem_raw[];
    __half* Ah = (__half*)smem_raw;                       // [2][128][72]
    __half* Al = (__half*)(smem_raw + 36864);             // [2][128][72]
    __half* Bh = (__half*)(smem_raw + 73728);             // [2][64][72]

    const int mode = mode_base + blockIdx.z;
    const __half* Sh = g_sh[(mode < 3) ? mode : 0];
    const __half* Sl = g_sl[(mode < 3) ? mode : 0];
    const __half* Wh = g_wh + (size_t)mode * 512 * 512;

    const int tid  = threadIdx.x;
    const int wid  = tid >> 5;
    const int lane = tid & 31;
    const int wm = (wid >> 1) * 32;
    const int wn = (wid & 1) * 32;
    const int g  = lane >> 2;
    const int t4 = lane & 3;

    const int mBase = blockIdx.x * 128;
    const int nBase = blockIdx.y * 64;

    // loaders (BK=64): A 4 uint4/thread/buf, B 2 uint4/thread
    const int ar = tid >> 1;               // 0..127
    const int ac = (tid & 1) * 32;         // 0 or 32
    const int br = tid >> 2;               // 0..63
    const int bc = (tid & 3) * 16;         // 0,16,32,48

    const int a_r0 = wm + (lane & 15);
    const int a_c  = (lane >> 4) << 3;
    const int b_r0 = wn + (lane & 7) + ((lane >> 4) << 3);
    const int b_c  = ((lane >> 3) & 1) * 8;

    float acc[2][4][4] = {};

    uint4 sAh[4], sAl[4], sBh[2];
    auto stage = [&](int k0) {
        const size_t a0 = (size_t)(mBase + ar) * 512 + k0 + ac;
        #pragma unroll
        for (int j = 0; j < 4; j++) {
            sAh[j] = *(const uint4*)&Sh[a0 + j * 8];
            sAl[j] = *(const uint4*)&Sl[a0 + j * 8];
        }
        const size_t b0 = (size_t)(nBase + br) * 512 + k0 + bc;
        sBh[0] = *(const uint4*)&Wh[b0];
        sBh[1] = *(const uint4*)&Wh[b0 + 8];
    };
    auto commit = [&](int buf) {
        __half* ah = Ah + buf * 128 * BS + ar * BS + ac;
        __half* al = Al + buf * 128 * BS + ar * BS + ac;
        #pragma unroll
        for (int j = 0; j < 4; j++) {
            *(uint4*)(ah + j * 8) = sAh[j];
            *(uint4*)(al + j * 8) = sAl[j];
        }
        __half* bh = Bh + buf * 64 * BS + br * BS + bc;
        *(uint4*)bh       = sBh[0];
        *(uint4*)(bh + 8) = sBh[1];
    };

    stage(0);
    commit(0);
    stage(64);
    __syncthreads();

    int buf = 0;
    for (int k0 = 0; k0 < 512; k0 += 64, buf ^= 1) {
        if (k0 + 64 < 512) {
            commit(buf ^ 1);
            if (k0 + 128 < 512) stage(k0 + 128);
        }

        const __half* AhB = Ah + buf * 128 * BS;
        const __half* AlB = Al + buf * 128 * BS;
        const __half* BhB = Bh + buf * 64 * BS;
        #pragma unroll
        for (int ks = 0; ks < 64; ks += 16) {
            uint32_t ah0[4], ah1[4], al0[4], al1[4];
            ldsm_x4(ah0, &AhB[ a_r0       * BS + ks + a_c]);
            ldsm_x4(ah1, &AhB[(a_r0 + 16) * BS + ks + a_c]);
            ldsm_x4(al0, &AlB[ a_r0       * BS + ks + a_c]);
            ldsm_x4(al1, &AlB[(a_r0 + 16) * BS + ks + a_c]);
            uint32_t bh01[4], bh23[4];
            ldsm_x4(bh01, &BhB[ b_r0       * BS + ks + b_c]);
            ldsm_x4(bh23, &BhB[(b_r0 + 16) * BS + ks + b_c]);

            const uint32_t* AH[2] = {ah0, ah1};
            const uint32_t* AL[2] = {al0, al1};
            const uint32_t* BH[4] = {&bh01[0], &bh01[2], &bh23[0], &bh23[2]};
            #pragma unroll
            for (int mf = 0; mf < 2; mf++)
                #pragma unroll
                for (int nf = 0; nf < 4; nf++) {
                    mma_f16(acc[mf][nf], AH[mf], BH[nf]);
                    mma_f16(acc[mf][nf], AL[mf], BH[nf]);
                }
        }
        __syncthreads();
    }

    // ---- epilogue
    #pragma unroll
    for (int mf = 0; mf < 2; mf++) {
        #pragma unroll
        for (int nf = 0; nf < 4; nf++) {
            const int col = wn + nf * 8 + 2 * t4;
            const int r0  = mBase + wm + mf * 16 + g;
            const int r1  = r0 + 8;
            float v0 = acc[mf][nf][0], v1 = acc[mf][nf][1];
            float v2 = acc[mf][nf][2], v3 = acc[mf][nf][3];
            if (mode == 3) {
                float2 lo2 = {v0, v1}, hi2 = {v2, v3};
                *(float2*)&outp[(size_t)r0 * 512 + nBase + col] = lo2;
                *(float2*)&outp[(size_t)r1 * 512 + nBase + col] = hi2;
            } else {
                const int hh = blockIdx.y;               // BN=64 == DK
                const int b0 = r0 >> 9, l0 = r0 & 511;
                const int b1 = r1 >> 9, l1 = r1 & 511;
                if (mode == 2) {
                    size_t c0 = ((size_t)(b0 * Hsz + hh) * DKsz + col) * Lsz;
                    size_t c1 = ((size_t)(b0 * Hsz + hh) * DKsz + col + 1) * Lsz;
                    g_vth[c0 + l0] = __float2half_rn(v0);
                    g_vth[c1 + l0] = __float2half_rn(v1);
                    g_vth[c0 + l1] = __float2half_rn(v2);
                    g_vth[c1 + l1] = __float2half_rn(v3);
                } else if (mode == 1) {
                    size_t i0 = (((size_t)b0 * Hsz + hh) * Lsz + l0) * DKsz + col;
                    size_t i1 = (((size_t)b1 * Hsz + hh) * Lsz + l1) * DKsz + col;
                    *(uint32_t*)&g_kh[i0] = pack2h(v0, v1);
                    *(uint32_t*)&g_kh[i1] = pack2h(v2, v3);
                } else {
                    // Q: pre-scale by 1/8 (exact), then split hi/lo
                    uint32_t hp, lp;
                    split2h(v0 * 0.125f, v1 * 0.125f, hp, lp);
                    size_t i0 = (((size_t)b0 * Hsz + hh) * Lsz + l0) * DKsz + col;
                    *(uint32_t*)&g_qh[i0] = hp;
                    *(uint32_t*)&g_ql[i0] = lp;
                    split2h(v2 * 0.125f, v3 * 0.125f, hp, lp);
                    size_t i1 = (((size_t)b1 * Hsz + hh) * Lsz + l1) * DKsz + col;
                    *(uint32_t*)&g_qh[i1] = hp;
                    *(uint32_t*)&g_ql[i1] = lp;
                }
            }
        }
    }
}

// ---------------------------------------------------------------------------
// Tensor-core fused attention. 512 threads = 16 warps (4m x 4n).
// smem: s[64][516] fp32 + 6 fp16 bufs [64][72] = 187,392 B.
// Q pre-scaled by 1/8 -> scores written raw. One sync per chunk.
// ---------------------------------------------------------------------------
__global__ __launch_bounds__(512) void attn_mma(const int* __restrict__ mask,
                                                const float* __restrict__ aiw,
                                                float* __restrict__ p_out)
{
    extern __shared__ float sm[];
    float* s = sm;                                        // [64][516]
    __half* base = (__half*)(sm + 64 * SD);
    __half* Bf[6];
    #pragma unroll
    for (int i = 0; i < 6; i++) Bf[i] = base + (size_t)i * 64 * BS;

    const int tid  = threadIdx.x;
    const int wid  = tid >> 5;
    const int lane = tid & 31;
    const int g  = lane >> 2;
    const int t4 = lane & 3;
    const int wm = (wid & 3) * 16;
    const int wc = wid >> 2;

    const int bh = blockIdx.y;
    const int b  = bh >> 3;
    const int h  = bh & 7;
    const int qBase = blockIdx.x * 64;

    const int cr = tid >> 3;
    const int cc = (tid & 7) * 8;

    const int a_r = wm + (lane & 15);
    const int a_c = (lane >> 4) << 3;
    const int b_r = wc * 16 + (lane & 7) + ((lane >> 4) << 3);
    const int b_c = ((lane >> 3) & 1) * 8;

    // ---- Phase 1: S = (Q/8) K^T  (K hi-only ping-pong)
    {
        const size_t qo = ((size_t)bh * Lsz + qBase + cr) * DKsz + cc;
        *(uint4*)&Bf[0][cr * BS + cc] = *(const uint4*)&g_qh[qo];
        *(uint4*)&Bf[1][cr * BS + cc] = *(const uint4*)&g_ql[qo];
    }
    uint4 kh = *(const uint4*)&g_kh[((size_t)bh * Lsz + cr) * DKsz + cc];
    *(uint4*)&Bf[4][cr * BS + cc] = kh;
    kh = *(const uint4*)&g_kh[((size_t)bh * Lsz + 64 + cr) * DKsz + cc];
    __syncthreads();

    for (int nt = 0; nt < 8; nt++) {
        const int cb = 4 + (nt & 1);
        if (nt < 7) {
            const int nb = 4 + ((nt + 1) & 1);
            *(uint4*)&Bf[nb][cr * BS + cc] = kh;
            if (nt < 6)
                kh = *(const uint4*)&g_kh[((size_t)bh * Lsz + (nt + 2) * 64 + cr) * DKsz + cc];
        }

        float acc[2][4] = {};
        #pragma unroll
        for (int ks = 0; ks < 64; ks += 16) {
            uint32_t ah[4], al[4], bhv[4];
            ldsm_x4(ah,  &Bf[0][a_r * BS + ks + a_c]);
            ldsm_x4(al,  &Bf[1][a_r * BS + ks + a_c]);
            ldsm_x4(bhv, &Bf[cb][b_r * BS + ks + b_c]);
            mma_f16(acc[0], ah, &bhv[0]);
            mma_f16(acc[0], al, &bhv[0]);
            mma_f16(acc[1], ah, &bhv[2]);
            mma_f16(acc[1], al, &bhv[2]);
        }
        #pragma unroll
        for (int nf = 0; nf < 2; nf++) {
            const int col = nt * 64 + wc * 16 + nf * 8 + 2 * t4;
            const int row = wm + g;
            s[ row      * SD + col    ] = acc[nf][0];
            s[ row      * SD + col + 1] = acc[nf][1];
            s[(row + 8) * SD + col    ] = acc[nf][2];
            s[(row + 8) * SD + col + 1] = acc[nf][3];
        }
        __syncthreads();
    }

    // ---- Phase 2: vectorized mask + softmax + *aiw + p_attn (regs-resident)
    {
        #pragma unroll
        for (int r = 0; r < 4; r++) {
            const int m = wid * 4 + r;
            const int qRow = qBase + m;
            const int4*   m4 = (const int4*)  (mask + ((size_t)b * Lsz + qRow) * Lsz);
            const float4* a4 = (const float4*)(aiw  + ((size_t)b * Lsz + qRow) * Lsz);
            float4* s4 = (float4*)(s + m * SD);
            float4* p4 = (float4*)(p_out + ((size_t)bh * Lsz + qRow) * Lsz);

            float4 sv[4];
            float mx = -1e30f;
            #pragma unroll
            for (int j = 0; j < 4; j++) {
                const int gidx = j * 32 + lane;
                float4 v = s4[gidx];
                int4  mm = m4[gidx];
                v.x = mm.x ? -1e30f : v.x;
                v.y = mm.y ? -1e30f : v.y;
                v.z = mm.z ? -1e30f : v.z;
                v.w = mm.w ? -1e30f : v.w;
                sv[j] = v;
                mx = fmaxf(mx, fmaxf(fmaxf(v.x, v.y), fmaxf(v.z, v.w)));
            }
            #pragma unroll
            for (int o = 16; o; o >>= 1) mx = fmaxf(mx, __shfl_xor_sync(0xffffffffu, mx, o));

            float sum = 0.f;
            #pragma unroll
            for (int j = 0; j < 4; j++) {
                sv[j].x = __expf(sv[j].x - mx);
                sv[j].y = __expf(sv[j].y - mx);
                sv[j].z = __expf(sv[j].z - mx);
                sv[j].w = __expf(sv[j].w - mx);
                sum += (sv[j].x + sv[j].y) + (sv[j].z + sv[j].w);
            }
            #pragma unroll
            for (int o = 16; o; o >>= 1) sum += __shfl_xor_sync(0xffffffffu, sum, o);
            const float inv = 1.f / sum;

            #pragma unroll
            for (int j = 0; j < 4; j++) {
                const int gidx = j * 32 + lane;
                float4 a = a4[gidx];
                float4 p;
                p.x = sv[j].x * inv * a.x;
                p.y = sv[j].y * inv * a.y;
                p.z = sv[j].z * inv * a.z;
                p.w = sv[j].w * inv * a.w;
                p4[gidx] = p;
                s4[gidx] = p;
            }
        }
    }
    __syncthreads();

    // ---- Phase 3: X = P V  (P hi/lo ping-pong, V hi-only ping-pong)
    uint4 vh = *(const uint4*)&g_vth[((size_t)bh * DKsz + cr) * Lsz + cc];
    *(uint4*)&Bf[4][cr * BS + cc] = vh;
    {
        const float* ps = &s[cr * SD + cc];
        split8h(*(const float4*)ps, *(const float4*)(ps + 4),
                &Bf[0][cr * BS + cc], &Bf[1][cr * BS + cc]);
    }
    vh = *(const uint4*)&g_vth[((size_t)bh * DKsz + cr) * Lsz + 64 + cc];
    __syncthreads();

    float acc[2][4] = {};
    for (int kt = 0; kt < 8; kt++) {
        const int pb = (kt & 1) ? 2 : 0;
        const int vb = 4 + (kt & 1);
        if (kt < 7) {
            const int npb = (kt & 1) ? 0 : 2;
            const int nvb = 4 + ((kt + 1) & 1);
            *(uint4*)&Bf[nvb][cr * BS + cc] = vh;
            const float* ps = &s[cr * SD + (kt + 1) * 64 + cc];
            split8h(*(const float4*)ps, *(const float4*)(ps + 4),
                    &Bf[npb][cr * BS + cc], &Bf[npb + 1][cr * BS + cc]);
            if (kt < 6)
                vh = *(const uint4*)&g_vth[((size_t)bh * DKsz + cr) * Lsz + (kt + 2) * 64 + cc];
        }

        #pragma unroll
        for (int ks = 0; ks < 64; ks += 16) {
            uint32_t ah[4], al[4], bhv[4];
            ldsm_x4(ah,  &Bf[pb    ][a_r * BS + ks + a_c]);
            ldsm_x4(al,  &Bf[pb + 1][a_r * BS + ks + a_c]);
            ldsm_x4(bhv, &Bf[vb][b_r * BS + ks + b_c]);
            mma_f16(acc[0], ah, &bhv[0]);
            mma_f16(acc[0], al, &bhv[0]);
            mma_f16(acc[1], ah, &bhv[2]);
            mma_f16(acc[1], al, &bhv[2]);
        }
        __syncthreads();
    }

    // ---- X epilogue: fp16 hi/lo into staging buffer 0 (fc input)
    #pragma unroll
    for (int nf = 0; nf < 2; nf++) {
        const int col = wc * 16 + nf * 8 + 2 * t4;
        const int row = qBase + wm + g;
        uint32_t hp, lp;
        split2h(acc[nf][0], acc[nf][1], hp, lp);
        size_t i0 = ((size_t)b * Lsz + row) * Dsz + h * 64 + col;
        *(uint32_t*)&g_sh[0][i0] = hp;
        *(uint32_t*)&g_sl[0][i0] = lp;
        split2h(acc[nf][2], acc[nf][3], hp, lp);
        size_t i1 = ((size_t)b * Lsz + row + 8) * Dsz + h * 64 + col;
        *(uint32_t*)&g_sh[0][i1] = hp;
        *(uint32_t*)&g_sl[0][i1] = lp;
    }
}

// ---------------------------------------------------------------------------
extern "C" void kernel_launch(void* const* d_in, const int* in_sizes, int n_in,
                              void* d_out, int out_size)
{
    (void)in_sizes; (void)n_in; (void)out_size;
    const float* query = (const float*)d_in[0];
    const float* keyt  = (const float*)d_in[1];
    const float* value = (const float*)d_in[2];
    const int*   mask  = (const int*)d_in[3];     // bool upcast to int32
    const float* aiw   = (const float*)d_in[4];
    const float* wQ    = (const float*)d_in[5];
    const float* wK    = (const float*)d_in[6];
    const float* wV    = (const float*)d_in[7];
    const float* wfc   = (const float*)d_in[8];

    float* outx = (float*)d_out;                       // x: [B,L,D]
    float* outp = outx + (size_t)Bsz * Lsz * Dsz;      // p_attn: [B,H,L,L]

    cudaFuncSetAttribute((const void*)proj_all,
                         cudaFuncAttributeMaxDynamicSharedMemorySize, PROJ_SMEM_BYTES);
    const int attn_smem = 64 * SD * (int)sizeof(float)
                        + 6 * 64 * BS * (int)sizeof(__half);   // 187,392 B
    cudaFuncSetAttribute((const void*)attn_mma,
                         cudaFuncAttributeMaxDynamicSharedMemorySize, attn_smem);

    // 1. all weight transposes (one launch)
    cvt_wt_all<<<dim3(16, 16, 4), dim3(32, 32)>>>(wQ, wK, wV, wfc);
    // 2. all input splits (one launch)
    cvt_split3<<<dim3(2048, 3), 256>>>(query, keyt, value);
    // 3. Q/K/V projections (one launch, z = mode)
    proj_all<<<dim3(64, 8, 3), 256, PROJ_SMEM_BYTES>>>(0, nullptr);
    // 4. fused attention
    attn_mma<<<dim3(8, 128), 512, attn_smem>>>(mask, aiw, outp);
    // 5. fc projection
    proj_all<<<dim3(64, 8, 1), 256, PROJ_SMEM_BYTES>>>(3, outx);
}

// round 15
// speedup vs baseline: 3.0146x; 1.0844x over previous
#include <cuda_runtime.h>
#include <cuda_fp16.h>
#include <cstdint>

#define Bsz 16
#define Lsz 512
#define Dsz 512
#define Hsz 8
#define DKsz 64
#define BHsz (Bsz*Hsz)

#define SD 516   // score row stride (floats)
#define BS 72    // fp16 buffer row stride (halves)
#define PREG (64*BS)   // one fp16 buffer (halves)

// Scratch (allocation-free contract: __device__ globals)
__device__ __half g_qh[BHsz*Lsz*DKsz], g_ql[BHsz*Lsz*DKsz];   // Q pre-scaled by 1/8
__device__ __half g_kh[BHsz*Lsz*DKsz];
__device__ __half g_vth[BHsz*DKsz*Lsz];
__device__ __half g_sh[3][Bsz*Lsz*Dsz], g_sl[3][Bsz*Lsz*Dsz]; // staged inputs (0 reused for x)
__device__ __half g_wh[4*Dsz*Dsz];                            // weights, transposed [n][k]

// ---------------------------------------------------------------------------
__device__ __forceinline__ void mma_f16(float* c, const uint32_t* a, const uint32_t* b)
{
    asm volatile(
        "mma.sync.aligned.m16n8k16.row.col.f32.f16.f16.f32 "
        "{%0,%1,%2,%3}, {%4,%5,%6,%7}, {%8,%9}, {%0,%1,%2,%3};\n"
        : "+f"(c[0]), "+f"(c[1]), "+f"(c[2]), "+f"(c[3])
        : "r"(a[0]), "r"(a[1]), "r"(a[2]), "r"(a[3]), "r"(b[0]), "r"(b[1]));
}

__device__ __forceinline__ void ldsm_x4(uint32_t* r, const void* p)
{
    uint32_t a = (uint32_t)__cvta_generic_to_shared(p);
    asm volatile("ldmatrix.sync.aligned.m8n8.x4.shared.b16 {%0,%1,%2,%3}, [%4];"
                 : "=r"(r[0]), "=r"(r[1]), "=r"(r[2]), "=r"(r[3]) : "r"(a));
}

__device__ __forceinline__ void split8h(float4 v0, float4 v1,
                                        __half* dh, __half* dl)
{
    __align__(16) __half hh[8], ll[8];
    float vv[8] = {v0.x, v0.y, v0.z, v0.w, v1.x, v1.y, v1.z, v1.w};
    #pragma unroll
    for (int e = 0; e < 8; e++) {
        __half h = __float2half_rn(vv[e]);
        hh[e] = h;
        ll[e] = __float2half_rn(vv[e] - __half2float(h));
    }
    *(uint4*)dh = *(const uint4*)hh;
    *(uint4*)dl = *(const uint4*)ll;
}

__device__ __forceinline__ void split2h(float x, float y, uint32_t& hp, uint32_t& lp)
{
    __half hx = __float2half_rn(x), hy = __float2half_rn(y);
    __half lx = __float2half_rn(x - __half2float(hx));
    __half ly = __float2half_rn(y - __half2float(hy));
    __half2 hh = {hx, hy}, ll = {lx, ly};
    hp = *(uint32_t*)&hh;
    lp = *(uint32_t*)&ll;
}

__device__ __forceinline__ uint32_t pack2h(float x, float y)
{
    __half2 h = __floats2half2_rn(x, y);
    return *(uint32_t*)&h;
}

// ---------------------------------------------------------------------------
// Merged conversion kernels (unchanged from R13)
// ---------------------------------------------------------------------------
__global__ __launch_bounds__(1024) void cvt_wt_all(const float* __restrict__ wQ,
                                                   const float* __restrict__ wK,
                                                   const float* __restrict__ wV,
                                                   const float* __restrict__ wfc)
{
    __shared__ float t[32][33];
    const int widx = blockIdx.z;
    const float* w = (widx == 0) ? wQ : (widx == 1) ? wK : (widx == 2) ? wV : wfc;
    const int k0 = blockIdx.x * 32, n0 = blockIdx.y * 32;
    const int tx = threadIdx.x, ty = threadIdx.y;
    t[ty][tx] = w[(size_t)(k0 + ty) * 512 + n0 + tx];
    __syncthreads();
    float v = t[tx][ty];
    g_wh[(size_t)widx * 512 * 512 + (size_t)(n0 + ty) * 512 + (k0 + tx)] = __float2half_rn(v);
}

__global__ __launch_bounds__(256) void cvt_split3(const float* __restrict__ q,
                                                  const float* __restrict__ k,
                                                  const float* __restrict__ v)
{
    const int src = blockIdx.y;
    const float* s = (src == 0) ? q : (src == 1) ? k : v;
    const size_t i = ((size_t)blockIdx.x * 256 + threadIdx.x) * 8;
    float4 v0 = *(const float4*)&s[i];
    float4 v1 = *(const float4*)&s[i + 4];
    split8h(v0, v1, &g_sh[src][i], &g_sl[src][i]);
}

// ---------------------------------------------------------------------------
// fp16 2-MMA-split tensor-core GEMM (unchanged from R13)
// ---------------------------------------------------------------------------
#define PROJ_SMEM_BYTES 92160

__global__ __launch_bounds__(256, 2) void proj_all(int mode_base, float* __restrict__ outp)
{
    extern __shared__ __align__(16) char smem_raw[];
    __half* Ah = (__half*)smem_raw;                       // [2][128][72]
    __half* Al = (__half*)(smem_raw + 36864);             // [2][128][72]
    __half* Bh = (__half*)(smem_raw + 73728);             // [2][64][72]

    const int mode = mode_base + blockIdx.z;
    const __half* Sh = g_sh[(mode < 3) ? mode : 0];
    const __half* Sl = g_sl[(mode < 3) ? mode : 0];
    const __half* Wh = g_wh + (size_t)mode * 512 * 512;

    const int tid  = threadIdx.x;
    const int wid  = tid >> 5;
    const int lane = tid & 31;
    const int wm = (wid >> 1) * 32;
    const int wn = (wid & 1) * 32;
    const int g  = lane >> 2;
    const int t4 = lane & 3;

    const int mBase = blockIdx.x * 128;
    const int nBase = blockIdx.y * 64;

    const int ar = tid >> 1;
    const int ac = (tid & 1) * 32;
    const int br = tid >> 2;
    const int bc = (tid & 3) * 16;

    const int a_r0 = wm + (lane & 15);
    const int a_c  = (lane >> 4) << 3;
    const int b_r0 = wn + (lane & 7) + ((lane >> 4) << 3);
    const int b_c  = ((lane >> 3) & 1) * 8;

    float acc[2][4][4] = {};

    uint4 sAh[4], sAl[4], sBh[2];
    auto stage = [&](int k0) {
        const size_t a0 = (size_t)(mBase + ar) * 512 + k0 + ac;
        #pragma unroll
        for (int j = 0; j < 4; j++) {
            sAh[j] = *(const uint4*)&Sh[a0 + j * 8];
            sAl[j] = *(const uint4*)&Sl[a0 + j * 8];
        }
        const size_t b0 = (size_t)(nBase + br) * 512 + k0 + bc;
        sBh[0] = *(const uint4*)&Wh[b0];
        sBh[1] = *(const uint4*)&Wh[b0 + 8];
    };
    auto commit = [&](int buf) {
        __half* ah = Ah + buf * 128 * BS + ar * BS + ac;
        __half* al = Al + buf * 128 * BS + ar * BS + ac;
        #pragma unroll
        for (int j = 0; j < 4; j++) {
            *(uint4*)(ah + j * 8) = sAh[j];
            *(uint4*)(al + j * 8) = sAl[j];
        }
        __half* bh = Bh + buf * 64 * BS + br * BS + bc;
        *(uint4*)bh       = sBh[0];
        *(uint4*)(bh + 8) = sBh[1];
    };

    stage(0);
    commit(0);
    stage(64);
    __syncthreads();

    int buf = 0;
    for (int k0 = 0; k0 < 512; k0 += 64, buf ^= 1) {
        if (k0 + 64 < 512) {
            commit(buf ^ 1);
            if (k0 + 128 < 512) stage(k0 + 128);
        }

        const __half* AhB = Ah + buf * 128 * BS;
        const __half* AlB = Al + buf * 128 * BS;
        const __half* BhB = Bh + buf * 64 * BS;
        #pragma unroll
        for (int ks = 0; ks < 64; ks += 16) {
            uint32_t ah0[4], ah1[4], al0[4], al1[4];
            ldsm_x4(ah0, &AhB[ a_r0       * BS + ks + a_c]);
            ldsm_x4(ah1, &AhB[(a_r0 + 16) * BS + ks + a_c]);
            ldsm_x4(al0, &AlB[ a_r0       * BS + ks + a_c]);
            ldsm_x4(al1, &AlB[(a_r0 + 16) * BS + ks + a_c]);
            uint32_t bh01[4], bh23[4];
            ldsm_x4(bh01, &BhB[ b_r0       * BS + ks + b_c]);
            ldsm_x4(bh23, &BhB[(b_r0 + 16) * BS + ks + b_c]);

            const uint32_t* AH[2] = {ah0, ah1};
            const uint32_t* AL[2] = {al0, al1};
            const uint32_t* BH[4] = {&bh01[0], &bh01[2], &bh23[0], &bh23[2]};
            #pragma unroll
            for (int mf = 0; mf < 2; mf++)
                #pragma unroll
                for (int nf = 0; nf < 4; nf++) {
                    mma_f16(acc[mf][nf], AH[mf], BH[nf]);
                    mma_f16(acc[mf][nf], AL[mf], BH[nf]);
                }
        }
        __syncthreads();
    }

    #pragma unroll
    for (int mf = 0; mf < 2; mf++) {
        #pragma unroll
        for (int nf = 0; nf < 4; nf++) {
            const int col = wn + nf * 8 + 2 * t4;
            const int r0  = mBase + wm + mf * 16 + g;
            const int r1  = r0 + 8;
            float v0 = acc[mf][nf][0], v1 = acc[mf][nf][1];
            float v2 = acc[mf][nf][2], v3 = acc[mf][nf][3];
            if (mode == 3) {
                float2 lo2 = {v0, v1}, hi2 = {v2, v3};
                *(float2*)&outp[(size_t)r0 * 512 + nBase + col] = lo2;
                *(float2*)&outp[(size_t)r1 * 512 + nBase + col] = hi2;
            } else {
                const int hh = blockIdx.y;
                const int b0 = r0 >> 9, l0 = r0 & 511;
                const int b1 = r1 >> 9, l1 = r1 & 511;
                if (mode == 2) {
                    size_t c0 = ((size_t)(b0 * Hsz + hh) * DKsz + col) * Lsz;
                    size_t c1 = ((size_t)(b0 * Hsz + hh) * DKsz + col + 1) * Lsz;
                    g_vth[c0 + l0] = __float2half_rn(v0);
                    g_vth[c1 + l0] = __float2half_rn(v1);
                    g_vth[c0 + l1] = __float2half_rn(v2);
                    g_vth[c1 + l1] = __float2half_rn(v3);
                } else if (mode == 1) {
                    size_t i0 = (((size_t)b0 * Hsz + hh) * Lsz + l0) * DKsz + col;
                    size_t i1 = (((size_t)b1 * Hsz + hh) * Lsz + l1) * DKsz + col;
                    *(uint32_t*)&g_kh[i0] = pack2h(v0, v1);
                    *(uint32_t*)&g_kh[i1] = pack2h(v2, v3);
                } else {
                    uint32_t hp, lp;
                    split2h(v0 * 0.125f, v1 * 0.125f, hp, lp);
                    size_t i0 = (((size_t)b0 * Hsz + hh) * Lsz + l0) * DKsz + col;
                    *(uint32_t*)&g_qh[i0] = hp;
                    *(uint32_t*)&g_ql[i0] = lp;
                    split2h(v2 * 0.125f, v3 * 0.125f, hp, lp);
                    size_t i1 = (((size_t)b1 * Hsz + hh) * Lsz + l1) * DKsz + col;
                    *(uint32_t*)&g_qh[i1] = hp;
                    *(uint32_t*)&g_ql[i1] = lp;
                }
            }
        }
    }
}

// ---------------------------------------------------------------------------
// Tensor-core fused attention v2. 512 threads = 16 warps (4m x 4n).
// smem: s[64][516] fp32 (132,096) + P 8x[64][72] fp16 (73,728; aliased as
// Qh/Ql/K-ping in phase 1) + V 2x[64][72] fp16 (18,432) = 224,256 B.
// Phase 2 writes P as fp16 directly into chunk layout (lo-term dropped:
// P in [0,1], adds ~4.9e-4 to x). Phase 3: 2 MMAs/ks, no split, V ping-pong.
// Q fragments hoisted to registers (loaded once).
// ---------------------------------------------------------------------------
__global__ __launch_bounds__(512) void attn_mma(const int* __restrict__ mask,
                                                const float* __restrict__ aiw,
                                                float* __restrict__ p_out)
{
    extern __shared__ float sm[];
    float* s = sm;                                        // [64][516]
    __half* Pr = (__half*)(sm + 64 * SD);                 // 8 bufs [64][BS]
    __half* Vr = Pr + 8 * PREG;                           // 2 bufs [64][BS]

    const int tid  = threadIdx.x;
    const int wid  = tid >> 5;
    const int lane = tid & 31;
    const int g  = lane >> 2;
    const int t4 = lane & 3;
    const int wm = (wid & 3) * 16;
    const int wc = wid >> 2;

    const int bh = blockIdx.y;
    const int b  = bh >> 3;
    const int h  = bh & 7;
    const int qBase = blockIdx.x * 64;

    const int cr = tid >> 3;
    const int cc = (tid & 7) * 8;

    const int a_r = wm + (lane & 15);
    const int a_c = (lane >> 4) << 3;
    const int b_r = wc * 16 + (lane & 7) + ((lane >> 4) << 3);
    const int b_c = ((lane >> 3) & 1) * 8;

    // ---- Phase 1 prologue: Q (pre-scaled) into Pr bufs 0/1, K chunk0 into buf2
    {
        const size_t qo = ((size_t)bh * Lsz + qBase + cr) * DKsz + cc;
        *(uint4*)&Pr[cr * BS + cc]        = *(const uint4*)&g_qh[qo];
        *(uint4*)&Pr[PREG + cr * BS + cc] = *(const uint4*)&g_ql[qo];
    }
    uint4 kh = *(const uint4*)&g_kh[((size_t)bh * Lsz + cr) * DKsz + cc];
    *(uint4*)&Pr[2 * PREG + cr * BS + cc] = kh;
    kh = *(const uint4*)&g_kh[((size_t)bh * Lsz + 64 + cr) * DKsz + cc];
    __syncthreads();

    // Hoist Q fragments (all 4 ks steps) into registers — loaded once.
    uint32_t qah[4][4], qal[4][4];
    #pragma unroll
    for (int ksi = 0; ksi < 4; ksi++) {
        ldsm_x4(qah[ksi], &Pr[a_r * BS + ksi * 16 + a_c]);
        ldsm_x4(qal[ksi], &Pr[PREG + a_r * BS + ksi * 16 + a_c]);
    }

    for (int nt = 0; nt < 8; nt++) {
        __half* cb = Pr + (2 + (nt & 1)) * PREG;
        if (nt < 7) {
            __half* nb = Pr + (2 + ((nt + 1) & 1)) * PREG;
            *(uint4*)&nb[cr * BS + cc] = kh;
            if (nt < 6)
                kh = *(const uint4*)&g_kh[((size_t)bh * Lsz + (nt + 2) * 64 + cr) * DKsz + cc];
        }

        float acc[2][4] = {};
        #pragma unroll
        for (int ksi = 0; ksi < 4; ksi++) {
            uint32_t bhv[4];
            ldsm_x4(bhv, &cb[b_r * BS + ksi * 16 + b_c]);
            mma_f16(acc[0], qah[ksi], &bhv[0]);
            mma_f16(acc[0], qal[ksi], &bhv[0]);
            mma_f16(acc[1], qah[ksi], &bhv[2]);
            mma_f16(acc[1], qal[ksi], &bhv[2]);
        }
        #pragma unroll
        for (int nf = 0; nf < 2; nf++) {
            const int col = nt * 64 + wc * 16 + nf * 8 + 2 * t4;
            const int row = wm + g;
            float2 v01 = {acc[nf][0], acc[nf][1]};
            float2 v23 = {acc[nf][2], acc[nf][3]};
            *(float2*)&s[ row      * SD + col] = v01;
            *(float2*)&s[(row + 8) * SD + col] = v23;
        }
        __syncthreads();
    }

    // ---- Phase 2: mask + softmax + *aiw; write p_out (fp32 global) and
    //      P (fp16) directly into chunked smem layout.
    {
        #pragma unroll
        for (int r = 0; r < 4; r++) {
            const int m = wid * 4 + r;
            const int qRow = qBase + m;
            const int4*   m4 = (const int4*)  (mask + ((size_t)b * Lsz + qRow) * Lsz);
            const float4* a4 = (const float4*)(aiw  + ((size_t)b * Lsz + qRow) * Lsz);
            float4* s4 = (float4*)(s + m * SD);
            float4* p4 = (float4*)(p_out + ((size_t)bh * Lsz + qRow) * Lsz);

            float4 sv[4];
            float mx = -1e30f;
            #pragma unroll
            for (int j = 0; j < 4; j++) {
                const int gidx = j * 32 + lane;
                float4 v = s4[gidx];
                int4  mm = m4[gidx];
                v.x = mm.x ? -1e30f : v.x;
                v.y = mm.y ? -1e30f : v.y;
                v.z = mm.z ? -1e30f : v.z;
                v.w = mm.w ? -1e30f : v.w;
                sv[j] = v;
                mx = fmaxf(mx, fmaxf(fmaxf(v.x, v.y), fmaxf(v.z, v.w)));
            }
            #pragma unroll
            for (int o = 16; o; o >>= 1) mx = fmaxf(mx, __shfl_xor_sync(0xffffffffu, mx, o));

            float sum = 0.f;
            #pragma unroll
            for (int j = 0; j < 4; j++) {
                sv[j].x = __expf(sv[j].x - mx);
                sv[j].y = __expf(sv[j].y - mx);
                sv[j].z = __expf(sv[j].z - mx);
                sv[j].w = __expf(sv[j].w - mx);
                sum += (sv[j].x + sv[j].y) + (sv[j].z + sv[j].w);
            }
            #pragma unroll
            for (int o = 16; o; o >>= 1) sum += __shfl_xor_sync(0xffffffffu, sum, o);
            const float inv = 1.f / sum;

            #pragma unroll
            for (int j = 0; j < 4; j++) {
                const int gidx = j * 32 + lane;
                float4 a = a4[gidx];
                float4 p;
                p.x = sv[j].x * inv * a.x;
                p.y = sv[j].y * inv * a.y;
                p.z = sv[j].z * inv * a.z;
                p.w = sv[j].w * inv * a.w;
                p4[gidx] = p;
                // fp16 P into chunk buffer: chunk = col>>6, off = col&63
                const int chunk = (j << 1) + (lane >> 4);
                const int off   = 4 * (lane & 15);
                uint2 pk;
                pk.x = pack2h(p.x, p.y);
                pk.y = pack2h(p.z, p.w);
                *(uint2*)&Pr[chunk * PREG + m * BS + off] = pk;
            }
        }
    }
    __syncthreads();

    // ---- Phase 3: X = P V  (P resident fp16; V hi-only ping-pong)
    uint4 vh = *(const uint4*)&g_vth[((size_t)bh * DKsz + cr) * Lsz + cc];
    *(uint4*)&Vr[cr * BS + cc] = vh;
    vh = *(const uint4*)&g_vth[((size_t)bh * DKsz + cr) * Lsz + 64 + cc];
    __syncthreads();

    float acc[2][4] = {};
    for (int kt = 0; kt < 8; kt++) {
        __half* pc = Pr + kt * PREG;
        __half* vb = Vr + (kt & 1) * PREG;
        if (kt < 7) {
            __half* nvb = Vr + ((kt + 1) & 1) * PREG;
            *(uint4*)&nvb[cr * BS + cc] = vh;
            if (kt < 6)
                vh = *(const uint4*)&g_vth[((size_t)bh * DKsz + cr) * Lsz + (kt + 2) * 64 + cc];
        }

        #pragma unroll
        for (int ksi = 0; ksi < 4; ksi++) {
            uint32_t ah[4], bhv[4];
            ldsm_x4(ah,  &pc[a_r * BS + ksi * 16 + a_c]);
            ldsm_x4(bhv, &vb[b_r * BS + ksi * 16 + b_c]);
            mma_f16(acc[0], ah, &bhv[0]);
            mma_f16(acc[1], ah, &bhv[2]);
        }
        __syncthreads();
    }

    // ---- X epilogue: fp16 hi/lo into staging buffer 0 (fc input)
    #pragma unroll
    for (int nf = 0; nf < 2; nf++) {
        const int col = wc * 16 + nf * 8 + 2 * t4;
        const int row = qBase + wm + g;
        uint32_t hp, lp;
        split2h(acc[nf][0], acc[nf][1], hp, lp);
        size_t i0 = ((size_t)b * Lsz + row) * Dsz + h * 64 + col;
        *(uint32_t*)&g_sh[0][i0] = hp;
        *(uint32_t*)&g_sl[0][i0] = lp;
        split2h(acc[nf][2], acc[nf][3], hp, lp);
        size_t i1 = ((size_t)b * Lsz + row + 8) * Dsz + h * 64 + col;
        *(uint32_t*)&g_sh[0][i1] = hp;
        *(uint32_t*)&g_sl[0][i1] = lp;
    }
}

// ---------------------------------------------------------------------------
extern "C" void kernel_launch(void* const* d_in, const int* in_sizes, int n_in,
                              void* d_out, int out_size)
{
    (void)in_sizes; (void)n_in; (void)out_size;
    const float* query = (const float*)d_in[0];
    const float* keyt  = (const float*)d_in[1];
    const float* value = (const float*)d_in[2];
    const int*   mask  = (const int*)d_in[3];     // bool upcast to int32
    const float* aiw   = (const float*)d_in[4];
    const float* wQ    = (const float*)d_in[5];
    const float* wK    = (const float*)d_in[6];
    const float* wV    = (const float*)d_in[7];
    const float* wfc   = (const float*)d_in[8];

    float* outx = (float*)d_out;                       // x: [B,L,D]
    float* outp = outx + (size_t)Bsz * Lsz * Dsz;      // p_attn: [B,H,L,L]

    cudaFuncSetAttribute((const void*)proj_all,
                         cudaFuncAttributeMaxDynamicSharedMemorySize, PROJ_SMEM_BYTES);
    const int attn_smem = 64 * SD * (int)sizeof(float)
                        + 10 * PREG * (int)sizeof(__half);   // 224,256 B
    cudaFuncSetAttribute((const void*)attn_mma,
                         cudaFuncAttributeMaxDynamicSharedMemorySize, attn_smem);

    cvt_wt_all<<<dim3(16, 16, 4), dim3(32, 32)>>>(wQ, wK, wV, wfc);
    cvt_split3<<<dim3(2048, 3), 256>>>(query, keyt, value);
    proj_all<<<dim3(64, 8, 3), 256, PROJ_SMEM_BYTES>>>(0, nullptr);
    attn_mma<<<dim3(8, 128), 512, attn_smem>>>(mask, aiw, outp);
    proj_all<<<dim3(64, 8, 1), 256, PROJ_SMEM_BYTES>>>(3, outx);
}

// round 16
// speedup vs baseline: 3.3313x; 1.1051x over previous
#include <cuda_runtime.h>
#include <cuda_fp16.h>
#include <cstdint>

#define Bsz 16
#define Lsz 512
#define Dsz 512
#define Hsz 8
#define DKsz 64
#define BHsz (Bsz*Hsz)

#define SD 516   // score row stride (floats)
#define BS 72    // fp16 buffer row stride (halves)
#define PREG (64*BS)   // one fp16 buffer (halves)

// Scratch (allocation-free contract: __device__ globals)
__device__ __half g_qh[BHsz*Lsz*DKsz], g_ql[BHsz*Lsz*DKsz];   // Q pre-scaled by 1/8
__device__ __half g_kh[BHsz*Lsz*DKsz];
__device__ __half g_vth[BHsz*DKsz*Lsz];
__device__ __half g_sh[3][Bsz*Lsz*Dsz], g_sl[3][Bsz*Lsz*Dsz]; // staged inputs (0 reused for x)
__device__ __half g_wh[4*Dsz*Dsz];                            // weights, transposed [n][k]

// ---------------------------------------------------------------------------
__device__ __forceinline__ void mma_f16(float* c, const uint32_t* a, const uint32_t* b)
{
    asm volatile(
        "mma.sync.aligned.m16n8k16.row.col.f32.f16.f16.f32 "
        "{%0,%1,%2,%3}, {%4,%5,%6,%7}, {%8,%9}, {%0,%1,%2,%3};\n"
        : "+f"(c[0]), "+f"(c[1]), "+f"(c[2]), "+f"(c[3])
        : "r"(a[0]), "r"(a[1]), "r"(a[2]), "r"(a[3]), "r"(b[0]), "r"(b[1]));
}

__device__ __forceinline__ void ldsm_x4(uint32_t* r, const void* p)
{
    uint32_t a = (uint32_t)__cvta_generic_to_shared(p);
    asm volatile("ldmatrix.sync.aligned.m8n8.x4.shared.b16 {%0,%1,%2,%3}, [%4];"
                 : "=r"(r[0]), "=r"(r[1]), "=r"(r[2]), "=r"(r[3]) : "r"(a));
}

__device__ __forceinline__ void split8h(float4 v0, float4 v1,
                                        __half* dh, __half* dl)
{
    __align__(16) __half hh[8], ll[8];
    float vv[8] = {v0.x, v0.y, v0.z, v0.w, v1.x, v1.y, v1.z, v1.w};
    #pragma unroll
    for (int e = 0; e < 8; e++) {
        __half h = __float2half_rn(vv[e]);
        hh[e] = h;
        ll[e] = __float2half_rn(vv[e] - __half2float(h));
    }
    *(uint4*)dh = *(const uint4*)hh;
    *(uint4*)dl = *(const uint4*)ll;
}

__device__ __forceinline__ void cvt8h(float4 v0, float4 v1, __half* dh)
{
    __align__(16) __half hh[8];
    float vv[8] = {v0.x, v0.y, v0.z, v0.w, v1.x, v1.y, v1.z, v1.w};
    #pragma unroll
    for (int e = 0; e < 8; e++) hh[e] = __float2half_rn(vv[e]);
    *(uint4*)dh = *(const uint4*)hh;
}

__device__ __forceinline__ void split2h(float x, float y, uint32_t& hp, uint32_t& lp)
{
    __half hx = __float2half_rn(x), hy = __float2half_rn(y);
    __half lx = __float2half_rn(x - __half2float(hx));
    __half ly = __float2half_rn(y - __half2float(hy));
    __half2 hh = {hx, hy}, ll = {lx, ly};
    hp = *(uint32_t*)&hh;
    lp = *(uint32_t*)&ll;
}

__device__ __forceinline__ uint32_t pack2h(float x, float y)
{
    __half2 h = __floats2half2_rn(x, y);
    return *(uint32_t*)&h;
}

// ---------------------------------------------------------------------------
// Merged conversion kernels
// ---------------------------------------------------------------------------
__global__ __launch_bounds__(1024) void cvt_wt_all(const float* __restrict__ wQ,
                                                   const float* __restrict__ wK,
                                                   const float* __restrict__ wV,
                                                   const float* __restrict__ wfc)
{
    __shared__ float t[32][33];
    const int widx = blockIdx.z;
    const float* w = (widx == 0) ? wQ : (widx == 1) ? wK : (widx == 2) ? wV : wfc;
    const int k0 = blockIdx.x * 32, n0 = blockIdx.y * 32;
    const int tx = threadIdx.x, ty = threadIdx.y;
    t[ty][tx] = w[(size_t)(k0 + ty) * 512 + n0 + tx];
    __syncthreads();
    float v = t[tx][ty];
    g_wh[(size_t)widx * 512 * 512 + (size_t)(n0 + ty) * 512 + (k0 + tx)] = __float2half_rn(v);
}

// query gets hi+lo (Q proj keeps split); key/value get hi only (their
// projections run hi-only since K/V are fp16-rounded for attention anyway).
__global__ __launch_bounds__(256) void cvt_split3(const float* __restrict__ q,
                                                  const float* __restrict__ k,
                                                  const float* __restrict__ v)
{
    const int src = blockIdx.y;
    const float* s = (src == 0) ? q : (src == 1) ? k : v;
    const size_t i = ((size_t)blockIdx.x * 256 + threadIdx.x) * 8;
    float4 v0 = *(const float4*)&s[i];
    float4 v1 = *(const float4*)&s[i + 4];
    if (src == 0) split8h(v0, v1, &g_sh[0][i], &g_sl[0][i]);
    else          cvt8h(v0, v1, &g_sh[src][i]);
}

// ---------------------------------------------------------------------------
// fp16 tensor-core GEMM: C[8192,512] = A @ Whi(mode)
// A = (Ahi+Alo) split for modes 0 (Q) and 3 (fc); hi-only for modes 1 (K),
// 2 (V) — those outputs are fp16-rounded downstream anyway.
// BM=128,BN=64,BK=64, 256 thr (8 warps 4m x 2n), smem double-buffer.
// ---------------------------------------------------------------------------
#define PROJ_SMEM_BYTES 92160

__global__ __launch_bounds__(256, 2) void proj_all(int mode_base, float* __restrict__ outp)
{
    extern __shared__ __align__(16) char smem_raw[];
    __half* Ah = (__half*)smem_raw;                       // [2][128][72]
    __half* Al = (__half*)(smem_raw + 36864);             // [2][128][72]
    __half* Bh = (__half*)(smem_raw + 73728);             // [2][64][72]

    const int mode = mode_base + blockIdx.z;
    const bool needSplit = (mode == 0) || (mode == 3);
    const __half* Sh = g_sh[(mode < 3) ? mode : 0];
    const __half* Sl = g_sl[(mode < 3) ? mode : 0];
    const __half* Wh = g_wh + (size_t)mode * 512 * 512;

    const int tid  = threadIdx.x;
    const int wid  = tid >> 5;
    const int lane = tid & 31;
    const int wm = (wid >> 1) * 32;
    const int wn = (wid & 1) * 32;
    const int g  = lane >> 2;
    const int t4 = lane & 3;

    const int mBase = blockIdx.x * 128;
    const int nBase = blockIdx.y * 64;

    const int ar = tid >> 1;
    const int ac = (tid & 1) * 32;
    const int br = tid >> 2;
    const int bc = (tid & 3) * 16;

    const int a_r0 = wm + (lane & 15);
    const int a_c  = (lane >> 4) << 3;
    const int b_r0 = wn + (lane & 7) + ((lane >> 4) << 3);
    const int b_c  = ((lane >> 3) & 1) * 8;

    float acc[2][4][4] = {};

    uint4 sAh[4], sAl[4], sBh[2];
    auto stage = [&](int k0) {
        const size_t a0 = (size_t)(mBase + ar) * 512 + k0 + ac;
        #pragma unroll
        for (int j = 0; j < 4; j++) {
            sAh[j] = *(const uint4*)&Sh[a0 + j * 8];
            if (needSplit) sAl[j] = *(const uint4*)&Sl[a0 + j * 8];
        }
        const size_t b0 = (size_t)(nBase + br) * 512 + k0 + bc;
        sBh[0] = *(const uint4*)&Wh[b0];
        sBh[1] = *(const uint4*)&Wh[b0 + 8];
    };
    auto commit = [&](int buf) {
        __half* ah = Ah + buf * 128 * BS + ar * BS + ac;
        __half* al = Al + buf * 128 * BS + ar * BS + ac;
        #pragma unroll
        for (int j = 0; j < 4; j++) {
            *(uint4*)(ah + j * 8) = sAh[j];
            if (needSplit) *(uint4*)(al + j * 8) = sAl[j];
        }
        __half* bh = Bh + buf * 64 * BS + br * BS + bc;
        *(uint4*)bh       = sBh[0];
        *(uint4*)(bh + 8) = sBh[1];
    };

    stage(0);
    commit(0);
    stage(64);
    __syncthreads();

    int buf = 0;
    for (int k0 = 0; k0 < 512; k0 += 64, buf ^= 1) {
        if (k0 + 64 < 512) {
            commit(buf ^ 1);
            if (k0 + 128 < 512) stage(k0 + 128);
        }

        const __half* AhB = Ah + buf * 128 * BS;
        const __half* AlB = Al + buf * 128 * BS;
        const __half* BhB = Bh + buf * 64 * BS;
        #pragma unroll
        for (int ks = 0; ks < 64; ks += 16) {
            uint32_t ah0[4], ah1[4], al0[4], al1[4];
            ldsm_x4(ah0, &AhB[ a_r0       * BS + ks + a_c]);
            ldsm_x4(ah1, &AhB[(a_r0 + 16) * BS + ks + a_c]);
            if (needSplit) {
                ldsm_x4(al0, &AlB[ a_r0       * BS + ks + a_c]);
                ldsm_x4(al1, &AlB[(a_r0 + 16) * BS + ks + a_c]);
            }
            uint32_t bh01[4], bh23[4];
            ldsm_x4(bh01, &BhB[ b_r0       * BS + ks + b_c]);
            ldsm_x4(bh23, &BhB[(b_r0 + 16) * BS + ks + b_c]);

            const uint32_t* AH[2] = {ah0, ah1};
            const uint32_t* AL[2] = {al0, al1};
            const uint32_t* BH[4] = {&bh01[0], &bh01[2], &bh23[0], &bh23[2]};
            #pragma unroll
            for (int mf = 0; mf < 2; mf++)
                #pragma unroll
                for (int nf = 0; nf < 4; nf++) {
                    mma_f16(acc[mf][nf], AH[mf], BH[nf]);
                    if (needSplit) mma_f16(acc[mf][nf], AL[mf], BH[nf]);
                }
        }
        __syncthreads();
    }

    #pragma unroll
    for (int mf = 0; mf < 2; mf++) {
        #pragma unroll
        for (int nf = 0; nf < 4; nf++) {
            const int col = wn + nf * 8 + 2 * t4;
            const int r0  = mBase + wm + mf * 16 + g;
            const int r1  = r0 + 8;
            float v0 = acc[mf][nf][0], v1 = acc[mf][nf][1];
            float v2 = acc[mf][nf][2], v3 = acc[mf][nf][3];
            if (mode == 3) {
                float2 lo2 = {v0, v1}, hi2 = {v2, v3};
                *(float2*)&outp[(size_t)r0 * 512 + nBase + col] = lo2;
                *(float2*)&outp[(size_t)r1 * 512 + nBase + col] = hi2;
            } else {
                const int hh = blockIdx.y;
                const int b0 = r0 >> 9, l0 = r0 & 511;
                const int b1 = r1 >> 9, l1 = r1 & 511;
                if (mode == 2) {
                    size_t c0 = ((size_t)(b0 * Hsz + hh) * DKsz + col) * Lsz;
                    size_t c1 = ((size_t)(b0 * Hsz + hh) * DKsz + col + 1) * Lsz;
                    g_vth[c0 + l0] = __float2half_rn(v0);
                    g_vth[c1 + l0] = __float2half_rn(v1);
                    g_vth[c0 + l1] = __float2half_rn(v2);
                    g_vth[c1 + l1] = __float2half_rn(v3);
                } else if (mode == 1) {
                    size_t i0 = (((size_t)b0 * Hsz + hh) * Lsz + l0) * DKsz + col;
                    size_t i1 = (((size_t)b1 * Hsz + hh) * Lsz + l1) * DKsz + col;
                    *(uint32_t*)&g_kh[i0] = pack2h(v0, v1);
                    *(uint32_t*)&g_kh[i1] = pack2h(v2, v3);
                } else {
                    uint32_t hp, lp;
                    split2h(v0 * 0.125f, v1 * 0.125f, hp, lp);
                    size_t i0 = (((size_t)b0 * Hsz + hh) * Lsz + l0) * DKsz + col;
                    *(uint32_t*)&g_qh[i0] = hp;
                    *(uint32_t*)&g_ql[i0] = lp;
                    split2h(v2 * 0.125f, v3 * 0.125f, hp, lp);
                    size_t i1 = (((size_t)b1 * Hsz + hh) * Lsz + l1) * DKsz + col;
                    *(uint32_t*)&g_qh[i1] = hp;
                    *(uint32_t*)&g_ql[i1] = lp;
                }
            }
        }
    }
}

// ---------------------------------------------------------------------------
// Tensor-core fused attention v3. 512 threads = 16 warps (4m x 4n).
// smem: s[64][516] fp32 + P 8x[64][72] fp16 + V 2x[64][72] fp16 = 224,256 B.
// Phase 2: rolling register prefetch of mask+aiw (next row loads overlap
// current row's exp/reduce math — hides the DRAM latency that bound R14).
// ---------------------------------------------------------------------------
__global__ __launch_bounds__(512) void attn_mma(const int* __restrict__ mask,
                                                const float* __restrict__ aiw,
                                                float* __restrict__ p_out)
{
    extern __shared__ float sm[];
    float* s = sm;                                        // [64][516]
    __half* Pr = (__half*)(sm + 64 * SD);                 // 8 bufs [64][BS]
    __half* Vr = Pr + 8 * PREG;                           // 2 bufs [64][BS]

    const int tid  = threadIdx.x;
    const int wid  = tid >> 5;
    const int lane = tid & 31;
    const int g  = lane >> 2;
    const int t4 = lane & 3;
    const int wm = (wid & 3) * 16;
    const int wc = wid >> 2;

    const int bh = blockIdx.y;
    const int b  = bh >> 3;
    const int h  = bh & 7;
    const int qBase = blockIdx.x * 64;

    const int cr = tid >> 3;
    const int cc = (tid & 7) * 8;

    const int a_r = wm + (lane & 15);
    const int a_c = (lane >> 4) << 3;
    const int b_r = wc * 16 + (lane & 7) + ((lane >> 4) << 3);
    const int b_c = ((lane >> 3) & 1) * 8;

    // ---- Phase 1 prologue: Q into Pr bufs 0/1, K chunk0 into buf2
    {
        const size_t qo = ((size_t)bh * Lsz + qBase + cr) * DKsz + cc;
        *(uint4*)&Pr[cr * BS + cc]        = *(const uint4*)&g_qh[qo];
        *(uint4*)&Pr[PREG + cr * BS + cc] = *(const uint4*)&g_ql[qo];
    }
    uint4 kh = *(const uint4*)&g_kh[((size_t)bh * Lsz + cr) * DKsz + cc];
    *(uint4*)&Pr[2 * PREG + cr * BS + cc] = kh;
    kh = *(const uint4*)&g_kh[((size_t)bh * Lsz + 64 + cr) * DKsz + cc];
    __syncthreads();

    // Hoist Q fragments into registers (loaded once).
    uint32_t qah[4][4], qal[4][4];
    #pragma unroll
    for (int ksi = 0; ksi < 4; ksi++) {
        ldsm_x4(qah[ksi], &Pr[a_r * BS + ksi * 16 + a_c]);
        ldsm_x4(qal[ksi], &Pr[PREG + a_r * BS + ksi * 16 + a_c]);
    }

    for (int nt = 0; nt < 8; nt++) {
        __half* cb = Pr + (2 + (nt & 1)) * PREG;
        if (nt < 7) {
            __half* nb = Pr + (2 + ((nt + 1) & 1)) * PREG;
            *(uint4*)&nb[cr * BS + cc] = kh;
            if (nt < 6)
                kh = *(const uint4*)&g_kh[((size_t)bh * Lsz + (nt + 2) * 64 + cr) * DKsz + cc];
        }

        float acc[2][4] = {};
        #pragma unroll
        for (int ksi = 0; ksi < 4; ksi++) {
            uint32_t bhv[4];
            ldsm_x4(bhv, &cb[b_r * BS + ksi * 16 + b_c]);
            mma_f16(acc[0], qah[ksi], &bhv[0]);
            mma_f16(acc[0], qal[ksi], &bhv[0]);
            mma_f16(acc[1], qah[ksi], &bhv[2]);
            mma_f16(acc[1], qal[ksi], &bhv[2]);
        }
        #pragma unroll
        for (int nf = 0; nf < 2; nf++) {
            const int col = nt * 64 + wc * 16 + nf * 8 + 2 * t4;
            const int row = wm + g;
            float2 v01 = {acc[nf][0], acc[nf][1]};
            float2 v23 = {acc[nf][2], acc[nf][3]};
            *(float2*)&s[ row      * SD + col] = v01;
            *(float2*)&s[(row + 8) * SD + col] = v23;
        }
        __syncthreads();
    }

    // ---- Phase 2: mask + softmax + *aiw with rolling register prefetch
    {
        int4   mm[2][4];
        float4 aa[2][4];
        auto mload = [&](int r, int slot) {
            const int qRow = qBase + wid * 4 + r;
            const int4*   m4 = (const int4*)  (mask + ((size_t)b * Lsz + qRow) * Lsz);
            const float4* a4 = (const float4*)(aiw  + ((size_t)b * Lsz + qRow) * Lsz);
            #pragma unroll
            for (int j = 0; j < 4; j++) {
                const int gidx = j * 32 + lane;
                mm[slot][j] = m4[gidx];
                aa[slot][j] = a4[gidx];
            }
        };
        mload(0, 0);

        #pragma unroll
        for (int r = 0; r < 4; r++) {
            const int cur = r & 1;
            if (r < 3) mload(r + 1, cur ^ 1);   // overlaps this row's math

            const int m = wid * 4 + r;
            const int qRow = qBase + m;
            float4* s4 = (float4*)(s + m * SD);
            float4* p4 = (float4*)(p_out + ((size_t)bh * Lsz + qRow) * Lsz);

            float4 sv[4];
            float mx = -1e30f;
            #pragma unroll
            for (int j = 0; j < 4; j++) {
                const int gidx = j * 32 + lane;
                float4 v = s4[gidx];
                int4  mmv = mm[cur][j];
                v.x = mmv.x ? -1e30f : v.x;
                v.y = mmv.y ? -1e30f : v.y;
                v.z = mmv.z ? -1e30f : v.z;
                v.w = mmv.w ? -1e30f : v.w;
                sv[j] = v;
                mx = fmaxf(mx, fmaxf(fmaxf(v.x, v.y), fmaxf(v.z, v.w)));
            }
            #pragma unroll
            for (int o = 16; o; o >>= 1) mx = fmaxf(mx, __shfl_xor_sync(0xffffffffu, mx, o));

            float sum = 0.f;
            #pragma unroll
            for (int j = 0; j < 4; j++) {
                sv[j].x = __expf(sv[j].x - mx);
                sv[j].y = __expf(sv[j].y - mx);
                sv[j].z = __expf(sv[j].z - mx);
                sv[j].w = __expf(sv[j].w - mx);
                sum += (sv[j].x + sv[j].y) + (sv[j].z + sv[j].w);
            }
            #pragma unroll
            for (int o = 16; o; o >>= 1) sum += __shfl_xor_sync(0xffffffffu, sum, o);
            const float inv = 1.f / sum;

            #pragma unroll
            for (int j = 0; j < 4; j++) {
                const int gidx = j * 32 + lane;
                float4 a = aa[cur][j];
                float4 p;
                p.x = sv[j].x * inv * a.x;
                p.y = sv[j].y * inv * a.y;
                p.z = sv[j].z * inv * a.z;
                p.w = sv[j].w * inv * a.w;
                p4[gidx] = p;
                const int chunk = (j << 1) + (lane >> 4);
                const int off   = 4 * (lane & 15);
                uint2 pk;
                pk.x = pack2h(p.x, p.y);
                pk.y = pack2h(p.z, p.w);
                *(uint2*)&Pr[chunk * PREG + m * BS + off] = pk;
            }
        }
    }
    __syncthreads();

    // ---- Phase 3: X = P V  (P resident fp16; V hi-only ping-pong)
    uint4 vh = *(const uint4*)&g_vth[((size_t)bh * DKsz + cr) * Lsz + cc];
    *(uint4*)&Vr[cr * BS + cc] = vh;
    vh = *(const uint4*)&g_vth[((size_t)bh * DKsz + cr) * Lsz + 64 + cc];
    __syncthreads();

    float acc[2][4] = {};
    for (int kt = 0; kt < 8; kt++) {
        __half* pc = Pr + kt * PREG;
        __half* vb = Vr + (kt & 1) * PREG;
        if (kt < 7) {
            __half* nvb = Vr + ((kt + 1) & 1) * PREG;
            *(uint4*)&nvb[cr * BS + cc] = vh;
            if (kt < 6)
                vh = *(const uint4*)&g_vth[((size_t)bh * DKsz + cr) * Lsz + (kt + 2) * 64 + cc];
        }

        #pragma unroll
        for (int ksi = 0; ksi < 4; ksi++) {
            uint32_t ah[4], bhv[4];
            ldsm_x4(ah,  &pc[a_r * BS + ksi * 16 + a_c]);
            ldsm_x4(bhv, &vb[b_r * BS + ksi * 16 + b_c]);
            mma_f16(acc[0], ah, &bhv[0]);
            mma_f16(acc[1], ah, &bhv[2]);
        }
        __syncthreads();
    }

    // ---- X epilogue: fp16 hi/lo into staging buffer 0 (fc input)
    #pragma unroll
    for (int nf = 0; nf < 2; nf++) {
        const int col = wc * 16 + nf * 8 + 2 * t4;
        const int row = qBase + wm + g;
        uint32_t hp, lp;
        split2h(acc[nf][0], acc[nf][1], hp, lp);
        size_t i0 = ((size_t)b * Lsz + row) * Dsz + h * 64 + col;
        *(uint32_t*)&g_sh[0][i0] = hp;
        *(uint32_t*)&g_sl[0][i0] = lp;
        split2h(acc[nf][2], acc[nf][3], hp, lp);
        size_t i1 = ((size_t)b * Lsz + row + 8) * Dsz + h * 64 + col;
        *(uint32_t*)&g_sh[0][i1] = hp;
        *(uint32_t*)&g_sl[0][i1] = lp;
    }
}

// ---------------------------------------------------------------------------
extern "C" void kernel_launch(void* const* d_in, const int* in_sizes, int n_in,
                              void* d_out, int out_size)
{
    (void)in_sizes; (void)n_in; (void)out_size;
    const float* query = (const float*)d_in[0];
    const float* keyt  = (const float*)d_in[1];
    const float* value = (const float*)d_in[2];
    const int*   mask  = (const int*)d_in[3];     // bool upcast to int32
    const float* aiw   = (const float*)d_in[4];
    const float* wQ    = (const float*)d_in[5];
    const float* wK    = (const float*)d_in[6];
    const float* wV    = (const float*)d_in[7];
    const float* wfc   = (const float*)d_in[8];

    float* outx = (float*)d_out;                       // x: [B,L,D]
    float* outp = outx + (size_t)Bsz * Lsz * Dsz;      // p_attn: [B,H,L,L]

    cudaFuncSetAttribute((const void*)proj_all,
                         cudaFuncAttributeMaxDynamicSharedMemorySize, PROJ_SMEM_BYTES);
    const int attn_smem = 64 * SD * (int)sizeof(float)
                        + 10 * PREG * (int)sizeof(__half);   // 224,256 B
    cudaFuncSetAttribute((const void*)attn_mma,
                         cudaFuncAttributeMaxDynamicSharedMemorySize, attn_smem);

    cvt_wt_all<<<dim3(16, 16, 4), dim3(32, 32)>>>(wQ, wK, wV, wfc);
    cvt_split3<<<dim3(2048, 3), 256>>>(query, keyt, value);
    proj_all<<<dim3(64, 8, 3), 256, PROJ_SMEM_BYTES>>>(0, nullptr);
    attn_mma<<<dim3(8, 128), 512, attn_smem>>>(mask, aiw, outp);
    proj_all<<<dim3(64, 8, 1), 256, PROJ_SMEM_BYTES>>>(3, outx);
}

// round 17
// speedup vs baseline: 3.3317x; 1.0001x over previous
#include <cuda_runtime.h>
#include <cuda_fp16.h>
#include <cstdint>

#define Bsz 16
#define Lsz 512
#define Dsz 512
#define Hsz 8
#define DKsz 64
#define BHsz (Bsz*Hsz)

#define SD 516        // score row stride (floats)
#define BS 72         // fp16 buffer row stride (halves)
#define PC (32*BS)    // one P chunk [32][72] (halves)

// Scratch (allocation-free contract: __device__ globals)
__device__ __half g_qh[BHsz*Lsz*DKsz], g_ql[BHsz*Lsz*DKsz];   // Q pre-scaled by 1/8
__device__ __half g_kh[BHsz*Lsz*DKsz];
__device__ __half g_vth[BHsz*DKsz*Lsz];
__device__ __half g_sh[3][Bsz*Lsz*Dsz], g_sl[3][Bsz*Lsz*Dsz]; // staged inputs (0 reused for x)
__device__ __half g_wh[4*Dsz*Dsz];                            // weights, transposed [n][k]

// ---------------------------------------------------------------------------
__device__ __forceinline__ void mma_f16(float* c, const uint32_t* a, const uint32_t* b)
{
    asm volatile(
        "mma.sync.aligned.m16n8k16.row.col.f32.f16.f16.f32 "
        "{%0,%1,%2,%3}, {%4,%5,%6,%7}, {%8,%9}, {%0,%1,%2,%3};\n"
        : "+f"(c[0]), "+f"(c[1]), "+f"(c[2]), "+f"(c[3])
        : "r"(a[0]), "r"(a[1]), "r"(a[2]), "r"(a[3]), "r"(b[0]), "r"(b[1]));
}

__device__ __forceinline__ void ldsm_x4(uint32_t* r, const void* p)
{
    uint32_t a = (uint32_t)__cvta_generic_to_shared(p);
    asm volatile("ldmatrix.sync.aligned.m8n8.x4.shared.b16 {%0,%1,%2,%3}, [%4];"
                 : "=r"(r[0]), "=r"(r[1]), "=r"(r[2]), "=r"(r[3]) : "r"(a));
}

__device__ __forceinline__ void split8h(float4 v0, float4 v1,
                                        __half* dh, __half* dl)
{
    __align__(16) __half hh[8], ll[8];
    float vv[8] = {v0.x, v0.y, v0.z, v0.w, v1.x, v1.y, v1.z, v1.w};
    #pragma unroll
    for (int e = 0; e < 8; e++) {
        __half h = __float2half_rn(vv[e]);
        hh[e] = h;
        ll[e] = __float2half_rn(vv[e] - __half2float(h));
    }
    *(uint4*)dh = *(const uint4*)hh;
    *(uint4*)dl = *(const uint4*)ll;
}

__device__ __forceinline__ void cvt8h(float4 v0, float4 v1, __half* dh)
{
    __align__(16) __half hh[8];
    float vv[8] = {v0.x, v0.y, v0.z, v0.w, v1.x, v1.y, v1.z, v1.w};
    #pragma unroll
    for (int e = 0; e < 8; e++) hh[e] = __float2half_rn(vv[e]);
    *(uint4*)dh = *(const uint4*)hh;
}

__device__ __forceinline__ void split2h(float x, float y, uint32_t& hp, uint32_t& lp)
{
    __half hx = __float2half_rn(x), hy = __float2half_rn(y);
    __half lx = __float2half_rn(x - __half2float(hx));
    __half ly = __float2half_rn(y - __half2float(hy));
    __half2 hh = {hx, hy}, ll = {lx, ly};
    hp = *(uint32_t*)&hh;
    lp = *(uint32_t*)&ll;
}

__device__ __forceinline__ uint32_t pack2h(float x, float y)
{
    __half2 h = __floats2half2_rn(x, y);
    return *(uint32_t*)&h;
}

// ---------------------------------------------------------------------------
// Merged conversion kernels (unchanged from R15)
// ---------------------------------------------------------------------------
__global__ __launch_bounds__(1024) void cvt_wt_all(const float* __restrict__ wQ,
                                                   const float* __restrict__ wK,
                                                   const float* __restrict__ wV,
                                                   const float* __restrict__ wfc)
{
    __shared__ float t[32][33];
    const int widx = blockIdx.z;
    const float* w = (widx == 0) ? wQ : (widx == 1) ? wK : (widx == 2) ? wV : wfc;
    const int k0 = blockIdx.x * 32, n0 = blockIdx.y * 32;
    const int tx = threadIdx.x, ty = threadIdx.y;
    t[ty][tx] = w[(size_t)(k0 + ty) * 512 + n0 + tx];
    __syncthreads();
    float v = t[tx][ty];
    g_wh[(size_t)widx * 512 * 512 + (size_t)(n0 + ty) * 512 + (k0 + tx)] = __float2half_rn(v);
}

__global__ __launch_bounds__(256) void cvt_split3(const float* __restrict__ q,
                                                  const float* __restrict__ k,
                                                  const float* __restrict__ v)
{
    const int src = blockIdx.y;
    const float* s = (src == 0) ? q : (src == 1) ? k : v;
    const size_t i = ((size_t)blockIdx.x * 256 + threadIdx.x) * 8;
    float4 v0 = *(const float4*)&s[i];
    float4 v1 = *(const float4*)&s[i + 4];
    if (src == 0) split8h(v0, v1, &g_sh[0][i], &g_sl[0][i]);
    else          cvt8h(v0, v1, &g_sh[src][i]);
}

// ---------------------------------------------------------------------------
// fp16 tensor-core GEMM (unchanged from R15): split A for modes 0/3,
// hi-only A for modes 1/2. BM=128,BN=64,BK=64.
// ---------------------------------------------------------------------------
#define PROJ_SMEM_BYTES 92160

__global__ __launch_bounds__(256, 2) void proj_all(int mode_base, float* __restrict__ outp)
{
    extern __shared__ __align__(16) char smem_raw[];
    __half* Ah = (__half*)smem_raw;                       // [2][128][72]
    __half* Al = (__half*)(smem_raw + 36864);             // [2][128][72]
    __half* Bh = (__half*)(smem_raw + 73728);             // [2][64][72]

    const int mode = mode_base + blockIdx.z;
    const bool needSplit = (mode == 0) || (mode == 3);
    const __half* Sh = g_sh[(mode < 3) ? mode : 0];
    const __half* Sl = g_sl[(mode < 3) ? mode : 0];
    const __half* Wh = g_wh + (size_t)mode * 512 * 512;

    const int tid  = threadIdx.x;
    const int wid  = tid >> 5;
    const int lane = tid & 31;
    const int wm = (wid >> 1) * 32;
    const int wn = (wid & 1) * 32;
    const int g  = lane >> 2;
    const int t4 = lane & 3;

    const int mBase = blockIdx.x * 128;
    const int nBase = blockIdx.y * 64;

    const int ar = tid >> 1;
    const int ac = (tid & 1) * 32;
    const int br = tid >> 2;
    const int bc = (tid & 3) * 16;

    const int a_r0 = wm + (lane & 15);
    const int a_c  = (lane >> 4) << 3;
    const int b_r0 = wn + (lane & 7) + ((lane >> 4) << 3);
    const int b_c  = ((lane >> 3) & 1) * 8;

    float acc[2][4][4] = {};

    uint4 sAh[4], sAl[4], sBh[2];
    auto stage = [&](int k0) {
        const size_t a0 = (size_t)(mBase + ar) * 512 + k0 + ac;
        #pragma unroll
        for (int j = 0; j < 4; j++) {
            sAh[j] = *(const uint4*)&Sh[a0 + j * 8];
            if (needSplit) sAl[j] = *(const uint4*)&Sl[a0 + j * 8];
        }
        const size_t b0 = (size_t)(nBase + br) * 512 + k0 + bc;
        sBh[0] = *(const uint4*)&Wh[b0];
        sBh[1] = *(const uint4*)&Wh[b0 + 8];
    };
    auto commit = [&](int buf) {
        __half* ah = Ah + buf * 128 * BS + ar * BS + ac;
        __half* al = Al + buf * 128 * BS + ar * BS + ac;
        #pragma unroll
        for (int j = 0; j < 4; j++) {
            *(uint4*)(ah + j * 8) = sAh[j];
            if (needSplit) *(uint4*)(al + j * 8) = sAl[j];
        }
        __half* bh = Bh + buf * 64 * BS + br * BS + bc;
        *(uint4*)bh       = sBh[0];
        *(uint4*)(bh + 8) = sBh[1];
    };

    stage(0);
    commit(0);
    stage(64);
    __syncthreads();

    int buf = 0;
    for (int k0 = 0; k0 < 512; k0 += 64, buf ^= 1) {
        if (k0 + 64 < 512) {
            commit(buf ^ 1);
            if (k0 + 128 < 512) stage(k0 + 128);
        }

        const __half* AhB = Ah + buf * 128 * BS;
        const __half* AlB = Al + buf * 128 * BS;
        const __half* BhB = Bh + buf * 64 * BS;
        #pragma unroll
        for (int ks = 0; ks < 64; ks += 16) {
            uint32_t ah0[4], ah1[4], al0[4], al1[4];
            ldsm_x4(ah0, &AhB[ a_r0       * BS + ks + a_c]);
            ldsm_x4(ah1, &AhB[(a_r0 + 16) * BS + ks + a_c]);
            if (needSplit) {
                ldsm_x4(al0, &AlB[ a_r0       * BS + ks + a_c]);
                ldsm_x4(al1, &AlB[(a_r0 + 16) * BS + ks + a_c]);
            }
            uint32_t bh01[4], bh23[4];
            ldsm_x4(bh01, &BhB[ b_r0       * BS + ks + b_c]);
            ldsm_x4(bh23, &BhB[(b_r0 + 16) * BS + ks + b_c]);

            const uint32_t* AH[2] = {ah0, ah1};
            const uint32_t* AL[2] = {al0, al1};
            const uint32_t* BH[4] = {&bh01[0], &bh01[2], &bh23[0], &bh23[2]};
            #pragma unroll
            for (int mf = 0; mf < 2; mf++)
                #pragma unroll
                for (int nf = 0; nf < 4; nf++) {
                    mma_f16(acc[mf][nf], AH[mf], BH[nf]);
                    if (needSplit) mma_f16(acc[mf][nf], AL[mf], BH[nf]);
                }
        }
        __syncthreads();
    }

    #pragma unroll
    for (int mf = 0; mf < 2; mf++) {
        #pragma unroll
        for (int nf = 0; nf < 4; nf++) {
            const int col = wn + nf * 8 + 2 * t4;
            const int r0  = mBase + wm + mf * 16 + g;
            const int r1  = r0 + 8;
            float v0 = acc[mf][nf][0], v1 = acc[mf][nf][1];
            float v2 = acc[mf][nf][2], v3 = acc[mf][nf][3];
            if (mode == 3) {
                float2 lo2 = {v0, v1}, hi2 = {v2, v3};
                *(float2*)&outp[(size_t)r0 * 512 + nBase + col] = lo2;
                *(float2*)&outp[(size_t)r1 * 512 + nBase + col] = hi2;
            } else {
                const int hh = blockIdx.y;
                const int b0 = r0 >> 9, l0 = r0 & 511;
                const int b1 = r1 >> 9, l1 = r1 & 511;
                if (mode == 2) {
                    size_t c0 = ((size_t)(b0 * Hsz + hh) * DKsz + col) * Lsz;
                    size_t c1 = ((size_t)(b0 * Hsz + hh) * DKsz + col + 1) * Lsz;
                    g_vth[c0 + l0] = __float2half_rn(v0);
                    g_vth[c1 + l0] = __float2half_rn(v1);
                    g_vth[c0 + l1] = __float2half_rn(v2);
                    g_vth[c1 + l1] = __float2half_rn(v3);
                } else if (mode == 1) {
                    size_t i0 = (((size_t)b0 * Hsz + hh) * Lsz + l0) * DKsz + col;
                    size_t i1 = (((size_t)b1 * Hsz + hh) * Lsz + l1) * DKsz + col;
                    *(uint32_t*)&g_kh[i0] = pack2h(v0, v1);
                    *(uint32_t*)&g_kh[i1] = pack2h(v2, v3);
                } else {
                    uint32_t hp, lp;
                    split2h(v0 * 0.125f, v1 * 0.125f, hp, lp);
                    size_t i0 = (((size_t)b0 * Hsz + hh) * Lsz + l0) * DKsz + col;
                    *(uint32_t*)&g_qh[i0] = hp;
                    *(uint32_t*)&g_ql[i0] = lp;
                    split2h(v2 * 0.125f, v3 * 0.125f, hp, lp);
                    size_t i1 = (((size_t)b1 * Hsz + hh) * Lsz + l1) * DKsz + col;
                    *(uint32_t*)&g_qh[i1] = hp;
                    *(uint32_t*)&g_ql[i1] = lp;
                }
            }
        }
    }
}

// ---------------------------------------------------------------------------
// Tensor-core fused attention v4: 32-row q-tiles, 256 threads (8 warps,
// 2m x 4n), smem 112,128 B -> 2 CTAs/SM for cross-CTA phase overlap.
// smem: s[32][516] fp32 (66,048) + P 8x[32][72] fp16 (36,864; Q/K aliased
// inside during phase 1) + V [64][72] fp16 (9,216).
// Numerics identical to R15 (same tiles, same MMA order).
// ---------------------------------------------------------------------------
#define ATTN_SMEM_BYTES (32*SD*4 + 8*PC*2 + 64*BS*2)   // 112,128

__global__ __launch_bounds__(256, 2) void attn_mma(const int* __restrict__ mask,
                                                   const float* __restrict__ aiw,
                                                   float* __restrict__ p_out)
{
    extern __shared__ float sm[];
    float* s = sm;                                        // [32][516]
    __half* Pr = (__half*)(sm + 32 * SD);                 // 8 P chunks [32][72]
    __half* Vr = Pr + 8 * PC;                             // V buf [64][72]
    // phase-1 aliases inside the P region:
    __half* QH = Pr;                                      // [32][72]
    __half* QL = Pr + PC;
    __half* K0 = Pr + 2 * PC;                             // [64][72] = 2*PC
    __half* K1 = Pr + 4 * PC;

    const int tid  = threadIdx.x;
    const int wid  = tid >> 5;
    const int lane = tid & 31;
    const int g  = lane >> 2;
    const int t4 = lane & 3;
    const int wm = (wid & 1) * 16;     // 2 m-groups
    const int wc = wid >> 1;           // 4 n-groups

    const int bh = blockIdx.y;
    const int b  = bh >> 3;
    const int h  = bh & 7;
    const int qBase = blockIdx.x * 32;

    // copy indices: Q [32][64]: 1 uint4/thread; K/V [64][64]: 2 uint4/thread
    const int qr = tid >> 3, qc = (tid & 7) * 8;
    const int kr = tid >> 2, kc = (tid & 3) * 16;

    const int a_r = wm + (lane & 15);
    const int a_c = (lane >> 4) << 3;
    const int b_r = wc * 16 + (lane & 7) + ((lane >> 4) << 3);
    const int b_c = ((lane >> 3) & 1) * 8;

    // ---- Phase 1 prologue: Q into QH/QL, K chunk0 into K0
    {
        const size_t qo = ((size_t)bh * Lsz + qBase + qr) * DKsz + qc;
        *(uint4*)&QH[qr * BS + qc] = *(const uint4*)&g_qh[qo];
        *(uint4*)&QL[qr * BS + qc] = *(const uint4*)&g_ql[qo];
    }
    uint4 kh0, kh1;
    {
        const size_t ko = ((size_t)bh * Lsz + kr) * DKsz + kc;
        kh0 = *(const uint4*)&g_kh[ko];
        kh1 = *(const uint4*)&g_kh[ko + 8];
    }
    *(uint4*)&K0[kr * BS + kc]     = kh0;
    *(uint4*)&K0[kr * BS + kc + 8] = kh1;
    {
        const size_t ko = ((size_t)bh * Lsz + 64 + kr) * DKsz + kc;
        kh0 = *(const uint4*)&g_kh[ko];
        kh1 = *(const uint4*)&g_kh[ko + 8];
    }
    __syncthreads();

    // Hoist Q fragments into registers (loaded once).
    uint32_t qah[4][4], qal[4][4];
    #pragma unroll
    for (int ksi = 0; ksi < 4; ksi++) {
        ldsm_x4(qah[ksi], &QH[a_r * BS + ksi * 16 + a_c]);
        ldsm_x4(qal[ksi], &QL[a_r * BS + ksi * 16 + a_c]);
    }

    for (int nt = 0; nt < 8; nt++) {
        __half* cb = (nt & 1) ? K1 : K0;
        if (nt < 7) {
            __half* nb = (nt & 1) ? K0 : K1;
            *(uint4*)&nb[kr * BS + kc]     = kh0;
            *(uint4*)&nb[kr * BS + kc + 8] = kh1;
            if (nt < 6) {
                const size_t ko = ((size_t)bh * Lsz + (nt + 2) * 64 + kr) * DKsz + kc;
                kh0 = *(const uint4*)&g_kh[ko];
                kh1 = *(const uint4*)&g_kh[ko + 8];
            }
        }

        float acc[2][4] = {};
        #pragma unroll
        for (int ksi = 0; ksi < 4; ksi++) {
            uint32_t bhv[4];
            ldsm_x4(bhv, &cb[b_r * BS + ksi * 16 + b_c]);
            mma_f16(acc[0], qah[ksi], &bhv[0]);
            mma_f16(acc[0], qal[ksi], &bhv[0]);
            mma_f16(acc[1], qah[ksi], &bhv[2]);
            mma_f16(acc[1], qal[ksi], &bhv[2]);
        }
        #pragma unroll
        for (int nf = 0; nf < 2; nf++) {
            const int col = nt * 64 + wc * 16 + nf * 8 + 2 * t4;
            const int row = wm + g;
            float2 v01 = {acc[nf][0], acc[nf][1]};
            float2 v23 = {acc[nf][2], acc[nf][3]};
            *(float2*)&s[ row      * SD + col] = v01;
            *(float2*)&s[(row + 8) * SD + col] = v23;
        }
        __syncthreads();
    }

    // ---- Phase 2: mask + softmax + *aiw with rolling register prefetch
    {
        int4   mm[2][4];
        float4 aa[2][4];
        auto mload = [&](int r, int slot) {
            const int qRow = qBase + wid * 4 + r;
            const int4*   m4 = (const int4*)  (mask + ((size_t)b * Lsz + qRow) * Lsz);
            const float4* a4 = (const float4*)(aiw  + ((size_t)b * Lsz + qRow) * Lsz);
            #pragma unroll
            for (int j = 0; j < 4; j++) {
                const int gidx = j * 32 + lane;
                mm[slot][j] = m4[gidx];
                aa[slot][j] = a4[gidx];
            }
        };
        mload(0, 0);

        #pragma unroll
        for (int r = 0; r < 4; r++) {
            const int cur = r & 1;
            if (r < 3) mload(r + 1, cur ^ 1);

            const int m = wid * 4 + r;            // 0..31
            const int qRow = qBase + m;
            float4* s4 = (float4*)(s + m * SD);
            float4* p4 = (float4*)(p_out + ((size_t)bh * Lsz + qRow) * Lsz);

            float4 sv[4];
            float mx = -1e30f;
            #pragma unroll
            for (int j = 0; j < 4; j++) {
                const int gidx = j * 32 + lane;
                float4 v = s4[gidx];
                int4  mmv = mm[cur][j];
                v.x = mmv.x ? -1e30f : v.x;
                v.y = mmv.y ? -1e30f : v.y;
                v.z = mmv.z ? -1e30f : v.z;
                v.w = mmv.w ? -1e30f : v.w;
                sv[j] = v;
                mx = fmaxf(mx, fmaxf(fmaxf(v.x, v.y), fmaxf(v.z, v.w)));
            }
            #pragma unroll
            for (int o = 16; o; o >>= 1) mx = fmaxf(mx, __shfl_xor_sync(0xffffffffu, mx, o));

            float sum = 0.f;
            #pragma unroll
            for (int j = 0; j < 4; j++) {
                sv[j].x = __expf(sv[j].x - mx);
                sv[j].y = __expf(sv[j].y - mx);
                sv[j].z = __expf(sv[j].z - mx);
                sv[j].w = __expf(sv[j].w - mx);
                sum += (sv[j].x + sv[j].y) + (sv[j].z + sv[j].w);
            }
            #pragma unroll
            for (int o = 16; o; o >>= 1) sum += __shfl_xor_sync(0xffffffffu, sum, o);
            const float inv = 1.f / sum;

            #pragma unroll
            for (int j = 0; j < 4; j++) {
                const int gidx = j * 32 + lane;
                float4 a = aa[cur][j];
                float4 p;
                p.x = sv[j].x * inv * a.x;
                p.y = sv[j].y * inv * a.y;
                p.z = sv[j].z * inv * a.z;
                p.w = sv[j].w * inv * a.w;
                p4[gidx] = p;
                const int chunk = (j << 1) + (lane >> 4);
                const int off   = 4 * (lane & 15);
                uint2 pk;
                pk.x = pack2h(p.x, p.y);
                pk.y = pack2h(p.z, p.w);
                *(uint2*)&Pr[chunk * PC + m * BS + off] = pk;
            }
        }
    }
    __syncthreads();

    // ---- Phase 3: X = P V  (P resident fp16; V single buffer, reg prefetch)
    uint4 vh0, vh1;
    {
        const size_t vo = ((size_t)bh * DKsz + kr) * Lsz + kc;
        vh0 = *(const uint4*)&g_vth[vo];
        vh1 = *(const uint4*)&g_vth[vo + 8];
    }

    float acc[2][4] = {};
    for (int kt = 0; kt < 8; kt++) {
        *(uint4*)&Vr[kr * BS + kc]     = vh0;
        *(uint4*)&Vr[kr * BS + kc + 8] = vh1;
        __syncthreads();
        if (kt < 7) {
            const size_t vo = ((size_t)bh * DKsz + kr) * Lsz + (kt + 1) * 64 + kc;
            vh0 = *(const uint4*)&g_vth[vo];
            vh1 = *(const uint4*)&g_vth[vo + 8];
        }

        __half* pc = Pr + kt * PC;
        #pragma unroll
        for (int ksi = 0; ksi < 4; ksi++) {
            uint32_t ah[4], bhv[4];
            ldsm_x4(ah,  &pc[a_r * BS + ksi * 16 + a_c]);
            ldsm_x4(bhv, &Vr[b_r * BS + ksi * 16 + b_c]);
            mma_f16(acc[0], ah, &bhv[0]);
            mma_f16(acc[1], ah, &bhv[2]);
        }
        __syncthreads();
    }

    // ---- X epilogue: fp16 hi/lo into staging buffer 0 (fc input)
    #pragma unroll
    for (int nf = 0; nf < 2; nf++) {
        const int col = wc * 16 + nf * 8 + 2 * t4;
        const int row = qBase + wm + g;
        uint32_t hp, lp;
        split2h(acc[nf][0], acc[nf][1], hp, lp);
        size_t i0 = ((size_t)b * Lsz + row) * Dsz + h * 64 + col;
        *(uint32_t*)&g_sh[0][i0] = hp;
        *(uint32_t*)&g_sl[0][i0] = lp;
        split2h(acc[nf][2], acc[nf][3], hp, lp);
        size_t i1 = ((size_t)b * Lsz + row + 8) * Dsz + h * 64 + col;
        *(uint32_t*)&g_sh[0][i1] = hp;
        *(uint32_t*)&g_sl[0][i1] = lp;
    }
}

// ---------------------------------------------------------------------------
extern "C" void kernel_launch(void* const* d_in, const int* in_sizes, int n_in,
                              void* d_out, int out_size)
{
    (void)in_sizes; (void)n_in; (void)out_size;
    const float* query = (const float*)d_in[0];
    const float* keyt  = (const float*)d_in[1];
    const float* value = (const float*)d_in[2];
    const int*   mask  = (const int*)d_in[3];     // bool upcast to int32
    const float* aiw   = (const float*)d_in[4];
    const float* wQ    = (const float*)d_in[5];
    const float* wK    = (const float*)d_in[6];
    const float* wV    = (const float*)d_in[7];
    const float* wfc   = (const float*)d_in[8];

    float* outx = (float*)d_out;                       // x: [B,L,D]
    float* outp = outx + (size_t)Bsz * Lsz * Dsz;      // p_attn: [B,H,L,L]

    cudaFuncSetAttribute((const void*)proj_all,
                         cudaFuncAttributeMaxDynamicSharedMemorySize, PROJ_SMEM_BYTES);
    cudaFuncSetAttribute((const void*)attn_mma,
                         cudaFuncAttributeMaxDynamicSharedMemorySize, ATTN_SMEM_BYTES);

    cvt_wt_all<<<dim3(16, 16, 4), dim3(32, 32)>>>(wQ, wK, wV, wfc);
    cvt_split3<<<dim3(2048, 3), 256>>>(query, keyt, value);
    proj_all<<<dim3(64, 8, 3), 256, PROJ_SMEM_BYTES>>>(0, nullptr);
    attn_mma<<<dim3(16, 128), 256, ATTN_SMEM_BYTES>>>(mask, aiw, outp);
    proj_all<<<dim3(64, 8, 1), 256, PROJ_SMEM_BYTES>>>(3, outx);
}